// round 1
// baseline (speedup 1.0000x reference)
#include <cuda_runtime.h>
#include <math.h>

// Problem constants
#define Bb   64
#define Nn   64
#define Hh   128
#define NBb  8
#define Tt   32
#define Ll   2
#define JPB  4          // receivers per CTA in message kernel

// ---------------- device scratch (no allocations allowed) ----------------
__device__ float g_h [Bb*Nn*Hh];        // node scalar features   (2 MB)
__device__ float g_v [Bb*Nn*Hh*3];      // node vector features   (6 MB)
__device__ float g_a0[Bb*Nn*Hh];        // scalar aggregates      (2 MB)
__device__ float g_a1[Bb*Nn*Hh*3];      // vector aggregates      (6 MB)
__device__ int   g_z64;                 // species dtype flag

// ---------------- K0: probe node_features dtype -------------------------
// If the array is int64 (little-endian), all odd int32 words are 0 (values 0..4).
// If int32, odd positions hold species values (nonzero w.h.p.).
__global__ void probe_kernel(const int* __restrict__ z) {
    int nz = 0;
    for (int t = 0; t < 64; ++t) nz |= z[2*t + 1];
    g_z64 = (nz == 0) ? 1 : 0;
}

// ---------------- K1: h = emb[z] + t @ Wt ; v = 0 -----------------------
__global__ void init_kernel(const int* __restrict__ z,
                            const float* __restrict__ gf,
                            const float* __restrict__ emb,
                            const float* __restrict__ Wt) {
    const int node = blockIdx.x;          // 0..B*N-1
    const int c    = threadIdx.x;         // 0..127
    const int b    = node >> 6;
    const int zi   = g_z64 ? z[2*node] : z[node];
    float acc = emb[zi*Hh + c];
    const float* g = gf + b*Tt;
    #pragma unroll
    for (int t = 0; t < Tt; ++t) acc += g[t] * Wt[t*Hh + c];
    g_h[node*Hh + c] = acc;
    float* vp = g_v + (size_t)(node*Hh + c)*3;
    vp[0] = 0.f; vp[1] = 0.f; vp[2] = 0.f;
}

// ---------------- K2: message pass (hot kernel) --------------------------
// CTA = (batch b, group of JPB receivers). Per receiver j:
//   S[i][k] = silu( rb(i->j) @ Wr1 )      (i = sender, zero if i==j or r>=Rmax)
//   W[i][c] = sum_k S[i][k] * Wr2[k][c]   (register-tiled GEMM)
//   a0[j][c] = sum_i W[i][c]*h[i][c] / 63
//   a1[j][c][d] = sum_i W[i][c]*h[i][c]*u(i->j)[d] / 63
__global__ __launch_bounds__(256, 1)
void msg_kernel(const float* __restrict__ pos,
                const float* __restrict__ Wr1,
                const float* __restrict__ Wr2) {
    extern __shared__ float sm[];
    float* h_s   = sm;                    // 8192   [64][128]
    float* Wr2_s = h_s   + Nn*Hh;         // 16384  [128][128]
    float* Wr1_s = Wr2_s + Hh*Hh;         // 1024   [8][128]
    float* S_s   = Wr1_s + NBb*Hh;        // 8192   [k=128][i=64]  (transposed)
    float* pos_s = S_s   + Hh*Nn;         // 192
    float* u_s   = pos_s + Nn*3;          // 192
    float* rb_s  = u_s   + Nn*3;          // 512    [q=8][i=64]
    float* red_s = rb_s  + NBb*Nn;        // 2048   [16][128]

    const int b   = blockIdx.y;
    const int jg  = blockIdx.x;
    const int tid = threadIdx.x;

    for (int idx = tid; idx < Nn*Hh; idx += 256) h_s[idx]   = g_h[b*Nn*Hh + idx];
    for (int idx = tid; idx < Hh*Hh; idx += 256) Wr2_s[idx] = Wr2[idx];
    for (int idx = tid; idx < NBb*Hh; idx += 256) Wr1_s[idx] = Wr1[idx];
    for (int idx = tid; idx < Nn*3;  idx += 256) pos_s[idx] = pos[b*Nn*3 + idx];
    __syncthreads();

    const int ig = tid >> 4;              // 0..15  (i-tile)
    const int cg = tid & 15;              // 0..15  (c-tile)
    const int i0 = ig * 4;
    const int c0 = cg * 8;
    const float PI5 = 0.62831853071795864769f;   // pi / 5

    for (int jj = 0; jj < JPB; ++jj) {
        const int j = jg*JPB + jj;

        // ---- edge geometry + bessel basis (64 threads) ----
        if (tid < Nn) {
            const int i = tid;
            float dx = pos_s[j*3+0] - pos_s[i*3+0];
            float dy = pos_s[j*3+1] - pos_s[i*3+1];
            float dz = pos_s[j*3+2] - pos_s[i*3+2];
            float r2 = dx*dx + dy*dy + dz*dz + 1e-12f;
            float r  = sqrtf(r2);
            float inv = 1.0f / r;
            u_s[i*3+0] = dx*inv; u_s[i*3+1] = dy*inv; u_s[i*3+2] = dz*inv;
            float fc = 0.0f;
            if (r < 5.0f && i != j) fc = 0.5f * (cosf(PI5 * r) + 1.0f);
            float sc  = inv * fc;
            float arg = PI5 * r;
            #pragma unroll
            for (int q = 0; q < NBb; ++q)
                rb_s[q*Nn + i] = sinf((float)(q+1) * arg) * sc;
        }
        __syncthreads();

        // ---- S = silu(rb @ Wr1), stored transposed [k][i] ----
        for (int idx = tid; idx < Hh*Nn; idx += 256) {
            int k = idx >> 6, i = idx & 63;
            float x = 0.f;
            #pragma unroll
            for (int q = 0; q < NBb; ++q) x += rb_s[q*Nn + i] * Wr1_s[q*Hh + k];
            S_s[k*Nn + i] = x / (1.0f + __expf(-x));
        }
        __syncthreads();

        // ---- register-tiled GEMM: W[i0..i0+3][c0..c0+7] ----
        float acc[4][8];
        #pragma unroll
        for (int r = 0; r < 4; ++r)
            #pragma unroll
            for (int c = 0; c < 8; ++c) acc[r][c] = 0.f;

        #pragma unroll 4
        for (int k = 0; k < Hh; ++k) {
            float4 wa = *(const float4*)(Wr2_s + k*Hh + c0);
            float4 wb = *(const float4*)(Wr2_s + k*Hh + c0 + 4);
            float w2[8] = {wa.x, wa.y, wa.z, wa.w, wb.x, wb.y, wb.z, wb.w};
            float sr[4];
            #pragma unroll
            for (int r = 0; r < 4; ++r) sr[r] = S_s[k*Nn + i0 + r];
            #pragma unroll
            for (int r = 0; r < 4; ++r)
                #pragma unroll
                for (int c = 0; c < 8; ++c) acc[r][c] += sr[r] * w2[c];
        }

        // ---- fuse with h[snd] and u -> partial a0/a1 ----
        float pa0[8], pax[8], pay[8], paz[8];
        #pragma unroll
        for (int c = 0; c < 8; ++c) { pa0[c]=0.f; pax[c]=0.f; pay[c]=0.f; paz[c]=0.f; }
        #pragma unroll
        for (int r = 0; r < 4; ++r) {
            int i = i0 + r;
            float ux = u_s[i*3+0], uy = u_s[i*3+1], uz = u_s[i*3+2];
            #pragma unroll
            for (int c = 0; c < 8; ++c) {
                float m = acc[r][c] * h_s[i*Hh + c0 + c];
                pa0[c] += m; pax[c] += m*ux; pay[c] += m*uy; paz[c] += m*uz;
            }
        }

        const float s63 = 1.0f / 63.0f;
        const int nidx = (b*Nn + j);

        // reduce across 16 i-groups, 4 rounds (a0, a1x, a1y, a1z)
        #pragma unroll
        for (int c = 0; c < 8; ++c) red_s[ig*Hh + c0 + c] = pa0[c];
        __syncthreads();
        if (tid < Hh) {
            float s = 0.f;
            #pragma unroll
            for (int g = 0; g < 16; ++g) s += red_s[g*Hh + tid];
            g_a0[nidx*Hh + tid] = s * s63;
        }
        __syncthreads();

        #pragma unroll
        for (int c = 0; c < 8; ++c) red_s[ig*Hh + c0 + c] = pax[c];
        __syncthreads();
        if (tid < Hh) {
            float s = 0.f;
            #pragma unroll
            for (int g = 0; g < 16; ++g) s += red_s[g*Hh + tid];
            g_a1[(nidx*Hh + tid)*3 + 0] = s * s63;
        }
        __syncthreads();

        #pragma unroll
        for (int c = 0; c < 8; ++c) red_s[ig*Hh + c0 + c] = pay[c];
        __syncthreads();
        if (tid < Hh) {
            float s = 0.f;
            #pragma unroll
            for (int g = 0; g < 16; ++g) s += red_s[g*Hh + tid];
            g_a1[(nidx*Hh + tid)*3 + 1] = s * s63;
        }
        __syncthreads();

        #pragma unroll
        for (int c = 0; c < 8; ++c) red_s[ig*Hh + c0 + c] = paz[c];
        __syncthreads();
        if (tid < Hh) {
            float s = 0.f;
            #pragma unroll
            for (int g = 0; g < 16; ++g) s += red_s[g*Hh + tid];
            g_a1[(nidx*Hh + tid)*3 + 2] = s * s63;
        }
        __syncthreads();
    }
}

// ---------------- K3: h += a0 @ Wupd ; v += einsum(a1, Wmix) -------------
__global__ void upd_kernel(const float* __restrict__ Wupd,
                           const float* __restrict__ Wmix) {
    __shared__ float a0_s[8*128];
    __shared__ float a1_s[8*384];
    const int n0 = blockIdx.x * 8;
    const int c  = threadIdx.x;
    for (int idx = c; idx < 8*128; idx += 128) a0_s[idx] = g_a0[n0*128 + idx];
    for (int idx = c; idx < 8*384; idx += 128) a1_s[idx] = g_a1[(size_t)n0*384 + idx];
    __syncthreads();
    float ah[8];  float av[8][3];
    #pragma unroll
    for (int m = 0; m < 8; ++m) { ah[m]=0.f; av[m][0]=0.f; av[m][1]=0.f; av[m][2]=0.f; }
    for (int g = 0; g < 128; ++g) {
        float wu = Wupd[g*128 + c];
        float wm = Wmix[g*128 + c];
        #pragma unroll
        for (int m = 0; m < 8; ++m) {
            ah[m] += a0_s[m*128 + g] * wu;
            const float* ap = a1_s + m*384 + g*3;
            av[m][0] += ap[0]*wm; av[m][1] += ap[1]*wm; av[m][2] += ap[2]*wm;
        }
    }
    #pragma unroll
    for (int m = 0; m < 8; ++m) {
        g_h[(n0+m)*128 + c] += ah[m];
        float* vp = g_v + (size_t)((n0+m)*128 + c)*3;
        vp[0] += av[m][0]; vp[1] += av[m][1]; vp[2] += av[m][2];
    }
}

// ---------------- K4: gated readout --------------------------------------
__global__ void readout_kernel(const float* __restrict__ Wg1,
                               const float* __restrict__ Wg2,
                               const float* __restrict__ fsp,
                               float* __restrict__ out) {
    __shared__ float h_s[8*128];
    __shared__ float t_s[8*128];
    __shared__ float wred[4][3];
    const int n0 = blockIdx.x * 8;
    const int c  = threadIdx.x;
    for (int idx = c; idx < 8*128; idx += 128) h_s[idx] = g_h[n0*128 + idx];
    __syncthreads();

    float t[8];
    #pragma unroll
    for (int m = 0; m < 8; ++m) t[m] = 0.f;
    for (int g = 0; g < 128; ++g) {
        float w = Wg1[g*128 + c];
        #pragma unroll
        for (int m = 0; m < 8; ++m) t[m] += h_s[m*128 + g] * w;
    }
    #pragma unroll
    for (int m = 0; m < 8; ++m) t_s[m*128 + c] = t[m] / (1.0f + __expf(-t[m]));
    __syncthreads();

    float gg[8];
    #pragma unroll
    for (int m = 0; m < 8; ++m) gg[m] = 0.f;
    for (int k = 0; k < 128; ++k) {
        float w = Wg2[k*128 + c];
        #pragma unroll
        for (int m = 0; m < 8; ++m) gg[m] += t_s[m*128 + k] * w;
    }

    const float fs = fsp[0];
    const int lane = c & 31, warp = c >> 5;
    for (int m = 0; m < 8; ++m) {
        const float* vp = g_v + (size_t)((n0+m)*128 + c)*3;
        float p0 = vp[0]*gg[m], p1 = vp[1]*gg[m], p2 = vp[2]*gg[m];
        #pragma unroll
        for (int off = 16; off; off >>= 1) {
            p0 += __shfl_down_sync(0xffffffffu, p0, off);
            p1 += __shfl_down_sync(0xffffffffu, p1, off);
            p2 += __shfl_down_sync(0xffffffffu, p2, off);
        }
        if (lane == 0) { wred[warp][0]=p0; wred[warp][1]=p1; wred[warp][2]=p2; }
        __syncthreads();
        if (c == 0) {
            float o0 = wred[0][0]+wred[1][0]+wred[2][0]+wred[3][0];
            float o1 = wred[0][1]+wred[1][1]+wred[2][1]+wred[3][1];
            float o2 = wred[0][2]+wred[1][2]+wred[2][2]+wred[3][2];
            out[(n0+m)*3 + 0] = o0*fs;
            out[(n0+m)*3 + 1] = o1*fs;
            out[(n0+m)*3 + 2] = o2*fs;
        }
        __syncthreads();
    }
}

// ---------------- launch ---------------------------------------------------
extern "C" void kernel_launch(void* const* d_in, const int* in_sizes, int n_in,
                              void* d_out, int out_size) {
    const float* positions = (const float*)d_in[0];
    const int*   nodef     = (const int*)  d_in[1];
    const float* gf        = (const float*)d_in[2];
    const float* emb       = (const float*)d_in[3];
    const float* Wt        = (const float*)d_in[4];
    const float* Wr1       = (const float*)d_in[5];
    const float* Wr2       = (const float*)d_in[6];
    const float* Wupd      = (const float*)d_in[7];
    const float* Wmix      = (const float*)d_in[8];
    const float* Wg1       = (const float*)d_in[9];
    const float* Wg2       = (const float*)d_in[10];
    const float* fs        = (const float*)d_in[11];
    float*       out       = (float*)d_out;

    const int msg_smem = (Nn*Hh + Hh*Hh + NBb*Hh + Hh*Nn + Nn*3 + Nn*3 + NBb*Nn + 16*Hh) * 4;
    cudaFuncSetAttribute(msg_kernel, cudaFuncAttributeMaxDynamicSharedMemorySize, msg_smem);

    probe_kernel<<<1, 1>>>(nodef);
    init_kernel<<<Bb*Nn, Hh>>>(nodef, gf, emb, Wt);

    for (int l = 0; l < Ll; ++l) {
        dim3 grid(Nn/JPB, Bb);
        msg_kernel<<<grid, 256, msg_smem>>>(positions,
                                            Wr1 + l*NBb*Hh,
                                            Wr2 + l*Hh*Hh);
        upd_kernel<<<Bb*Nn/8, Hh>>>(Wupd + l*Hh*Hh, Wmix + l*Hh*Hh);
    }
    readout_kernel<<<Bb*Nn/8, Hh>>>(Wg1, Wg2, fs, out);
}

// round 2
// speedup vs baseline: 1.1724x; 1.1724x over previous
#include <cuda_runtime.h>
#include <math.h>

// Problem constants
#define Bb   64
#define Nn   64
#define Hh   128
#define NBb  8
#define Tt   32
#define Ll   2
#define JPB  8          // receivers per CTA in message kernel (processed in pairs)

// ---------------- device scratch (no allocations allowed) ----------------
__device__ float g_h [Bb*Nn*Hh];          // node scalar features            (2 MB)
__device__ float g_v [Bb*Nn*3*Hh];        // vector features SoA [n][d][c]   (6 MB)
__device__ float g_a0[Bb*Nn*Hh];          // scalar aggregates               (2 MB)
__device__ float g_a1[Bb*Nn*3*Hh];        // vector aggregates SoA [n][d][c] (6 MB)
__device__ int   g_z64;                   // species dtype flag

// ---------------- K0: probe node_features dtype -------------------------
__global__ void probe_kernel(const int* __restrict__ z) {
    int nz = 0;
    for (int t = 0; t < 64; ++t) nz |= z[2*t + 1];
    g_z64 = (nz == 0) ? 1 : 0;
}

// ---------------- K1: h = emb[z] + t @ Wt ; v = 0 -----------------------
__global__ void init_kernel(const int* __restrict__ z,
                            const float* __restrict__ gf,
                            const float* __restrict__ emb,
                            const float* __restrict__ Wt) {
    const int node = blockIdx.x;          // 0..B*N-1
    const int c    = threadIdx.x;         // 0..127
    const int b    = node >> 6;
    const int zi   = g_z64 ? z[2*node] : z[node];
    float acc = emb[zi*Hh + c];
    const float* g = gf + b*Tt;
    #pragma unroll
    for (int t = 0; t < Tt; ++t) acc += g[t] * Wt[t*Hh + c];
    g_h[node*Hh + c] = acc;
    g_v[node*3*Hh + 0*Hh + c] = 0.f;
    g_v[node*3*Hh + 1*Hh + c] = 0.f;
    g_v[node*3*Hh + 2*Hh + c] = 0.f;
}

// ---------------- K2: message pass (hot kernel) --------------------------
// CTA = (batch b, group of 8 receivers), 512 threads, 2 receivers in flight.
// Per receiver j:
//   S[k][i] = silu( rb(i->j) @ Wr1 )
//   W[i][c] = sum_k S[k][i] * Wr2[k][c]      (register-tiled GEMM)
//   a0[j][c]    = sum_i W[i][c]*h[i][c] / 63
//   a1[j][d][c] = sum_i W[i][c]*h[i][c]*u(i->j)[d] / 63
__global__ __launch_bounds__(512, 1)
void msg_kernel(const float* __restrict__ pos,
                const float* __restrict__ Wr1,
                const float* __restrict__ Wr2) {
    extern __shared__ float sm[];
    float* h_s    = sm;                       // 8192   [64][128]
    float* Wr2_s  = h_s    + Nn*Hh;           // 16384  [128][128]
    float* Wr1_s  = Wr2_s  + Hh*Hh;           // 1024   [8][128]
    float* S_s    = Wr1_s  + NBb*Hh;          // 16384  [2][k=128][i=64]
    float* pos_s  = S_s    + 2*Hh*Nn;         // 192
    float* u_all  = pos_s  + Nn*3;            // 1536   [8][64][3]
    float* rb_all = u_all  + JPB*Nn*3;        // 4096   [8][8][64]
    float* red_s  = rb_all + JPB*NBb*Nn;      // 8192   [2][2][16][128]

    const int b   = blockIdx.y;
    const int jg  = blockIdx.x;               // 0..7
    const int tid = threadIdx.x;

    for (int idx = tid; idx < Nn*Hh;  idx += 512) h_s[idx]   = g_h[b*Nn*Hh + idx];
    for (int idx = tid; idx < Hh*Hh;  idx += 512) Wr2_s[idx] = Wr2[idx];
    for (int idx = tid; idx < NBb*Hh; idx += 512) Wr1_s[idx] = Wr1[idx];
    for (int idx = tid; idx < Nn*3;   idx += 512) pos_s[idx] = pos[b*Nn*3 + idx];
    __syncthreads();

    const float PI5 = 0.62831853071795864769f;   // pi / 5

    // ---- geometry + bessel for all 8 receivers at once (512 = 8j x 64i) ----
    {
        const int jl = tid >> 6;              // 0..7
        const int i  = tid & 63;
        const int j  = jg*JPB + jl;
        float dx = pos_s[j*3+0] - pos_s[i*3+0];
        float dy = pos_s[j*3+1] - pos_s[i*3+1];
        float dz = pos_s[j*3+2] - pos_s[i*3+2];
        float r2 = dx*dx + dy*dy + dz*dz + 1e-12f;
        float r  = sqrtf(r2);
        float inv = 1.0f / r;
        u_all[(jl*Nn + i)*3 + 0] = dx*inv;
        u_all[(jl*Nn + i)*3 + 1] = dy*inv;
        u_all[(jl*Nn + i)*3 + 2] = dz*inv;
        float fc = 0.0f;
        if (r < 5.0f && i != j) fc = 0.5f * (cosf(PI5 * r) + 1.0f);
        float sc  = inv * fc;
        float arg = PI5 * r;
        #pragma unroll
        for (int q = 0; q < NBb; ++q)
            rb_all[jl*NBb*Nn + q*Nn + i] = sinf((float)(q+1) * arg) * sc;
    }
    __syncthreads();

    const int half = tid >> 8;                // 0/1: which receiver of the pair
    const int t    = tid & 255;
    const int ig   = t >> 4;                  // 0..15 i-tile
    const int cg   = t & 15;                  // 0..15 c-tile
    const int i0   = ig * 4;
    const int c0   = cg * 8;
    const float s63 = 1.0f / 63.0f;

    for (int jj = 0; jj < JPB/2; ++jj) {
        const int jl2 = jj*2 + half;
        const int j   = jg*JPB + jl2;
        float* Sh = S_s + half*Hh*Nn;

        // ---- S = silu(rb @ Wr1), stored transposed [k][i] ----
        const float* rbj = rb_all + jl2*NBb*Nn;
        for (int idx = t; idx < Hh*Nn; idx += 256) {
            int k = idx >> 6, i = idx & 63;
            float x = 0.f;
            #pragma unroll
            for (int q = 0; q < NBb; ++q) x += rbj[q*Nn + i] * Wr1_s[q*Hh + k];
            Sh[k*Nn + i] = x / (1.0f + __expf(-x));
        }
        __syncthreads();                                          // (1)

        // ---- register-tiled GEMM: W[i0..i0+3][c0..c0+7] ----
        float acc[4][8];
        #pragma unroll
        for (int r = 0; r < 4; ++r)
            #pragma unroll
            for (int c = 0; c < 8; ++c) acc[r][c] = 0.f;

        #pragma unroll 4
        for (int k = 0; k < Hh; ++k) {
            float4 wa = *(const float4*)(Wr2_s + k*Hh + c0);
            float4 wb = *(const float4*)(Wr2_s + k*Hh + c0 + 4);
            float4 s4 = *(const float4*)(Sh + k*Nn + i0);
            float w2[8] = {wa.x, wa.y, wa.z, wa.w, wb.x, wb.y, wb.z, wb.w};
            float sr[4] = {s4.x, s4.y, s4.z, s4.w};
            #pragma unroll
            for (int r = 0; r < 4; ++r)
                #pragma unroll
                for (int c = 0; c < 8; ++c) acc[r][c] += sr[r] * w2[c];
        }

        // ---- fuse with h[snd] and u -> partial a0/a1 ----
        float pa0[8], pax[8], pay[8], paz[8];
        #pragma unroll
        for (int c = 0; c < 8; ++c) { pa0[c]=0.f; pax[c]=0.f; pay[c]=0.f; paz[c]=0.f; }
        #pragma unroll
        for (int r = 0; r < 4; ++r) {
            int i = i0 + r;
            const float* up = u_all + (jl2*Nn + i)*3;
            float ux = up[0], uy = up[1], uz = up[2];
            float4 ha = *(const float4*)(h_s + i*Hh + c0);
            float4 hb = *(const float4*)(h_s + i*Hh + c0 + 4);
            float hv[8] = {ha.x, ha.y, ha.z, ha.w, hb.x, hb.y, hb.z, hb.w};
            #pragma unroll
            for (int c = 0; c < 8; ++c) {
                float m = acc[r][c] * hv[c];
                pa0[c] += m; pax[c] += m*ux; pay[c] += m*uy; paz[c] += m*uz;
            }
        }

        const int nidx = b*Nn + j;
        float* redh = red_s + half*2*16*Hh;

        // ---- reduction round 1: a0, a1x ----
        #pragma unroll
        for (int c = 0; c < 8; ++c) {
            redh[0*16*Hh + ig*Hh + c0 + c] = pa0[c];
            redh[1*16*Hh + ig*Hh + c0 + c] = pax[c];
        }
        __syncthreads();                                          // (2)
        {
            int q = t >> 7, ch = t & 127;
            const float* rp = redh + q*16*Hh + ch;
            float s = 0.f;
            #pragma unroll
            for (int g = 0; g < 16; ++g) s += rp[g*Hh];
            s *= s63;
            if (q == 0) g_a0[nidx*Hh + ch] = s;
            else        g_a1[(nidx*3 + 0)*Hh + ch] = s;
        }
        __syncthreads();                                          // (3)

        // ---- reduction round 2: a1y, a1z ----
        #pragma unroll
        for (int c = 0; c < 8; ++c) {
            redh[0*16*Hh + ig*Hh + c0 + c] = pay[c];
            redh[1*16*Hh + ig*Hh + c0 + c] = paz[c];
        }
        __syncthreads();                                          // (4)
        {
            int q = t >> 7, ch = t & 127;
            const float* rp = redh + q*16*Hh + ch;
            float s = 0.f;
            #pragma unroll
            for (int g = 0; g < 16; ++g) s += rp[g*Hh];
            s *= s63;
            g_a1[(nidx*3 + 1 + q)*Hh + ch] = s;
        }
        __syncthreads();                                          // (5) guards next S write
    }
}

// ---------------- K3: h += a0 @ Wupd ; v += einsum(a1, Wmix) -------------
// 512 threads, 16 nodes/CTA, weights staged in smem.
__global__ __launch_bounds__(512, 1)
void upd_kernel(const float* __restrict__ Wupd,
                const float* __restrict__ Wmix) {
    extern __shared__ float usm[];
    float* Wu_s = usm;                  // 16384
    float* Wm_s = Wu_s + Hh*Hh;         // 16384
    float* a0_s = Wm_s + Hh*Hh;         // 2048   [16][128]
    float* a1_s = a0_s + 16*Hh;         // 6144   [16][3][128]

    const int n0  = blockIdx.x * 16;
    const int tid = threadIdx.x;
    for (int idx = tid; idx < Hh*Hh; idx += 512) { Wu_s[idx] = Wupd[idx]; Wm_s[idx] = Wmix[idx]; }
    for (int idx = tid; idx < 16*Hh;   idx += 512) a0_s[idx] = g_a0[n0*Hh + idx];
    for (int idx = tid; idx < 16*3*Hh; idx += 512) a1_s[idx] = g_a1[n0*3*Hh + idx];
    __syncthreads();

    const int c  = tid & 127;
    const int qt = tid >> 7;            // 0..3 -> nodes qt*4..qt*4+3
    float ah[4]; float av[4][3];
    #pragma unroll
    for (int m = 0; m < 4; ++m) { ah[m]=0.f; av[m][0]=0.f; av[m][1]=0.f; av[m][2]=0.f; }

    #pragma unroll 4
    for (int g = 0; g < Hh; ++g) {
        float wu = Wu_s[g*Hh + c];
        float wm = Wm_s[g*Hh + c];
        #pragma unroll
        for (int m = 0; m < 4; ++m) {
            int nm = qt*4 + m;
            ah[m]    += a0_s[nm*Hh + g] * wu;
            av[m][0] += a1_s[(nm*3 + 0)*Hh + g] * wm;
            av[m][1] += a1_s[(nm*3 + 1)*Hh + g] * wm;
            av[m][2] += a1_s[(nm*3 + 2)*Hh + g] * wm;
        }
    }
    #pragma unroll
    for (int m = 0; m < 4; ++m) {
        int n = n0 + qt*4 + m;
        g_h[n*Hh + c] += ah[m];
        g_v[(n*3 + 0)*Hh + c] += av[m][0];
        g_v[(n*3 + 1)*Hh + c] += av[m][1];
        g_v[(n*3 + 2)*Hh + c] += av[m][2];
    }
}

// ---------------- K4: gated readout --------------------------------------
__global__ void readout_kernel(const float* __restrict__ Wg1,
                               const float* __restrict__ Wg2,
                               const float* __restrict__ fsp,
                               float* __restrict__ out) {
    __shared__ float h_s[8*128];
    __shared__ float t_s[8*128];
    __shared__ float wred[4][3];
    const int n0 = blockIdx.x * 8;
    const int c  = threadIdx.x;
    for (int idx = c; idx < 8*128; idx += 128) h_s[idx] = g_h[n0*128 + idx];
    __syncthreads();

    float t[8];
    #pragma unroll
    for (int m = 0; m < 8; ++m) t[m] = 0.f;
    for (int g = 0; g < 128; ++g) {
        float w = Wg1[g*128 + c];
        #pragma unroll
        for (int m = 0; m < 8; ++m) t[m] += h_s[m*128 + g] * w;
    }
    #pragma unroll
    for (int m = 0; m < 8; ++m) t_s[m*128 + c] = t[m] / (1.0f + __expf(-t[m]));
    __syncthreads();

    float gg[8];
    #pragma unroll
    for (int m = 0; m < 8; ++m) gg[m] = 0.f;
    for (int k = 0; k < 128; ++k) {
        float w = Wg2[k*128 + c];
        #pragma unroll
        for (int m = 0; m < 8; ++m) gg[m] += t_s[m*128 + k] * w;
    }

    const float fs = fsp[0];
    const int lane = c & 31, warp = c >> 5;
    for (int m = 0; m < 8; ++m) {
        const int n = n0 + m;
        float p0 = g_v[(n*3 + 0)*128 + c] * gg[m];
        float p1 = g_v[(n*3 + 1)*128 + c] * gg[m];
        float p2 = g_v[(n*3 + 2)*128 + c] * gg[m];
        #pragma unroll
        for (int off = 16; off; off >>= 1) {
            p0 += __shfl_down_sync(0xffffffffu, p0, off);
            p1 += __shfl_down_sync(0xffffffffu, p1, off);
            p2 += __shfl_down_sync(0xffffffffu, p2, off);
        }
        if (lane == 0) { wred[warp][0]=p0; wred[warp][1]=p1; wred[warp][2]=p2; }
        __syncthreads();
        if (c == 0) {
            out[n*3 + 0] = (wred[0][0]+wred[1][0]+wred[2][0]+wred[3][0])*fs;
            out[n*3 + 1] = (wred[0][1]+wred[1][1]+wred[2][1]+wred[3][1])*fs;
            out[n*3 + 2] = (wred[0][2]+wred[1][2]+wred[2][2]+wred[3][2])*fs;
        }
        __syncthreads();
    }
}

// ---------------- launch ---------------------------------------------------
extern "C" void kernel_launch(void* const* d_in, const int* in_sizes, int n_in,
                              void* d_out, int out_size) {
    const float* positions = (const float*)d_in[0];
    const int*   nodef     = (const int*)  d_in[1];
    const float* gf        = (const float*)d_in[2];
    const float* emb       = (const float*)d_in[3];
    const float* Wt        = (const float*)d_in[4];
    const float* Wr1       = (const float*)d_in[5];
    const float* Wr2       = (const float*)d_in[6];
    const float* Wupd      = (const float*)d_in[7];
    const float* Wmix      = (const float*)d_in[8];
    const float* Wg1       = (const float*)d_in[9];
    const float* Wg2       = (const float*)d_in[10];
    const float* fs        = (const float*)d_in[11];
    float*       out       = (float*)d_out;

    const int msg_smem = (Nn*Hh + Hh*Hh + NBb*Hh + 2*Hh*Nn + Nn*3
                          + JPB*Nn*3 + JPB*NBb*Nn + 2*2*16*Hh) * 4;   // 224000 B
    const int upd_smem = (Hh*Hh*2 + 16*Hh + 16*3*Hh) * 4;             // 163840 B
    cudaFuncSetAttribute(msg_kernel, cudaFuncAttributeMaxDynamicSharedMemorySize, msg_smem);
    cudaFuncSetAttribute(upd_kernel, cudaFuncAttributeMaxDynamicSharedMemorySize, upd_smem);

    probe_kernel<<<1, 1>>>(nodef);
    init_kernel<<<Bb*Nn, Hh>>>(nodef, gf, emb, Wt);

    for (int l = 0; l < Ll; ++l) {
        dim3 grid(Nn/JPB, Bb);
        msg_kernel<<<grid, 512, msg_smem>>>(positions,
                                            Wr1 + l*NBb*Hh,
                                            Wr2 + l*Hh*Hh);
        upd_kernel<<<Bb*Nn/16, 512, upd_smem>>>(Wupd + l*Hh*Hh, Wmix + l*Hh*Hh);
    }
    readout_kernel<<<Bb*Nn/8, Hh>>>(Wg1, Wg2, fs, out);
}

// round 4
// speedup vs baseline: 2.4754x; 2.1113x over previous
#include <cuda_runtime.h>
#include <math.h>
#include <stdint.h>

// Problem constants
#define Bb   64
#define Nn   64
#define Hh   128
#define NBb  8
#define Tt   32
#define Ll   2
#define PITCH 136        // smem row pitch (floats) for S / Wr2T fragments

// ---------------- device scratch (no allocations allowed) ----------------
__device__ float    g_h   [Bb*Nn*Hh];      // node scalar features
__device__ float    g_v   [Bb*Nn*3*Hh];    // vector features SoA [n][d][c]
__device__ float    g_a0  [Bb*Nn*Hh];      // scalar aggregates
__device__ float    g_a1  [Bb*Nn*3*Hh];    // vector aggregates SoA [n][d][c]
__device__ uint32_t g_Wr2T[Ll*Hh*Hh];      // Wr2 transposed [c][k], tf32-rounded
__device__ int      g_z64;                 // species dtype flag

// ---------------- helpers -------------------------------------------------
__device__ __forceinline__ uint32_t f2tf32(float x) {
    uint32_t r;
    asm("cvt.rn.tf32.f32 %0, %1;" : "=r"(r) : "f"(x));
    return r;
}
// within-k8 permutation: fragment lanes read (t, t+4) as adjacent pair
__device__ __forceinline__ int kperm(int k) {
    int k7 = k & 7;
    return (k & ~7) | ((k7 & 3) << 1) | (k7 >> 2);
}
__device__ __forceinline__ void mma_tf32(float* c,
                                         uint32_t a0, uint32_t a1, uint32_t a2, uint32_t a3,
                                         uint32_t b0, uint32_t b1) {
    asm volatile(
        "mma.sync.aligned.m16n8k8.row.col.f32.tf32.tf32.f32 "
        "{%0,%1,%2,%3},{%4,%5,%6,%7},{%8,%9},{%0,%1,%2,%3};"
        : "+f"(c[0]), "+f"(c[1]), "+f"(c[2]), "+f"(c[3])
        : "r"(a0), "r"(a1), "r"(a2), "r"(a3), "r"(b0), "r"(b1));
}

// ---------------- K0: probe node_features dtype -------------------------
__global__ void probe_kernel(const int* __restrict__ z) {
    int nz = 0;
    for (int t = 0; t < 64; ++t) nz |= z[2*t + 1];
    g_z64 = (nz == 0) ? 1 : 0;
}

// ---------------- K1: h = emb[z] + t @ Wt ; v = 0 -----------------------
__global__ void init_kernel(const int* __restrict__ z,
                            const float* __restrict__ gf,
                            const float* __restrict__ emb,
                            const float* __restrict__ Wt) {
    const int node = blockIdx.x;
    const int c    = threadIdx.x;
    const int b    = node >> 6;
    const int zi   = g_z64 ? z[2*node] : z[node];
    float acc = emb[zi*Hh + c];
    const float* g = gf + b*Tt;
    #pragma unroll
    for (int t = 0; t < Tt; ++t) acc += g[t] * Wt[t*Hh + c];
    g_h[node*Hh + c] = acc;
    g_v[node*3*Hh + 0*Hh + c] = 0.f;
    g_v[node*3*Hh + 1*Hh + c] = 0.f;
    g_v[node*3*Hh + 2*Hh + c] = 0.f;
}

// ---------------- K1b: Wr2T = round_tf32(Wr2^T) --------------------------
__global__ void wr2t_kernel(const float* __restrict__ Wr2) {
    const int l = blockIdx.x;
    for (int idx = threadIdx.x; idx < Hh*Hh; idx += 256) {
        int c = idx >> 7, k = idx & 127;
        g_Wr2T[l*Hh*Hh + idx] = f2tf32(Wr2[l*Hh*Hh + k*Hh + c]);
    }
}

// ---------------- K2: message pass (mma.sync tf32) ------------------------
// CTA = (8 receivers jg, batch b), 512 threads = 2 halves x 8 warps.
// Per receiver j (one half):
//   S[i][k] = silu(rb @ Wr1)  (tf32, fragment layout)
//   W = S @ Wr2   via mma.sync m16n8k8 tf32  (warp w: n-cols [16w,16w+16))
//   fused epilogue: a0[j][c] = sum_i W[i][c] h[i][c] / 63, a1 likewise * u
__global__ __launch_bounds__(512, 1)
void msg_kernel(const float* __restrict__ pos,
                const float* __restrict__ Wr1,
                int layer) {
    extern __shared__ float smf[];
    float* W2T   = smf;                     // 128*136 = 17408
    float* S     = W2T   + Hh*PITCH;        // 2*64*136 = 17408
    float* h_s   = S     + 2*Nn*PITCH;      // 8192
    float* rb    = h_s   + Nn*Hh;           // 8*8*64 = 4096
    float* u_a   = rb    + 8*NBb*Nn;        // 8*3*64 = 1536
    float* pos_s = u_a   + 8*3*Nn;          // 192
    float* w1    = pos_s + Nn*3;            // 1024

    const int b    = blockIdx.y;
    const int jg   = blockIdx.x;            // 0..7
    const int tid  = threadIdx.x;
    const int lane = tid & 31;
    const int wid  = tid >> 5;
    const int half = wid >> 3;              // 0/1
    const int widh = wid & 7;               // warp within half

    // ---- stage: Wr2T (fragment layout), h, pos, Wr1 ----
    for (int idx = tid; idx < Hh*Hh; idx += 512) {
        int c = idx >> 7, k = idx & 127;
        ((uint32_t*)W2T)[c*PITCH + kperm(k)] = g_Wr2T[layer*Hh*Hh + idx];
    }
    for (int idx = tid; idx < Nn*Hh;  idx += 512) h_s[idx]   = g_h[b*Nn*Hh + idx];
    for (int idx = tid; idx < Nn*3;   idx += 512) pos_s[idx] = pos[b*Nn*3 + idx];
    for (int idx = tid; idx < NBb*Hh; idx += 512) w1[idx]    = Wr1[idx];
    __syncthreads();

    const float PI5 = 0.62831853071795864769f;   // pi/5
    const float s63 = 1.0f / 63.0f;

    // ---- geometry + bessel for all 8 receivers (512 = 8j x 64i) ----
    {
        const int jl = tid >> 6;             // 0..7
        const int i  = tid & 63;
        const int j  = jg*8 + jl;
        float dx = pos_s[j*3+0] - pos_s[i*3+0];
        float dy = pos_s[j*3+1] - pos_s[i*3+1];
        float dz = pos_s[j*3+2] - pos_s[i*3+2];
        float r2 = dx*dx + dy*dy + dz*dz + 1e-12f;
        float r  = sqrtf(r2);
        float inv = 1.0f / r;
        u_a[jl*192 + 0*64 + i] = dx*inv;
        u_a[jl*192 + 1*64 + i] = dy*inv;
        u_a[jl*192 + 2*64 + i] = dz*inv;
        float fc = 0.0f;
        if (r < 5.0f && i != j) fc = 0.5f * (cosf(PI5 * r) + 1.0f);
        float sc  = inv * fc;
        float arg = PI5 * r;
        #pragma unroll
        for (int q = 0; q < NBb; ++q)
            rb[(jl*NBb + q)*64 + i] = sinf((float)(q+1) * arg) * sc;
    }
    __syncthreads();

    float* Sh = S + half*Nn*PITCH;
    const int t8 = tid & 255;

    for (int jj = 0; jj < 4; ++jj) {
        const int jl2 = jj*2 + half;
        const int j   = jg*8 + jl2;

        // ---- S = silu(rb @ Wr1) -> tf32, fragment layout ----
        const float* rbj = rb + jl2*NBb*64;
        #pragma unroll 4
        for (int it = 0; it < 32; ++it) {
            int idx = it*256 + t8;
            int row = idx >> 7, k = idx & 127;
            float x = 0.f;
            #pragma unroll
            for (int q = 0; q < NBb; ++q) x += rbj[q*64 + row] * w1[q*Hh + k];
            float sv = x / (1.0f + __expf(-x));
            ((uint32_t*)Sh)[row*PITCH + kperm(k)] = f2tf32(sv);
        }
        __syncthreads();

        // ---- warp GEMM: acc[mt][nt] covers rows mt*16.., cols widh*16 + nt*8.. ----
        float acc[8][4];
        #pragma unroll
        for (int q = 0; q < 8; ++q) { acc[q][0]=0.f; acc[q][1]=0.f; acc[q][2]=0.f; acc[q][3]=0.f; }

        const uint32_t* Ap = (const uint32_t*)Sh  + (lane>>2)*PITCH + (lane&3)*2;
        const uint32_t* Bp = (const uint32_t*)W2T + (widh*16 + (lane>>2))*PITCH + (lane&3)*2;

        #pragma unroll 4
        for (int kb = 0; kb < 16; ++kb) {
            uint2 Bv0 = *(const uint2*)(Bp + kb*8);
            uint2 Bv1 = *(const uint2*)(Bp + 8*PITCH + kb*8);
            #pragma unroll
            for (int mt = 0; mt < 4; ++mt) {
                uint2 A0 = *(const uint2*)(Ap + mt*16*PITCH + kb*8);
                uint2 A1 = *(const uint2*)(Ap + mt*16*PITCH + 8*PITCH + kb*8);
                mma_tf32(acc[mt*2+0], A0.x, A1.x, A0.y, A1.y, Bv0.x, Bv0.y);
                mma_tf32(acc[mt*2+1], A0.x, A1.x, A0.y, A1.y, Bv1.x, Bv1.y);
            }
        }

        // ---- fused epilogue: multiply by h[i][c], u; reduce over rows ----
        float pa[2][2][4];
        #pragma unroll
        for (int nt = 0; nt < 2; ++nt)
            #pragma unroll
            for (int cp = 0; cp < 2; ++cp) {
                pa[nt][cp][0]=0.f; pa[nt][cp][1]=0.f; pa[nt][cp][2]=0.f; pa[nt][cp][3]=0.f;
            }
        const float* uj = u_a + jl2*192;
        #pragma unroll
        for (int mt = 0; mt < 4; ++mt) {
            #pragma unroll
            for (int rg = 0; rg < 2; ++rg) {
                int i = mt*16 + (lane>>2) + rg*8;
                float ux = uj[0*64 + i], uy = uj[1*64 + i], uz = uj[2*64 + i];
                const float* hrow = h_s + i*Hh + widh*16 + (lane&3)*2;
                #pragma unroll
                for (int nt = 0; nt < 2; ++nt) {
                    #pragma unroll
                    for (int cp = 0; cp < 2; ++cp) {
                        float m = acc[mt*2+nt][rg*2+cp] * hrow[nt*8 + cp];
                        pa[nt][cp][0] += m;
                        pa[nt][cp][1] = fmaf(m, ux, pa[nt][cp][1]);
                        pa[nt][cp][2] = fmaf(m, uy, pa[nt][cp][2]);
                        pa[nt][cp][3] = fmaf(m, uz, pa[nt][cp][3]);
                    }
                }
            }
        }
        #pragma unroll
        for (int nt = 0; nt < 2; ++nt)
            #pragma unroll
            for (int cp = 0; cp < 2; ++cp)
                #pragma unroll
                for (int q = 0; q < 4; ++q) {
                    float v = pa[nt][cp][q];
                    v += __shfl_xor_sync(0xffffffffu, v, 4);
                    v += __shfl_xor_sync(0xffffffffu, v, 8);
                    v += __shfl_xor_sync(0xffffffffu, v, 16);
                    pa[nt][cp][q] = v;
                }
        if (lane < 4) {
            const int nidx = b*Nn + j;
            #pragma unroll
            for (int nt = 0; nt < 2; ++nt)
                #pragma unroll
                for (int cp = 0; cp < 2; ++cp) {
                    int c = widh*16 + nt*8 + lane*2 + cp;
                    g_a0[nidx*Hh + c]         = pa[nt][cp][0] * s63;
                    g_a1[(nidx*3+0)*Hh + c]   = pa[nt][cp][1] * s63;
                    g_a1[(nidx*3+1)*Hh + c]   = pa[nt][cp][2] * s63;
                    g_a1[(nidx*3+2)*Hh + c]   = pa[nt][cp][3] * s63;
                }
        }
        __syncthreads();   // guard Sh overwrite next iteration
    }
}

// ---------------- K3: h += a0 @ Wupd ; v += einsum(a1, Wmix) -------------
#define UP0 20
__global__ __launch_bounds__(512, 1)
void upd_kernel(const float* __restrict__ Wupd,
                const float* __restrict__ Wmix) {
    extern __shared__ float usm[];
    float* Wu_s = usm;                       // 16384
    float* Wm_s = Wu_s + Hh*Hh;              // 16384
    float* a0T  = Wm_s + Hh*Hh;              // 128*20
    float* a1T  = a0T + Hh*UP0;              // 384*20

    const int n0  = blockIdx.x * 16;
    const int tid = threadIdx.x;
    for (int idx = tid; idx < Hh*Hh; idx += 512) { Wu_s[idx] = Wupd[idx]; Wm_s[idx] = Wmix[idx]; }
    for (int idx = tid; idx < 16*Hh; idx += 512) {
        int n = idx >> 7, g = idx & 127;
        a0T[g*UP0 + n] = g_a0[n0*Hh + idx];
    }
    for (int idx = tid; idx < 16*3*Hh; idx += 512) {
        int n = idx / 384, r = idx - n*384;
        int d = r >> 7, g = r & 127;
        a1T[(g*3 + d)*UP0 + n] = g_a1[(size_t)n0*3*Hh + idx];
    }
    __syncthreads();

    const int c  = tid & 127;
    const int qt = tid >> 7;
    float ah[4], avx[4], avy[4], avz[4];
    #pragma unroll
    for (int m = 0; m < 4; ++m) { ah[m]=0.f; avx[m]=0.f; avy[m]=0.f; avz[m]=0.f; }

    #pragma unroll 2
    for (int g = 0; g < Hh; ++g) {
        float wu = Wu_s[g*Hh + c];
        float wm = Wm_s[g*Hh + c];
        float4 a0v = *(const float4*)(a0T + g*UP0 + qt*4);
        float4 a1x = *(const float4*)(a1T + (g*3 + 0)*UP0 + qt*4);
        float4 a1y = *(const float4*)(a1T + (g*3 + 1)*UP0 + qt*4);
        float4 a1z = *(const float4*)(a1T + (g*3 + 2)*UP0 + qt*4);
        const float* a0p = (const float*)&a0v;
        const float* axp = (const float*)&a1x;
        const float* ayp = (const float*)&a1y;
        const float* azp = (const float*)&a1z;
        #pragma unroll
        for (int m = 0; m < 4; ++m) {
            ah[m]  = fmaf(a0p[m], wu, ah[m]);
            avx[m] = fmaf(axp[m], wm, avx[m]);
            avy[m] = fmaf(ayp[m], wm, avy[m]);
            avz[m] = fmaf(azp[m], wm, avz[m]);
        }
    }
    #pragma unroll
    for (int m = 0; m < 4; ++m) {
        int n = n0 + qt*4 + m;
        g_h[n*Hh + c] += ah[m];
        g_v[(n*3 + 0)*Hh + c] += avx[m];
        g_v[(n*3 + 1)*Hh + c] += avy[m];
        g_v[(n*3 + 2)*Hh + c] += avz[m];
    }
}

// ---------------- K4: gated readout --------------------------------------
__global__ void readout_kernel(const float* __restrict__ Wg1,
                               const float* __restrict__ Wg2,
                               const float* __restrict__ fsp,
                               float* __restrict__ out) {
    __shared__ float h_s[8*128];
    __shared__ float t_s[8*128];
    __shared__ float wred[4][3];
    const int n0 = blockIdx.x * 8;
    const int c  = threadIdx.x;
    for (int idx = c; idx < 8*128; idx += 128) h_s[idx] = g_h[n0*128 + idx];
    __syncthreads();

    float t[8];
    #pragma unroll
    for (int m = 0; m < 8; ++m) t[m] = 0.f;
    for (int g = 0; g < 128; ++g) {
        float w = Wg1[g*128 + c];
        #pragma unroll
        for (int m = 0; m < 8; ++m) t[m] += h_s[m*128 + g] * w;
    }
    #pragma unroll
    for (int m = 0; m < 8; ++m) t_s[m*128 + c] = t[m] / (1.0f + __expf(-t[m]));
    __syncthreads();

    float gg[8];
    #pragma unroll
    for (int m = 0; m < 8; ++m) gg[m] = 0.f;
    for (int k = 0; k < 128; ++k) {
        float w = Wg2[k*128 + c];
        #pragma unroll
        for (int m = 0; m < 8; ++m) gg[m] += t_s[m*128 + k] * w;
    }

    const float fs = fsp[0];
    const int lane = c & 31, warp = c >> 5;
    for (int m = 0; m < 8; ++m) {
        const int n = n0 + m;
        float p0 = g_v[(n*3 + 0)*128 + c] * gg[m];
        float p1 = g_v[(n*3 + 1)*128 + c] * gg[m];
        float p2 = g_v[(n*3 + 2)*128 + c] * gg[m];
        #pragma unroll
        for (int off = 16; off; off >>= 1) {
            p0 += __shfl_down_sync(0xffffffffu, p0, off);
            p1 += __shfl_down_sync(0xffffffffu, p1, off);
            p2 += __shfl_down_sync(0xffffffffu, p2, off);
        }
        if (lane == 0) { wred[warp][0]=p0; wred[warp][1]=p1; wred[warp][2]=p2; }
        __syncthreads();
        if (c == 0) {
            out[n*3 + 0] = (wred[0][0]+wred[1][0]+wred[2][0]+wred[3][0])*fs;
            out[n*3 + 1] = (wred[0][1]+wred[1][1]+wred[2][1]+wred[3][1])*fs;
            out[n*3 + 2] = (wred[0][2]+wred[1][2]+wred[2][2]+wred[3][2])*fs;
        }
        __syncthreads();
    }
}

// ---------------- launch ---------------------------------------------------
extern "C" void kernel_launch(void* const* d_in, const int* in_sizes, int n_in,
                              void* d_out, int out_size) {
    const float* positions = (const float*)d_in[0];
    const int*   nodef     = (const int*)  d_in[1];
    const float* gf        = (const float*)d_in[2];
    const float* emb       = (const float*)d_in[3];
    const float* Wt        = (const float*)d_in[4];
    const float* Wr1       = (const float*)d_in[5];
    const float* Wr2       = (const float*)d_in[6];
    const float* Wupd      = (const float*)d_in[7];
    const float* Wmix      = (const float*)d_in[8];
    const float* Wg1       = (const float*)d_in[9];
    const float* Wg2       = (const float*)d_in[10];
    const float* fs        = (const float*)d_in[11];
    float*       out       = (float*)d_out;

    const int msg_smem = (Hh*PITCH + 2*Nn*PITCH + Nn*Hh + 8*NBb*Nn + 8*3*Nn + Nn*3 + NBb*Hh) * 4;
    const int upd_smem = (Hh*Hh*2 + Hh*UP0 + Hh*3*UP0) * 4;
    cudaFuncSetAttribute(msg_kernel, cudaFuncAttributeMaxDynamicSharedMemorySize, msg_smem);
    cudaFuncSetAttribute(upd_kernel, cudaFuncAttributeMaxDynamicSharedMemorySize, upd_smem);

    probe_kernel<<<1, 1>>>(nodef);
    init_kernel<<<Bb*Nn, Hh>>>(nodef, gf, emb, Wt);
    wr2t_kernel<<<Ll, 256>>>(Wr2);

    for (int l = 0; l < Ll; ++l) {
        dim3 grid(8, Bb);
        msg_kernel<<<grid, 512, msg_smem>>>(positions, Wr1 + l*NBb*Hh, l);
        upd_kernel<<<Bb*Nn/16, 512, upd_smem>>>(Wupd + l*Hh*Hh, Wmix + l*Hh*Hh);
    }
    readout_kernel<<<Bb*Nn/8, Hh>>>(Wg1, Wg2, fs, out);
}

// round 5
// speedup vs baseline: 2.8181x; 1.1384x over previous
#include <cuda_runtime.h>
#include <math.h>
#include <stdint.h>

// Problem constants
#define Bb   64
#define Nn   64
#define Hh   128
#define NBb  8
#define Tt   32
#define Ll   2
#define PITCH 136        // smem row pitch (floats) for S / Wr2T fragments

// ---------------- device scratch (no allocations allowed) ----------------
__device__ float    g_h   [Bb*Nn*Hh];      // node scalar features
__device__ float    g_v   [Bb*Nn*3*Hh];    // vector features SoA [n][d][c]
__device__ float    g_a0  [Bb*Nn*Hh];      // scalar aggregates
__device__ float    g_a1  [Bb*Nn*3*Hh];    // vector aggregates SoA [n][d][c]
__device__ uint32_t g_Wr2T[Ll*Hh*Hh];      // Wr2 transposed [c][k], tf32-rounded
__device__ int      g_z64;                 // species dtype flag

// ---------------- helpers -------------------------------------------------
__device__ __forceinline__ uint32_t f2tf32(float x) {
    uint32_t r;
    asm("cvt.rn.tf32.f32 %0, %1;" : "=r"(r) : "f"(x));
    return r;
}
// within-k8 permutation: fragment lanes read (t, t+4) as adjacent pair
__device__ __forceinline__ int kperm(int k) {
    int k7 = k & 7;
    return (k & ~7) | ((k7 & 3) << 1) | (k7 >> 2);
}
__device__ __forceinline__ void mma_tf32(float* c,
                                         uint32_t a0, uint32_t a1, uint32_t a2, uint32_t a3,
                                         uint32_t b0, uint32_t b1) {
    asm volatile(
        "mma.sync.aligned.m16n8k8.row.col.f32.tf32.tf32.f32 "
        "{%0,%1,%2,%3},{%4,%5,%6,%7},{%8,%9},{%0,%1,%2,%3};"
        : "+f"(c[0]), "+f"(c[1]), "+f"(c[2]), "+f"(c[3])
        : "r"(a0), "r"(a1), "r"(a2), "r"(a3), "r"(b0), "r"(b1));
}
__device__ __forceinline__ float silu_f(float x) {
    return x / (1.0f + __expf(-x));
}

// ---------------- K0: probe node_features dtype -------------------------
__global__ void probe_kernel(const int* __restrict__ z) {
    int nz = 0;
    for (int t = 0; t < 64; ++t) nz |= z[2*t + 1];
    g_z64 = (nz == 0) ? 1 : 0;
}

// ---------------- K1: h = emb[z] + t @ Wt ; v = 0 -----------------------
__global__ void init_kernel(const int* __restrict__ z,
                            const float* __restrict__ gf,
                            const float* __restrict__ emb,
                            const float* __restrict__ Wt) {
    const int node = blockIdx.x;
    const int c    = threadIdx.x;
    const int b    = node >> 6;
    const int zi   = g_z64 ? z[2*node] : z[node];
    float acc = emb[zi*Hh + c];
    const float* g = gf + b*Tt;
    #pragma unroll
    for (int t = 0; t < Tt; ++t) acc += g[t] * Wt[t*Hh + c];
    g_h[node*Hh + c] = acc;
    g_v[node*3*Hh + 0*Hh + c] = 0.f;
    g_v[node*3*Hh + 1*Hh + c] = 0.f;
    g_v[node*3*Hh + 2*Hh + c] = 0.f;
}

// ---------------- K1b: Wr2T = round_tf32(Wr2^T) --------------------------
__global__ void wr2t_kernel(const float* __restrict__ Wr2) {
    const int l = blockIdx.x;
    for (int idx = threadIdx.x; idx < Hh*Hh; idx += 256) {
        int c = idx >> 7, k = idx & 127;
        g_Wr2T[l*Hh*Hh + idx] = f2tf32(Wr2[l*Hh*Hh + k*Hh + c]);
    }
}

// ---------------- K2: message pass (fully tensorized) ---------------------
// CTA = (8 receivers jg, batch b), 512 threads = 2 halves x 8 warps.
// Per receiver j (one half, 8 warps):
//   x  = rb @ Wr1 via mma.sync (K=8, B-frags hoisted in regs), silu -> S (smem)
//   W  = S @ Wr2  via mma.sync m16n8k8 tf32 (warp: n-cols [16w,16w+16))
//   fused epilogue: a0[j][c] = sum_i W[i][c] h[i][c] / 63, a1 likewise * u
__global__ __launch_bounds__(512, 1)
void msg_kernel(const float* __restrict__ pos,
                const float* __restrict__ Wr1,
                int layer) {
    extern __shared__ float smf[];
    float*    W2T   = smf;                    // 128*136 = 17408
    float*    S     = W2T   + Hh*PITCH;       // 2*64*136 = 17408
    float*    h_s   = S     + 2*Nn*PITCH;     // 8192
    uint32_t* rbf   = (uint32_t*)(h_s + Nn*Hh); // 8 jl * 64 i * 8 perm-k (tf32) = 4096
    float*    u4f   = (float*)(rbf + 8*Nn*NBb);  // 8 jl * 64 i * 4 = 2048
    float*    pos_s = u4f   + 8*Nn*4;         // 192
    uint32_t* w1u   = (uint32_t*)(pos_s + Nn*3); // 8*128 tf32 = 1024

    const int b    = blockIdx.y;
    const int jg   = blockIdx.x;            // 0..7
    const int tid  = threadIdx.x;
    const int lane = tid & 31;
    const int wid  = tid >> 5;
    const int half = wid >> 3;              // 0/1
    const int widh = wid & 7;               // warp within half

    // ---- stage: Wr2T (fragment layout), h, pos, Wr1(tf32) ----
    for (int idx = tid; idx < Hh*Hh; idx += 512) {
        int c = idx >> 7, k = idx & 127;
        ((uint32_t*)W2T)[c*PITCH + kperm(k)] = g_Wr2T[layer*Hh*Hh + idx];
    }
    for (int idx = tid; idx < Nn*Hh;  idx += 512) h_s[idx]   = g_h[b*Nn*Hh + idx];
    for (int idx = tid; idx < Nn*3;   idx += 512) pos_s[idx] = pos[b*Nn*3 + idx];
    for (int idx = tid; idx < NBb*Hh; idx += 512) w1u[idx]   = f2tf32(Wr1[idx]);
    __syncthreads();

    const float PI5 = 0.62831853071795864769f;   // pi/5
    const float s63 = 1.0f / 63.0f;

    // ---- geometry + bessel for all 8 receivers (512 = 8j x 64i) ----
    {
        const int jl = tid >> 6;             // 0..7
        const int i  = tid & 63;
        const int j  = jg*8 + jl;
        float dx = pos_s[j*3+0] - pos_s[i*3+0];
        float dy = pos_s[j*3+1] - pos_s[i*3+1];
        float dz = pos_s[j*3+2] - pos_s[i*3+2];
        float r2 = dx*dx + dy*dy + dz*dz + 1e-12f;
        float r  = sqrtf(r2);
        float inv = 1.0f / r;
        ((float4*)u4f)[jl*Nn + i] = make_float4(dx*inv, dy*inv, dz*inv, 0.f);
        float fc = 0.0f;
        if (r < 5.0f && i != j) fc = 0.5f * (cosf(PI5 * r) + 1.0f);
        float sc  = inv * fc;
        float arg = PI5 * r;
        float rv[8];
        #pragma unroll
        for (int q = 0; q < NBb; ++q) rv[q] = sinf((float)(q+1) * arg) * sc;
        // store in A-frag perm order: [q0,q4,q1,q5 | q2,q6,q3,q7]
        uint4 lo = make_uint4(f2tf32(rv[0]), f2tf32(rv[4]), f2tf32(rv[1]), f2tf32(rv[5]));
        uint4 hi = make_uint4(f2tf32(rv[2]), f2tf32(rv[6]), f2tf32(rv[3]), f2tf32(rv[7]));
        ((uint4*)rbf)[(jl*Nn + i)*2 + 0] = lo;
        ((uint4*)rbf)[(jl*Nn + i)*2 + 1] = hi;
    }
    __syncthreads();

    // ---- hoist Wr1 B-frags (per warp: cols widh*16 .. +16) ----
    uint32_t wb00, wb01, wb10, wb11;
    {
        int colA = widh*16 + (lane>>2);
        int colB = colA + 8;
        int kq   = lane & 3;
        wb00 = w1u[kq*Hh + colA];  wb01 = w1u[(kq+4)*Hh + colA];
        wb10 = w1u[kq*Hh + colB];  wb11 = w1u[(kq+4)*Hh + colB];
    }

    float* Sh = S + half*Nn*PITCH;

    for (int jj = 0; jj < 4; ++jj) {
        const int jl2 = jj*2 + half;
        const int j   = jg*8 + jl2;

        // ---- S = silu(rb @ Wr1) via MMA (K=8) ----
        {
            float sacc[8][4];
            #pragma unroll
            for (int q = 0; q < 8; ++q) { sacc[q][0]=0.f; sacc[q][1]=0.f; sacc[q][2]=0.f; sacc[q][3]=0.f; }
            const uint32_t* rbj = rbf + jl2*Nn*NBb;
            #pragma unroll
            for (int mt = 0; mt < 4; ++mt) {
                int r0 = mt*16 + (lane>>2);
                uint2 A0 = *(const uint2*)(rbj + r0*8       + (lane&3)*2);
                uint2 A1 = *(const uint2*)(rbj + (r0+8)*8   + (lane&3)*2);
                mma_tf32(sacc[mt*2+0], A0.x, A1.x, A0.y, A1.y, wb00, wb01);
                mma_tf32(sacc[mt*2+1], A0.x, A1.x, A0.y, A1.y, wb10, wb11);
            }
            // silu + tf32 + store to S (A-frag layout)
            uint32_t* Su = (uint32_t*)Sh;
            #pragma unroll
            for (int mt = 0; mt < 4; ++mt) {
                int r0 = mt*16 + (lane>>2);
                #pragma unroll
                for (int nt = 0; nt < 2; ++nt) {
                    int col0 = widh*16 + nt*8 + (lane&3)*2;
                    int p0 = kperm(col0), p1 = kperm(col0 + 1);
                    const float* a = sacc[mt*2+nt];
                    Su[r0*PITCH + p0]     = f2tf32(silu_f(a[0]));
                    Su[r0*PITCH + p1]     = f2tf32(silu_f(a[1]));
                    Su[(r0+8)*PITCH + p0] = f2tf32(silu_f(a[2]));
                    Su[(r0+8)*PITCH + p1] = f2tf32(silu_f(a[3]));
                }
            }
        }
        __syncthreads();

        // ---- main warp GEMM: acc[mt][nt] rows mt*16.., cols widh*16 + nt*8.. ----
        float acc[8][4];
        #pragma unroll
        for (int q = 0; q < 8; ++q) { acc[q][0]=0.f; acc[q][1]=0.f; acc[q][2]=0.f; acc[q][3]=0.f; }

        const uint32_t* Ap = (const uint32_t*)Sh  + (lane>>2)*PITCH + (lane&3)*2;
        const uint32_t* Bp = (const uint32_t*)W2T + (widh*16 + (lane>>2))*PITCH + (lane&3)*2;

        #pragma unroll 4
        for (int kb = 0; kb < 16; ++kb) {
            uint2 Bv0 = *(const uint2*)(Bp + kb*8);
            uint2 Bv1 = *(const uint2*)(Bp + 8*PITCH + kb*8);
            #pragma unroll
            for (int mt = 0; mt < 4; ++mt) {
                uint2 A0 = *(const uint2*)(Ap + mt*16*PITCH + kb*8);
                uint2 A1 = *(const uint2*)(Ap + mt*16*PITCH + 8*PITCH + kb*8);
                mma_tf32(acc[mt*2+0], A0.x, A1.x, A0.y, A1.y, Bv0.x, Bv0.y);
                mma_tf32(acc[mt*2+1], A0.x, A1.x, A0.y, A1.y, Bv1.x, Bv1.y);
            }
        }

        // ---- fused epilogue: multiply by h[i][c], u; reduce over rows ----
        float pa[2][2][4];
        #pragma unroll
        for (int nt = 0; nt < 2; ++nt)
            #pragma unroll
            for (int cp = 0; cp < 2; ++cp) {
                pa[nt][cp][0]=0.f; pa[nt][cp][1]=0.f; pa[nt][cp][2]=0.f; pa[nt][cp][3]=0.f;
            }
        const float4* uj = (const float4*)u4f + jl2*Nn;
        #pragma unroll
        for (int mt = 0; mt < 4; ++mt) {
            #pragma unroll
            for (int rg = 0; rg < 2; ++rg) {
                int i = mt*16 + (lane>>2) + rg*8;
                float4 uv = uj[i];
                const float* hrow = h_s + i*Hh + widh*16 + (lane&3)*2;
                float2 h0 = *(const float2*)(hrow);
                float2 h1 = *(const float2*)(hrow + 8);
                float hv[2][2] = {{h0.x, h0.y}, {h1.x, h1.y}};
                #pragma unroll
                for (int nt = 0; nt < 2; ++nt) {
                    #pragma unroll
                    for (int cp = 0; cp < 2; ++cp) {
                        float m = acc[mt*2+nt][rg*2+cp] * hv[nt][cp];
                        pa[nt][cp][0] += m;
                        pa[nt][cp][1] = fmaf(m, uv.x, pa[nt][cp][1]);
                        pa[nt][cp][2] = fmaf(m, uv.y, pa[nt][cp][2]);
                        pa[nt][cp][3] = fmaf(m, uv.z, pa[nt][cp][3]);
                    }
                }
            }
        }
        #pragma unroll
        for (int nt = 0; nt < 2; ++nt)
            #pragma unroll
            for (int cp = 0; cp < 2; ++cp)
                #pragma unroll
                for (int q = 0; q < 4; ++q) {
                    float v = pa[nt][cp][q];
                    v += __shfl_xor_sync(0xffffffffu, v, 4);
                    v += __shfl_xor_sync(0xffffffffu, v, 8);
                    v += __shfl_xor_sync(0xffffffffu, v, 16);
                    pa[nt][cp][q] = v;
                }
        if (lane < 4) {
            const int nidx = b*Nn + j;
            #pragma unroll
            for (int nt = 0; nt < 2; ++nt)
                #pragma unroll
                for (int cp = 0; cp < 2; ++cp) {
                    int c = widh*16 + nt*8 + lane*2 + cp;
                    g_a0[nidx*Hh + c]         = pa[nt][cp][0] * s63;
                    g_a1[(nidx*3+0)*Hh + c]   = pa[nt][cp][1] * s63;
                    g_a1[(nidx*3+1)*Hh + c]   = pa[nt][cp][2] * s63;
                    g_a1[(nidx*3+2)*Hh + c]   = pa[nt][cp][3] * s63;
                }
        }
        __syncthreads();   // guard Sh overwrite next iteration
    }
}

// ---------------- K3: h += a0 @ Wupd ; v += einsum(a1, Wmix) -------------
#define UP0 20
__global__ __launch_bounds__(512, 1)
void upd_kernel(const float* __restrict__ Wupd,
                const float* __restrict__ Wmix) {
    extern __shared__ float usm[];
    float* Wu_s = usm;                       // 16384
    float* Wm_s = Wu_s + Hh*Hh;              // 16384
    float* a0T  = Wm_s + Hh*Hh;              // 128*20
    float* a1T  = a0T + Hh*UP0;              // 384*20

    const int n0  = blockIdx.x * 16;
    const int tid = threadIdx.x;
    for (int idx = tid; idx < Hh*Hh; idx += 512) { Wu_s[idx] = Wupd[idx]; Wm_s[idx] = Wmix[idx]; }
    for (int idx = tid; idx < 16*Hh; idx += 512) {
        int n = idx >> 7, g = idx & 127;
        a0T[g*UP0 + n] = g_a0[n0*Hh + idx];
    }
    for (int idx = tid; idx < 16*3*Hh; idx += 512) {
        int n = idx / 384, r = idx - n*384;
        int d = r >> 7, g = r & 127;
        a1T[(g*3 + d)*UP0 + n] = g_a1[(size_t)n0*3*Hh + idx];
    }
    __syncthreads();

    const int c  = tid & 127;
    const int qt = tid >> 7;
    float ah[4], avx[4], avy[4], avz[4];
    #pragma unroll
    for (int m = 0; m < 4; ++m) { ah[m]=0.f; avx[m]=0.f; avy[m]=0.f; avz[m]=0.f; }

    #pragma unroll 2
    for (int g = 0; g < Hh; ++g) {
        float wu = Wu_s[g*Hh + c];
        float wm = Wm_s[g*Hh + c];
        float4 a0v = *(const float4*)(a0T + g*UP0 + qt*4);
        float4 a1x = *(const float4*)(a1T + (g*3 + 0)*UP0 + qt*4);
        float4 a1y = *(const float4*)(a1T + (g*3 + 1)*UP0 + qt*4);
        float4 a1z = *(const float4*)(a1T + (g*3 + 2)*UP0 + qt*4);
        const float* a0p = (const float*)&a0v;
        const float* axp = (const float*)&a1x;
        const float* ayp = (const float*)&a1y;
        const float* azp = (const float*)&a1z;
        #pragma unroll
        for (int m = 0; m < 4; ++m) {
            ah[m]  = fmaf(a0p[m], wu, ah[m]);
            avx[m] = fmaf(axp[m], wm, avx[m]);
            avy[m] = fmaf(ayp[m], wm, avy[m]);
            avz[m] = fmaf(azp[m], wm, avz[m]);
        }
    }
    #pragma unroll
    for (int m = 0; m < 4; ++m) {
        int n = n0 + qt*4 + m;
        g_h[n*Hh + c] += ah[m];
        g_v[(n*3 + 0)*Hh + c] += avx[m];
        g_v[(n*3 + 1)*Hh + c] += avy[m];
        g_v[(n*3 + 2)*Hh + c] += avz[m];
    }
}

// ---------------- K4: gated readout --------------------------------------
__global__ void readout_kernel(const float* __restrict__ Wg1,
                               const float* __restrict__ Wg2,
                               const float* __restrict__ fsp,
                               float* __restrict__ out) {
    __shared__ float h_s[8*128];
    __shared__ float t_s[8*128];
    __shared__ float wred[4][3];
    const int n0 = blockIdx.x * 8;
    const int c  = threadIdx.x;
    for (int idx = c; idx < 8*128; idx += 128) h_s[idx] = g_h[n0*128 + idx];
    __syncthreads();

    float t[8];
    #pragma unroll
    for (int m = 0; m < 8; ++m) t[m] = 0.f;
    for (int g = 0; g < 128; ++g) {
        float w = Wg1[g*128 + c];
        #pragma unroll
        for (int m = 0; m < 8; ++m) t[m] += h_s[m*128 + g] * w;
    }
    #pragma unroll
    for (int m = 0; m < 8; ++m) t_s[m*128 + c] = t[m] / (1.0f + __expf(-t[m]));
    __syncthreads();

    float gg[8];
    #pragma unroll
    for (int m = 0; m < 8; ++m) gg[m] = 0.f;
    for (int k = 0; k < 128; ++k) {
        float w = Wg2[k*128 + c];
        #pragma unroll
        for (int m = 0; m < 8; ++m) gg[m] += t_s[m*128 + k] * w;
    }

    const float fs = fsp[0];
    const int lane = c & 31, warp = c >> 5;
    for (int m = 0; m < 8; ++m) {
        const int n = n0 + m;
        float p0 = g_v[(n*3 + 0)*128 + c] * gg[m];
        float p1 = g_v[(n*3 + 1)*128 + c] * gg[m];
        float p2 = g_v[(n*3 + 2)*128 + c] * gg[m];
        #pragma unroll
        for (int off = 16; off; off >>= 1) {
            p0 += __shfl_down_sync(0xffffffffu, p0, off);
            p1 += __shfl_down_sync(0xffffffffu, p1, off);
            p2 += __shfl_down_sync(0xffffffffu, p2, off);
        }
        if (lane == 0) { wred[warp][0]=p0; wred[warp][1]=p1; wred[warp][2]=p2; }
        __syncthreads();
        if (c == 0) {
            out[n*3 + 0] = (wred[0][0]+wred[1][0]+wred[2][0]+wred[3][0])*fs;
            out[n*3 + 1] = (wred[0][1]+wred[1][1]+wred[2][1]+wred[3][1])*fs;
            out[n*3 + 2] = (wred[0][2]+wred[1][2]+wred[2][2]+wred[3][2])*fs;
        }
        __syncthreads();
    }
}

// ---------------- launch ---------------------------------------------------
extern "C" void kernel_launch(void* const* d_in, const int* in_sizes, int n_in,
                              void* d_out, int out_size) {
    const float* positions = (const float*)d_in[0];
    const int*   nodef     = (const int*)  d_in[1];
    const float* gf        = (const float*)d_in[2];
    const float* emb       = (const float*)d_in[3];
    const float* Wt        = (const float*)d_in[4];
    const float* Wr1       = (const float*)d_in[5];
    const float* Wr2       = (const float*)d_in[6];
    const float* Wupd      = (const float*)d_in[7];
    const float* Wmix      = (const float*)d_in[8];
    const float* Wg1       = (const float*)d_in[9];
    const float* Wg2       = (const float*)d_in[10];
    const float* fs        = (const float*)d_in[11];
    float*       out       = (float*)d_out;

    const int msg_smem = (Hh*PITCH + 2*Nn*PITCH + Nn*Hh + 8*Nn*NBb + 8*Nn*4 + Nn*3 + NBb*Hh) * 4;
    const int upd_smem = (Hh*Hh*2 + Hh*UP0 + Hh*3*UP0) * 4;
    cudaFuncSetAttribute(msg_kernel, cudaFuncAttributeMaxDynamicSharedMemorySize, msg_smem);
    cudaFuncSetAttribute(upd_kernel, cudaFuncAttributeMaxDynamicSharedMemorySize, upd_smem);

    probe_kernel<<<1, 1>>>(nodef);
    init_kernel<<<Bb*Nn, Hh>>>(nodef, gf, emb, Wt);
    wr2t_kernel<<<Ll, 256>>>(Wr2);

    for (int l = 0; l < Ll; ++l) {
        dim3 grid(8, Bb);
        msg_kernel<<<grid, 512, msg_smem>>>(positions, Wr1 + l*NBb*Hh, l);
        upd_kernel<<<Bb*Nn/16, 512, upd_smem>>>(Wupd + l*Hh*Hh, Wmix + l*Hh*Hh);
    }
    readout_kernel<<<Bb*Nn/8, Hh>>>(Wg1, Wg2, fs, out);
}

// round 6
// speedup vs baseline: 3.2411x; 1.1501x over previous
#include <cuda_runtime.h>
#include <math.h>
#include <stdint.h>

// Problem constants
#define Bb   64
#define Nn   64
#define Hh   128
#define NBb  8
#define Tt   32
#define Ll   2

// ---------------- device scratch (no allocations allowed) ----------------
__device__ float    g_h   [Bb*Nn*Hh];      // node scalar features
__device__ float    g_v   [Bb*Nn*3*Hh];    // vector features SoA [n][d][c]
__device__ float    g_a0  [Bb*Nn*Hh];      // scalar aggregates
__device__ float    g_a1  [Bb*Nn*3*Hh];    // vector aggregates SoA [n][d][c]
__device__ uint32_t g_Wr2T[Ll*Hh*Hh];      // Wr2 transposed [c][k], tf32-rounded
__device__ int      g_z64;                 // species dtype flag

// ---------------- helpers -------------------------------------------------
__device__ __forceinline__ uint32_t f2tf32(float x) {
    uint32_t r;
    asm("cvt.rn.tf32.f32 %0, %1;" : "=r"(r) : "f"(x));
    return r;
}
// within-k8 permutation: fragment lanes read (t, t+4) as adjacent pair
__device__ __forceinline__ int kperm7(int k7) {
    return ((k7 & 3) << 1) | (k7 >> 2);
}
__device__ __forceinline__ void mma_tf32(float* c,
                                         uint32_t a0, uint32_t a1, uint32_t a2, uint32_t a3,
                                         uint32_t b0, uint32_t b1) {
    asm volatile(
        "mma.sync.aligned.m16n8k8.row.col.f32.tf32.tf32.f32 "
        "{%0,%1,%2,%3},{%4,%5,%6,%7},{%8,%9},{%0,%1,%2,%3};"
        : "+f"(c[0]), "+f"(c[1]), "+f"(c[2]), "+f"(c[3])
        : "r"(a0), "r"(a1), "r"(a2), "r"(a3), "r"(b0), "r"(b1));
}
__device__ __forceinline__ float silu_f(float x) {
    return x / (1.0f + __expf(-x));
}
__device__ __forceinline__ void bar_half(int half) {
    asm volatile("bar.sync %0, %1;" :: "r"(1 + half), "r"(256) : "memory");
}

// ---------------- K0: probe node_features dtype -------------------------
__global__ void probe_kernel(const int* __restrict__ z) {
    int nz = 0;
    for (int t = 0; t < 64; ++t) nz |= z[2*t + 1];
    g_z64 = (nz == 0) ? 1 : 0;
}

// ---------------- K1: h = emb[z] + t @ Wt ; v = 0 -----------------------
__global__ void init_kernel(const int* __restrict__ z,
                            const float* __restrict__ gf,
                            const float* __restrict__ emb,
                            const float* __restrict__ Wt) {
    const int node = blockIdx.x;
    const int c    = threadIdx.x;
    const int b    = node >> 6;
    const int zi   = g_z64 ? z[2*node] : z[node];
    float acc = emb[zi*Hh + c];
    const float* g = gf + b*Tt;
    #pragma unroll
    for (int t = 0; t < Tt; ++t) acc += g[t] * Wt[t*Hh + c];
    g_h[node*Hh + c] = acc;
    g_v[node*3*Hh + 0*Hh + c] = 0.f;
    g_v[node*3*Hh + 1*Hh + c] = 0.f;
    g_v[node*3*Hh + 2*Hh + c] = 0.f;
}

// ---------------- K1b: Wr2T = round_tf32(Wr2^T) --------------------------
__global__ void wr2t_kernel(const float* __restrict__ Wr2) {
    const int l = blockIdx.x;
    for (int idx = threadIdx.x; idx < Hh*Hh; idx += 256) {
        int c = idx >> 7, k = idx & 127;
        g_Wr2T[l*Hh*Hh + idx] = f2tf32(Wr2[l*Hh*Hh + k*Hh + c]);
    }
}

// ---------------- smem word offsets for msg kernel ------------------------
#define OFF_W2T  0          // 16384 words: [kb16][c128][8]
#define OFF_S    16384      // 4 x 8192:   [half2][buf2][kb16][mt4][r16][8] (swizzled)
#define OFF_RBF  49152      // 4096:       [jl8][i64][8 perm-k] tf32
#define OFF_U4F  53248      // 2048:       [jl8][i64] float4
#define OFF_POS  55296      // 192
#define OFF_W1U  55488      // 1024:       Wr1 tf32 [8][128]
#define MSG_WORDS 56512     // 226048 bytes

// ---------------- K2: message pass (fully tensorized, pipelined) ----------
// CTA = (8 receivers jg, batch b), 512 threads = 2 independent halves x 8 warps.
__global__ __launch_bounds__(512, 1)
void msg_kernel(const float* __restrict__ pos,
                const float* __restrict__ Wr1,
                int layer) {
    extern __shared__ float smf[];
    uint32_t* W2Tf  = (uint32_t*)smf + OFF_W2T;
    uint32_t* Sall  = (uint32_t*)smf + OFF_S;
    uint32_t* rbf   = (uint32_t*)smf + OFF_RBF;
    float*    u4f   = smf + OFF_U4F;
    float*    pos_s = smf + OFF_POS;
    uint32_t* w1u   = (uint32_t*)smf + OFF_W1U;

    const int b    = blockIdx.y;
    const int jg   = blockIdx.x;            // 0..7
    const int tid  = threadIdx.x;
    const int lane = tid & 31;
    const int wid  = tid >> 5;
    const int half = wid >> 3;              // 0/1
    const int widh = wid & 7;               // warp within half

    // ---- stage W2T fragments, pos, Wr1(tf32) ----
    for (int idx = tid; idx < Hh*Hh; idx += 512) {
        int c = idx >> 7, k = idx & 127;
        W2Tf[((k >> 3)*128 + c)*8 + kperm7(k & 7)] = g_Wr2T[layer*Hh*Hh + idx];
    }
    for (int idx = tid; idx < Nn*3;   idx += 512) pos_s[idx] = pos[b*Nn*3 + idx];
    for (int idx = tid; idx < NBb*Hh; idx += 512) w1u[idx]   = f2tf32(Wr1[idx]);

    // ---- register-cache h (fixed across receivers): 8 rows x 2 float2 ----
    float2 hreg[4][2][2];
    {
        const float* hb = g_h + (size_t)b*Nn*Hh;
        #pragma unroll
        for (int mt = 0; mt < 4; ++mt)
            #pragma unroll
            for (int rg = 0; rg < 2; ++rg) {
                int i = mt*16 + (lane>>2) + rg*8;
                #pragma unroll
                for (int nt = 0; nt < 2; ++nt) {
                    int c = widh*16 + nt*8 + (lane&3)*2;
                    hreg[mt][rg][nt] = *(const float2*)(hb + i*Hh + c);
                }
            }
    }
    __syncthreads();

    const float PI5 = 0.62831853071795864769f;   // pi/5
    const float s63 = 1.0f / 63.0f;

    // ---- geometry + bessel for all 8 receivers (512 = 8j x 64i) ----
    {
        const int jl = tid >> 6;             // 0..7
        const int i  = tid & 63;
        const int j  = jg*8 + jl;
        float dx = pos_s[j*3+0] - pos_s[i*3+0];
        float dy = pos_s[j*3+1] - pos_s[i*3+1];
        float dz = pos_s[j*3+2] - pos_s[i*3+2];
        float r2 = dx*dx + dy*dy + dz*dz + 1e-12f;
        float r  = sqrtf(r2);
        float inv = 1.0f / r;
        ((float4*)u4f)[jl*Nn + i] = make_float4(dx*inv, dy*inv, dz*inv, 0.f);
        float fc = 0.0f;
        if (r < 5.0f && i != j) fc = 0.5f * (cosf(PI5 * r) + 1.0f);
        float sc  = inv * fc;
        float arg = PI5 * r;
        float rv[8];
        #pragma unroll
        for (int q = 0; q < NBb; ++q) rv[q] = sinf((float)(q+1) * arg) * sc;
        // perm order: positions [k0,k4,k1,k5 | k2,k6,k3,k7]
        uint4 lo = make_uint4(f2tf32(rv[0]), f2tf32(rv[4]), f2tf32(rv[1]), f2tf32(rv[5]));
        uint4 hi = make_uint4(f2tf32(rv[2]), f2tf32(rv[6]), f2tf32(rv[3]), f2tf32(rv[7]));
        ((uint4*)rbf)[(jl*Nn + i)*2 + 0] = lo;
        ((uint4*)rbf)[(jl*Nn + i)*2 + 1] = hi;
    }
    __syncthreads();

    // ---- hoist Wr1 B-frags (per warp: cols widh*16 .. +16) ----
    uint32_t wb00, wb01, wb10, wb11;
    {
        int colA = widh*16 + (lane>>2);
        int colB = colA + 8;
        int kq   = lane & 3;
        wb00 = w1u[kq*Hh + colA];  wb01 = w1u[(kq+4)*Hh + colA];
        wb10 = w1u[kq*Hh + colB];  wb11 = w1u[(kq+4)*Hh + colB];
    }

    const int xr = (lane & 16) >> 3;                 // row-bit2 swizzle (0 or 2)
    const int p0 = kperm7((lane&3)*2)     ^ xr;      // store positions
    const int p1 = kperm7((lane&3)*2 + 1) ^ xr;
    const int kwoff = ((lane&3)*2) ^ xr;             // load word offset
    uint32_t* Shalf = Sall + half*2*8192;

    // ---- S-MMA for a receiver jl2 into buffer Sb ----
    auto s_mma = [&](int jl2, uint32_t* Sb) {
        float sacc[8][4];
        #pragma unroll
        for (int q = 0; q < 8; ++q) { sacc[q][0]=0.f; sacc[q][1]=0.f; sacc[q][2]=0.f; sacc[q][3]=0.f; }
        const uint32_t* rbj = rbf + jl2*Nn*8;
        #pragma unroll
        for (int mt = 0; mt < 4; ++mt) {
            int r0 = mt*16 + (lane>>2);
            uint2 A0 = *(const uint2*)(rbj + r0*8     + (lane&3)*2);
            uint2 A1 = *(const uint2*)(rbj + (r0+8)*8 + (lane&3)*2);
            mma_tf32(sacc[mt*2+0], A0.x, A1.x, A0.y, A1.y, wb00, wb01);
            mma_tf32(sacc[mt*2+1], A0.x, A1.x, A0.y, A1.y, wb10, wb11);
        }
        #pragma unroll
        for (int mt = 0; mt < 4; ++mt) {
            #pragma unroll
            for (int nt = 0; nt < 2; ++nt) {
                const int kb = widh*2 + nt;
                const int base = ((kb*4 + mt)*16 + (lane>>2))*8;
                const float* a = sacc[mt*2+nt];
                Sb[base + p0]      = f2tf32(silu_f(a[0]));
                Sb[base + p1]      = f2tf32(silu_f(a[1]));
                Sb[base + 64 + p0] = f2tf32(silu_f(a[2]));
                Sb[base + 64 + p1] = f2tf32(silu_f(a[3]));
            }
        }
    };

    // prologue: fill buffer 0
    s_mma(half, Shalf);          // jj=0 -> jl2 = 0*2 + half
    bar_half(half);

    for (int jj = 0; jj < 4; ++jj) {
        const int jl2 = jj*2 + half;
        const int j   = jg*8 + jl2;
        const uint32_t* Sb = Shalf + (jj & 1)*8192;

        // ---- main warp GEMM ----
        float acc[8][4];
        #pragma unroll
        for (int q = 0; q < 8; ++q) { acc[q][0]=0.f; acc[q][1]=0.f; acc[q][2]=0.f; acc[q][3]=0.f; }

        const uint32_t* Ap = Sb + (lane>>2)*8 + kwoff;
        const uint32_t* Bp = W2Tf + (widh*16 + (lane>>2))*8 + (lane&3)*2;

        #pragma unroll 4
        for (int kb = 0; kb < 16; ++kb) {
            uint2 Bv0 = *(const uint2*)(Bp + kb*1024);
            uint2 Bv1 = *(const uint2*)(Bp + kb*1024 + 64);
            #pragma unroll
            for (int mt = 0; mt < 4; ++mt) {
                uint2 A0 = *(const uint2*)(Ap + (kb*4 + mt)*128);
                uint2 A1 = *(const uint2*)(Ap + (kb*4 + mt)*128 + 64);
                mma_tf32(acc[mt*2+0], A0.x, A1.x, A0.y, A1.y, Bv0.x, Bv0.y);
                mma_tf32(acc[mt*2+1], A0.x, A1.x, A0.y, A1.y, Bv1.x, Bv1.y);
            }
        }

        // ---- fused epilogue: multiply by h, u; reduce over rows ----
        float pa[2][2][4];
        #pragma unroll
        for (int nt = 0; nt < 2; ++nt)
            #pragma unroll
            for (int cp = 0; cp < 2; ++cp) {
                pa[nt][cp][0]=0.f; pa[nt][cp][1]=0.f; pa[nt][cp][2]=0.f; pa[nt][cp][3]=0.f;
            }
        const float4* uj = (const float4*)u4f + jl2*Nn;
        #pragma unroll
        for (int mt = 0; mt < 4; ++mt) {
            #pragma unroll
            for (int rg = 0; rg < 2; ++rg) {
                int i = mt*16 + (lane>>2) + rg*8;
                float4 uv = uj[i];
                #pragma unroll
                for (int nt = 0; nt < 2; ++nt) {
                    float hv0 = (nt ? hreg[mt][rg][1].x : hreg[mt][rg][0].x);
                    float hv1 = (nt ? hreg[mt][rg][1].y : hreg[mt][rg][0].y);
                    #pragma unroll
                    for (int cp = 0; cp < 2; ++cp) {
                        float m = acc[mt*2+nt][rg*2+cp] * (cp ? hv1 : hv0);
                        pa[nt][cp][0] += m;
                        pa[nt][cp][1] = fmaf(m, uv.x, pa[nt][cp][1]);
                        pa[nt][cp][2] = fmaf(m, uv.y, pa[nt][cp][2]);
                        pa[nt][cp][3] = fmaf(m, uv.z, pa[nt][cp][3]);
                    }
                }
            }
        }
        #pragma unroll
        for (int nt = 0; nt < 2; ++nt)
            #pragma unroll
            for (int cp = 0; cp < 2; ++cp)
                #pragma unroll
                for (int q = 0; q < 4; ++q) {
                    float v = pa[nt][cp][q];
                    v += __shfl_xor_sync(0xffffffffu, v, 4);
                    v += __shfl_xor_sync(0xffffffffu, v, 8);
                    v += __shfl_xor_sync(0xffffffffu, v, 16);
                    pa[nt][cp][q] = v;
                }
        if (lane < 4) {
            const int nidx = b*Nn + j;
            #pragma unroll
            for (int nt = 0; nt < 2; ++nt)
                #pragma unroll
                for (int cp = 0; cp < 2; ++cp) {
                    int c = widh*16 + nt*8 + lane*2 + cp;
                    g_a0[nidx*Hh + c]         = pa[nt][cp][0] * s63;
                    g_a1[(nidx*3+0)*Hh + c]   = pa[nt][cp][1] * s63;
                    g_a1[(nidx*3+1)*Hh + c]   = pa[nt][cp][2] * s63;
                    g_a1[(nidx*3+2)*Hh + c]   = pa[nt][cp][3] * s63;
                }
        }

        // ---- prepare next receiver's S into the other buffer ----
        if (jj < 3) s_mma(jl2 + 2, Shalf + ((jj + 1) & 1)*8192);
        bar_half(half);
    }
}

// ---------------- K3: h += a0 @ Wupd ; v += einsum(a1, Wmix) -------------
#define UP0 20
__global__ __launch_bounds__(512, 1)
void upd_kernel(const float* __restrict__ Wupd,
                const float* __restrict__ Wmix) {
    extern __shared__ float usm[];
    float* Wu_s = usm;                       // 16384
    float* Wm_s = Wu_s + Hh*Hh;              // 16384
    float* a0T  = Wm_s + Hh*Hh;              // 128*20
    float* a1T  = a0T + Hh*UP0;              // 384*20

    const int n0  = blockIdx.x * 16;
    const int tid = threadIdx.x;
    for (int idx = tid; idx < Hh*Hh; idx += 512) { Wu_s[idx] = Wupd[idx]; Wm_s[idx] = Wmix[idx]; }
    for (int idx = tid; idx < 16*Hh; idx += 512) {
        int n = idx >> 7, g = idx & 127;
        a0T[g*UP0 + n] = g_a0[n0*Hh + idx];
    }
    for (int idx = tid; idx < 16*3*Hh; idx += 512) {
        int n = idx / 384, r = idx - n*384;
        int d = r >> 7, g = r & 127;
        a1T[(g*3 + d)*UP0 + n] = g_a1[(size_t)n0*3*Hh + idx];
    }
    __syncthreads();

    const int c  = tid & 127;
    const int qt = tid >> 7;
    float ah[4], avx[4], avy[4], avz[4];
    #pragma unroll
    for (int m = 0; m < 4; ++m) { ah[m]=0.f; avx[m]=0.f; avy[m]=0.f; avz[m]=0.f; }

    #pragma unroll 2
    for (int g = 0; g < Hh; ++g) {
        float wu = Wu_s[g*Hh + c];
        float wm = Wm_s[g*Hh + c];
        float4 a0v = *(const float4*)(a0T + g*UP0 + qt*4);
        float4 a1x = *(const float4*)(a1T + (g*3 + 0)*UP0 + qt*4);
        float4 a1y = *(const float4*)(a1T + (g*3 + 1)*UP0 + qt*4);
        float4 a1z = *(const float4*)(a1T + (g*3 + 2)*UP0 + qt*4);
        const float* a0p = (const float*)&a0v;
        const float* axp = (const float*)&a1x;
        const float* ayp = (const float*)&a1y;
        const float* azp = (const float*)&a1z;
        #pragma unroll
        for (int m = 0; m < 4; ++m) {
            ah[m]  = fmaf(a0p[m], wu, ah[m]);
            avx[m] = fmaf(axp[m], wm, avx[m]);
            avy[m] = fmaf(ayp[m], wm, avy[m]);
            avz[m] = fmaf(azp[m], wm, avz[m]);
        }
    }
    #pragma unroll
    for (int m = 0; m < 4; ++m) {
        int n = n0 + qt*4 + m;
        g_h[n*Hh + c] += ah[m];
        g_v[(n*3 + 0)*Hh + c] += avx[m];
        g_v[(n*3 + 1)*Hh + c] += avy[m];
        g_v[(n*3 + 2)*Hh + c] += avz[m];
    }
}

// ---------------- K4: gated readout --------------------------------------
__global__ void readout_kernel(const float* __restrict__ Wg1,
                               const float* __restrict__ Wg2,
                               const float* __restrict__ fsp,
                               float* __restrict__ out) {
    __shared__ float h_s[8*128];
    __shared__ float t_s[8*128];
    __shared__ float wred[4][3];
    const int n0 = blockIdx.x * 8;
    const int c  = threadIdx.x;
    for (int idx = c; idx < 8*128; idx += 128) h_s[idx] = g_h[n0*128 + idx];
    __syncthreads();

    float t[8];
    #pragma unroll
    for (int m = 0; m < 8; ++m) t[m] = 0.f;
    for (int g = 0; g < 128; ++g) {
        float w = Wg1[g*128 + c];
        #pragma unroll
        for (int m = 0; m < 8; ++m) t[m] += h_s[m*128 + g] * w;
    }
    #pragma unroll
    for (int m = 0; m < 8; ++m) t_s[m*128 + c] = t[m] / (1.0f + __expf(-t[m]));
    __syncthreads();

    float gg[8];
    #pragma unroll
    for (int m = 0; m < 8; ++m) gg[m] = 0.f;
    for (int k = 0; k < 128; ++k) {
        float w = Wg2[k*128 + c];
        #pragma unroll
        for (int m = 0; m < 8; ++m) gg[m] += t_s[m*128 + k] * w;
    }

    const float fs = fsp[0];
    const int lane = c & 31, warp = c >> 5;
    for (int m = 0; m < 8; ++m) {
        const int n = n0 + m;
        float p0 = g_v[(n*3 + 0)*128 + c] * gg[m];
        float p1 = g_v[(n*3 + 1)*128 + c] * gg[m];
        float p2 = g_v[(n*3 + 2)*128 + c] * gg[m];
        #pragma unroll
        for (int off = 16; off; off >>= 1) {
            p0 += __shfl_down_sync(0xffffffffu, p0, off);
            p1 += __shfl_down_sync(0xffffffffu, p1, off);
            p2 += __shfl_down_sync(0xffffffffu, p2, off);
        }
        if (lane == 0) { wred[warp][0]=p0; wred[warp][1]=p1; wred[warp][2]=p2; }
        __syncthreads();
        if (c == 0) {
            out[n*3 + 0] = (wred[0][0]+wred[1][0]+wred[2][0]+wred[3][0])*fs;
            out[n*3 + 1] = (wred[0][1]+wred[1][1]+wred[2][1]+wred[3][1])*fs;
            out[n*3 + 2] = (wred[0][2]+wred[1][2]+wred[2][2]+wred[3][2])*fs;
        }
        __syncthreads();
    }
}

// ---------------- launch ---------------------------------------------------
extern "C" void kernel_launch(void* const* d_in, const int* in_sizes, int n_in,
                              void* d_out, int out_size) {
    const float* positions = (const float*)d_in[0];
    const int*   nodef     = (const int*)  d_in[1];
    const float* gf        = (const float*)d_in[2];
    const float* emb       = (const float*)d_in[3];
    const float* Wt        = (const float*)d_in[4];
    const float* Wr1       = (const float*)d_in[5];
    const float* Wr2       = (const float*)d_in[6];
    const float* Wupd      = (const float*)d_in[7];
    const float* Wmix      = (const float*)d_in[8];
    const float* Wg1       = (const float*)d_in[9];
    const float* Wg2       = (const float*)d_in[10];
    const float* fs        = (const float*)d_in[11];
    float*       out       = (float*)d_out;

    const int msg_smem = MSG_WORDS * 4;
    const int upd_smem = (Hh*Hh*2 + Hh*UP0 + Hh*3*UP0) * 4;
    cudaFuncSetAttribute(msg_kernel, cudaFuncAttributeMaxDynamicSharedMemorySize, msg_smem);
    cudaFuncSetAttribute(upd_kernel, cudaFuncAttributeMaxDynamicSharedMemorySize, upd_smem);

    probe_kernel<<<1, 1>>>(nodef);
    init_kernel<<<Bb*Nn, Hh>>>(nodef, gf, emb, Wt);
    wr2t_kernel<<<Ll, 256>>>(Wr2);

    for (int l = 0; l < Ll; ++l) {
        dim3 grid(8, Bb);
        msg_kernel<<<grid, 512, msg_smem>>>(positions, Wr1 + l*NBb*Hh, l);
        upd_kernel<<<Bb*Nn/16, 512, upd_smem>>>(Wupd + l*Hh*Hh, Wmix + l*Hh*Hh);
    }
    readout_kernel<<<Bb*Nn/8, Hh>>>(Wg1, Wg2, fs, out);
}

// round 7
// speedup vs baseline: 3.7567x; 1.1591x over previous
#include <cuda_runtime.h>
#include <cuda_fp16.h>
#include <math.h>
#include <stdint.h>

// Problem constants
#define Bb   64
#define Nn   64
#define Hh   128
#define NBb  8
#define Tt   32
#define Ll   2

// ---------------- device scratch (no allocations allowed) ----------------
__device__ float    g_h   [Bb*Nn*Hh];      // node scalar features
__device__ float    g_v   [Bb*Nn*3*Hh];    // vector features SoA [n][d][c]
__device__ float    g_a0  [Bb*Nn*Hh];      // scalar aggregates
__device__ float    g_a1  [Bb*Nn*3*Hh];    // vector aggregates SoA [n][d][c]
__device__ uint32_t g_Wr2H[Ll*8192];       // Wr2^T fp16, B-fragment layout [kb8][c128][8w]
__device__ int      g_z64;                 // species dtype flag

// ---------------- helpers -------------------------------------------------
__device__ __forceinline__ uint32_t f2tf32(float x) {
    uint32_t r;
    asm("cvt.rn.tf32.f32 %0, %1;" : "=r"(r) : "f"(x));
    return r;
}
__device__ __forceinline__ void mma_tf32(float* c,
                                         uint32_t a0, uint32_t a1, uint32_t a2, uint32_t a3,
                                         uint32_t b0, uint32_t b1) {
    asm volatile(
        "mma.sync.aligned.m16n8k8.row.col.f32.tf32.tf32.f32 "
        "{%0,%1,%2,%3},{%4,%5,%6,%7},{%8,%9},{%0,%1,%2,%3};"
        : "+f"(c[0]), "+f"(c[1]), "+f"(c[2]), "+f"(c[3])
        : "r"(a0), "r"(a1), "r"(a2), "r"(a3), "r"(b0), "r"(b1));
}
__device__ __forceinline__ void mma_f16(float* c,
                                        uint32_t a0, uint32_t a1, uint32_t a2, uint32_t a3,
                                        uint32_t b0, uint32_t b1) {
    asm volatile(
        "mma.sync.aligned.m16n8k16.row.col.f32.f16.f16.f32 "
        "{%0,%1,%2,%3},{%4,%5,%6,%7},{%8,%9},{%0,%1,%2,%3};"
        : "+f"(c[0]), "+f"(c[1]), "+f"(c[2]), "+f"(c[3])
        : "r"(a0), "r"(a1), "r"(a2), "r"(a3), "r"(b0), "r"(b1));
}
__device__ __forceinline__ float silu_f(float x) {
    return x / (1.0f + __expf(-x));
}
__device__ __forceinline__ uint32_t pack_h2(float lo, float hi) {
    __half2 h = __floats2half2_rn(lo, hi);
    return *(uint32_t*)&h;
}
__device__ __forceinline__ void bar_half(int half) {
    asm volatile("bar.sync %0, %1;" :: "r"(1 + half), "r"(256) : "memory");
}

// ---------------- K0: probe node_features dtype -------------------------
__global__ void probe_kernel(const int* __restrict__ z) {
    int nz = 0;
    for (int t = 0; t < 64; ++t) nz |= z[2*t + 1];
    g_z64 = (nz == 0) ? 1 : 0;
}

// ---------------- K1: h = emb[z] + t @ Wt ; v = 0  (16 nodes/CTA) --------
__global__ __launch_bounds__(512, 1)
void init_kernel(const int* __restrict__ z,
                 const float* __restrict__ gf,
                 const float* __restrict__ emb,
                 const float* __restrict__ Wt) {
    const int n0 = blockIdx.x * 16;
    const int b  = n0 >> 6;
    const int c  = threadIdx.x & 127;
    const int qt = threadIdx.x >> 7;
    float tw = 0.f;
    const float* g = gf + b*Tt;
    #pragma unroll
    for (int t = 0; t < Tt; ++t) tw += g[t] * Wt[t*Hh + c];
    #pragma unroll
    for (int m = 0; m < 4; ++m) {
        const int n  = n0 + qt*4 + m;
        const int zi = g_z64 ? z[2*n] : z[n];
        g_h[n*Hh + c] = emb[zi*Hh + c] + tw;
        g_v[(n*3 + 0)*Hh + c] = 0.f;
        g_v[(n*3 + 1)*Hh + c] = 0.f;
        g_v[(n*3 + 2)*Hh + c] = 0.f;
    }
}

// ---------------- K1b: Wr2H = fp16(Wr2^T) in fragment layout --------------
// layout word index: (kb*128 + c)*8 + q*2 + hi  where k = kb*16 + q*2 + hi*8 (+cp)
__global__ void wr2h_kernel(const float* __restrict__ Wr2) {
    const int l = blockIdx.x;
    for (int idx = threadIdx.x; idx < 8192; idx += 256) {
        int c  = idx >> 6, kp = idx & 63;
        int k  = kp * 2;
        int kb = k >> 4;
        int kw = k & 15;
        int q  = (kw >> 1) & 3;
        int hi = kw >> 3;
        float v0 = Wr2[l*Hh*Hh + k*Hh + c];
        float v1 = Wr2[l*Hh*Hh + (k+1)*Hh + c];
        g_Wr2H[l*8192 + (kb*128 + c)*8 + q*2 + hi] = pack_h2(v0, v1);
    }
}

// ---------------- smem word offsets for msg kernel ------------------------
#define OFF_W2T  0          // 8192 words: fp16 B frags [kb8][c128][8w]
#define OFF_S    8192       // 4 x 4096:   fp16 A frags [half2][buf2][kb8][mt4][r16][8w]
#define OFF_RBF  24576      // 4096:       [jl8][i64][8 perm-k] tf32
#define OFF_U4F  28672      // 2048:       [jl8][i64] float4
#define OFF_POS  30720      // 192
#define OFF_W1U  30912      // 1024:       Wr1 tf32 [8][128]
#define MSG_WORDS 31936     // 127744 bytes

// ---------------- K2: message pass (fp16 tensor GEMM, pipelined) ----------
// CTA = (8 receivers jg, batch b), 512 threads = 2 independent halves x 8 warps.
__global__ __launch_bounds__(512, 1)
void msg_kernel(const float* __restrict__ pos,
                const float* __restrict__ Wr1,
                int layer) {
    extern __shared__ float smf[];
    uint32_t* W2Tf  = (uint32_t*)smf + OFF_W2T;
    uint32_t* Sall  = (uint32_t*)smf + OFF_S;
    uint32_t* rbf   = (uint32_t*)smf + OFF_RBF;
    float*    u4f   = smf + OFF_U4F;
    float*    pos_s = smf + OFF_POS;
    uint32_t* w1u   = (uint32_t*)smf + OFF_W1U;

    const int b    = blockIdx.y;
    const int jg   = blockIdx.x;            // 0..7
    const int tid  = threadIdx.x;
    const int lane = tid & 31;
    const int wid  = tid >> 5;
    const int half = wid >> 3;              // 0/1
    const int widh = wid & 7;               // warp within half

    // ---- stage W2T fp16 fragments (direct copy), pos, Wr1(tf32) ----
    for (int idx = tid; idx < 8192; idx += 512) W2Tf[idx] = g_Wr2H[layer*8192 + idx];
    for (int idx = tid; idx < Nn*3;   idx += 512) pos_s[idx] = pos[b*Nn*3 + idx];
    for (int idx = tid; idx < NBb*Hh; idx += 512) w1u[idx]   = f2tf32(Wr1[idx]);

    // ---- register-cache h (fixed across receivers): 8 rows x 2 float2 ----
    float2 hreg[4][2][2];
    {
        const float* hb = g_h + (size_t)b*Nn*Hh;
        #pragma unroll
        for (int mt = 0; mt < 4; ++mt)
            #pragma unroll
            for (int rg = 0; rg < 2; ++rg) {
                int i = mt*16 + (lane>>2) + rg*8;
                #pragma unroll
                for (int nt = 0; nt < 2; ++nt) {
                    int c = widh*16 + nt*8 + (lane&3)*2;
                    hreg[mt][rg][nt] = *(const float2*)(hb + i*Hh + c);
                }
            }
    }
    __syncthreads();

    const float PI5 = 0.62831853071795864769f;   // pi/5
    const float s63 = 1.0f / 63.0f;

    // ---- geometry + bessel for all 8 receivers (512 = 8j x 64i) ----
    {
        const int jl = tid >> 6;             // 0..7
        const int i  = tid & 63;
        const int j  = jg*8 + jl;
        float dx = pos_s[j*3+0] - pos_s[i*3+0];
        float dy = pos_s[j*3+1] - pos_s[i*3+1];
        float dz = pos_s[j*3+2] - pos_s[i*3+2];
        float r2 = dx*dx + dy*dy + dz*dz + 1e-12f;
        float r  = sqrtf(r2);
        float inv = 1.0f / r;
        ((float4*)u4f)[jl*Nn + i] = make_float4(dx*inv, dy*inv, dz*inv, 0.f);
        float fc = 0.0f;
        if (r < 5.0f && i != j) fc = 0.5f * (cosf(PI5 * r) + 1.0f);
        float sc  = inv * fc;
        float arg = PI5 * r;
        float rv[8];
        #pragma unroll
        for (int q = 0; q < NBb; ++q) rv[q] = sinf((float)(q+1) * arg) * sc;
        // perm order for tf32 k8 A-frag: [k0,k4,k1,k5 | k2,k6,k3,k7]
        uint4 lo = make_uint4(f2tf32(rv[0]), f2tf32(rv[4]), f2tf32(rv[1]), f2tf32(rv[5]));
        uint4 hi = make_uint4(f2tf32(rv[2]), f2tf32(rv[6]), f2tf32(rv[3]), f2tf32(rv[7]));
        ((uint4*)rbf)[(jl*Nn + i)*2 + 0] = lo;
        ((uint4*)rbf)[(jl*Nn + i)*2 + 1] = hi;
    }
    __syncthreads();

    // ---- hoist Wr1 B-frags (per warp: cols widh*16 .. +16) ----
    uint32_t wb00, wb01, wb10, wb11;
    {
        int colA = widh*16 + (lane>>2);
        int colB = colA + 8;
        int kq   = lane & 3;
        wb00 = w1u[kq*Hh + colA];  wb01 = w1u[(kq+4)*Hh + colA];
        wb10 = w1u[kq*Hh + colB];  wb11 = w1u[(kq+4)*Hh + colB];
    }

    uint32_t* Shalf = Sall + half*2*4096;
    const int r4 = lane >> 2;                // 0..7
    const int q4 = lane & 3;                 // 0..3

    // ---- S-MMA for receiver jl2 into fp16 buffer Sb ----
    auto s_mma = [&](int jl2, uint32_t* Sb) {
        float sacc[8][4];
        #pragma unroll
        for (int q = 0; q < 8; ++q) { sacc[q][0]=0.f; sacc[q][1]=0.f; sacc[q][2]=0.f; sacc[q][3]=0.f; }
        const uint32_t* rbj = rbf + jl2*Nn*8;
        #pragma unroll
        for (int mt = 0; mt < 4; ++mt) {
            int r0 = mt*16 + r4;
            uint2 A0 = *(const uint2*)(rbj + r0*8     + q4*2);
            uint2 A1 = *(const uint2*)(rbj + (r0+8)*8 + q4*2);
            mma_tf32(sacc[mt*2+0], A0.x, A1.x, A0.y, A1.y, wb00, wb01);
            mma_tf32(sacc[mt*2+1], A0.x, A1.x, A0.y, A1.y, wb10, wb11);
        }
        // silu + fp16 pack + store in A-fragment layout (kb = widh)
        #pragma unroll
        for (int mt = 0; mt < 4; ++mt) {
            const int base = widh*512 + mt*128 + r4*8;
            #pragma unroll
            for (int nt = 0; nt < 2; ++nt) {
                const float* a = sacc[mt*2+nt];
                Sb[base + q4*2 + nt]      = pack_h2(silu_f(a[0]), silu_f(a[1]));
                Sb[base + 64 + q4*2 + nt] = pack_h2(silu_f(a[2]), silu_f(a[3]));
            }
        }
    };

    // prologue: fill buffer 0
    s_mma(half, Shalf);
    bar_half(half);

    for (int jj = 0; jj < 4; ++jj) {
        const int jl2 = jj*2 + half;
        const int j   = jg*8 + jl2;
        const uint32_t* Sb = Shalf + (jj & 1)*4096;

        // ---- main warp GEMM (fp16 m16n8k16, 8 kb-blocks) ----
        float acc[8][4];
        #pragma unroll
        for (int q = 0; q < 8; ++q) { acc[q][0]=0.f; acc[q][1]=0.f; acc[q][2]=0.f; acc[q][3]=0.f; }

        const uint32_t* Ap = Sb + r4*8 + q4*2;
        const uint32_t* Bp = W2Tf + (widh*16 + r4)*8 + q4*2;

        #pragma unroll
        for (int kb = 0; kb < 8; ++kb) {
            uint2 Bv0 = *(const uint2*)(Bp + kb*1024);
            uint2 Bv1 = *(const uint2*)(Bp + kb*1024 + 64);
            #pragma unroll
            for (int mt = 0; mt < 4; ++mt) {
                uint2 A0 = *(const uint2*)(Ap + kb*512 + mt*128);
                uint2 A1 = *(const uint2*)(Ap + kb*512 + mt*128 + 64);
                mma_f16(acc[mt*2+0], A0.x, A1.x, A0.y, A1.y, Bv0.x, Bv0.y);
                mma_f16(acc[mt*2+1], A0.x, A1.x, A0.y, A1.y, Bv1.x, Bv1.y);
            }
        }

        // ---- fused epilogue: multiply by h, u; reduce over rows ----
        float pa[2][2][4];
        #pragma unroll
        for (int nt = 0; nt < 2; ++nt)
            #pragma unroll
            for (int cp = 0; cp < 2; ++cp) {
                pa[nt][cp][0]=0.f; pa[nt][cp][1]=0.f; pa[nt][cp][2]=0.f; pa[nt][cp][3]=0.f;
            }
        const float4* uj = (const float4*)u4f + jl2*Nn;
        #pragma unroll
        for (int mt = 0; mt < 4; ++mt) {
            #pragma unroll
            for (int rg = 0; rg < 2; ++rg) {
                int i = mt*16 + r4 + rg*8;
                float4 uv = uj[i];
                #pragma unroll
                for (int nt = 0; nt < 2; ++nt) {
                    float hv0 = (nt ? hreg[mt][rg][1].x : hreg[mt][rg][0].x);
                    float hv1 = (nt ? hreg[mt][rg][1].y : hreg[mt][rg][0].y);
                    #pragma unroll
                    for (int cp = 0; cp < 2; ++cp) {
                        float m = acc[mt*2+nt][rg*2+cp] * (cp ? hv1 : hv0);
                        pa[nt][cp][0] += m;
                        pa[nt][cp][1] = fmaf(m, uv.x, pa[nt][cp][1]);
                        pa[nt][cp][2] = fmaf(m, uv.y, pa[nt][cp][2]);
                        pa[nt][cp][3] = fmaf(m, uv.z, pa[nt][cp][3]);
                    }
                }
            }
        }
        #pragma unroll
        for (int nt = 0; nt < 2; ++nt)
            #pragma unroll
            for (int cp = 0; cp < 2; ++cp)
                #pragma unroll
                for (int q = 0; q < 4; ++q) {
                    float v = pa[nt][cp][q];
                    v += __shfl_xor_sync(0xffffffffu, v, 4);
                    v += __shfl_xor_sync(0xffffffffu, v, 8);
                    v += __shfl_xor_sync(0xffffffffu, v, 16);
                    pa[nt][cp][q] = v;
                }
        if (lane < 4) {
            const int nidx = b*Nn + j;
            #pragma unroll
            for (int nt = 0; nt < 2; ++nt)
                #pragma unroll
                for (int cp = 0; cp < 2; ++cp) {
                    int c = widh*16 + nt*8 + lane*2 + cp;
                    g_a0[nidx*Hh + c]         = pa[nt][cp][0] * s63;
                    g_a1[(nidx*3+0)*Hh + c]   = pa[nt][cp][1] * s63;
                    g_a1[(nidx*3+1)*Hh + c]   = pa[nt][cp][2] * s63;
                    g_a1[(nidx*3+2)*Hh + c]   = pa[nt][cp][3] * s63;
                }
        }

        // ---- prepare next receiver's S into the other buffer ----
        if (jj < 3) s_mma(jl2 + 2, Shalf + ((jj + 1) & 1)*4096);
        bar_half(half);
    }
}

// ---------------- K3: h += a0 @ Wupd ; v += einsum(a1, Wmix) -------------
#define UP0 20
__global__ __launch_bounds__(512, 1)
void upd_kernel(const float* __restrict__ Wupd,
                const float* __restrict__ Wmix) {
    extern __shared__ float usm[];
    float* Wu_s = usm;                       // 16384
    float* Wm_s = Wu_s + Hh*Hh;              // 16384
    float* a0T  = Wm_s + Hh*Hh;              // 128*20
    float* a1T  = a0T + Hh*UP0;              // 384*20

    const int n0  = blockIdx.x * 16;
    const int tid = threadIdx.x;
    for (int idx = tid; idx < Hh*Hh; idx += 512) { Wu_s[idx] = Wupd[idx]; Wm_s[idx] = Wmix[idx]; }
    for (int idx = tid; idx < 16*Hh; idx += 512) {
        int n = idx >> 7, g = idx & 127;
        a0T[g*UP0 + n] = g_a0[n0*Hh + idx];
    }
    for (int idx = tid; idx < 16*3*Hh; idx += 512) {
        int n = idx / 384, r = idx - n*384;
        int d = r >> 7, g = r & 127;
        a1T[(g*3 + d)*UP0 + n] = g_a1[(size_t)n0*3*Hh + idx];
    }
    __syncthreads();

    const int c  = tid & 127;
    const int qt = tid >> 7;
    float ah[4], avx[4], avy[4], avz[4];
    #pragma unroll
    for (int m = 0; m < 4; ++m) { ah[m]=0.f; avx[m]=0.f; avy[m]=0.f; avz[m]=0.f; }

    #pragma unroll 2
    for (int g = 0; g < Hh; ++g) {
        float wu = Wu_s[g*Hh + c];
        float wm = Wm_s[g*Hh + c];
        float4 a0v = *(const float4*)(a0T + g*UP0 + qt*4);
        float4 a1x = *(const float4*)(a1T + (g*3 + 0)*UP0 + qt*4);
        float4 a1y = *(const float4*)(a1T + (g*3 + 1)*UP0 + qt*4);
        float4 a1z = *(const float4*)(a1T + (g*3 + 2)*UP0 + qt*4);
        const float* a0p = (const float*)&a0v;
        const float* axp = (const float*)&a1x;
        const float* ayp = (const float*)&a1y;
        const float* azp = (const float*)&a1z;
        #pragma unroll
        for (int m = 0; m < 4; ++m) {
            ah[m]  = fmaf(a0p[m], wu, ah[m]);
            avx[m] = fmaf(axp[m], wm, avx[m]);
            avy[m] = fmaf(ayp[m], wm, avy[m]);
            avz[m] = fmaf(azp[m], wm, avz[m]);
        }
    }
    #pragma unroll
    for (int m = 0; m < 4; ++m) {
        int n = n0 + qt*4 + m;
        g_h[n*Hh + c] += ah[m];
        g_v[(n*3 + 0)*Hh + c] += avx[m];
        g_v[(n*3 + 1)*Hh + c] += avy[m];
        g_v[(n*3 + 2)*Hh + c] += avz[m];
    }
}

// ---------------- K4: gated readout (16 nodes/CTA, staged weights) --------
#define RP 20
__global__ __launch_bounds__(512, 1)
void readout_kernel(const float* __restrict__ Wg1,
                    const float* __restrict__ Wg2,
                    const float* __restrict__ fsp,
                    float* __restrict__ out) {
    extern __shared__ float rsm[];
    float* W1_s = rsm;                       // 16384
    float* W2_s = W1_s + Hh*Hh;              // 16384
    float* hT   = W2_s + Hh*Hh;              // 128*RP
    float* tT   = hT + Hh*RP;                // 128*RP
    __shared__ float red[16][12];

    const int n0  = blockIdx.x * 16;
    const int tid = threadIdx.x;
    for (int idx = tid; idx < Hh*Hh; idx += 512) { W1_s[idx] = Wg1[idx]; W2_s[idx] = Wg2[idx]; }
    for (int idx = tid; idx < 16*Hh; idx += 512) {
        int n = idx >> 7, g = idx & 127;
        hT[g*RP + n] = g_h[n0*Hh + idx];
    }
    __syncthreads();

    const int c  = tid & 127;
    const int qt = tid >> 7;

    // t = h @ Wg1
    float t[4] = {0.f, 0.f, 0.f, 0.f};
    #pragma unroll 2
    for (int g = 0; g < Hh; ++g) {
        float w = W1_s[g*Hh + c];
        float4 hv = *(const float4*)(hT + g*RP + qt*4);
        t[0] = fmaf(hv.x, w, t[0]);
        t[1] = fmaf(hv.y, w, t[1]);
        t[2] = fmaf(hv.z, w, t[2]);
        t[3] = fmaf(hv.w, w, t[3]);
    }
    #pragma unroll
    for (int m = 0; m < 4; ++m) tT[c*RP + qt*4 + m] = silu_f(t[m]);
    __syncthreads();

    // g = silu(t) @ Wg2
    float gg[4] = {0.f, 0.f, 0.f, 0.f};
    #pragma unroll 2
    for (int k = 0; k < Hh; ++k) {
        float w = W2_s[k*Hh + c];
        float4 tv = *(const float4*)(tT + k*RP + qt*4);
        gg[0] = fmaf(tv.x, w, gg[0]);
        gg[1] = fmaf(tv.y, w, gg[1]);
        gg[2] = fmaf(tv.z, w, gg[2]);
        gg[3] = fmaf(tv.w, w, gg[3]);
    }

    // gate contraction: out[n][d] = sum_c v[n][d][c] * gg[n][c]
    float p[4][3];
    #pragma unroll
    for (int m = 0; m < 4; ++m) {
        int n = n0 + qt*4 + m;
        p[m][0] = g_v[(n*3 + 0)*Hh + c] * gg[m];
        p[m][1] = g_v[(n*3 + 1)*Hh + c] * gg[m];
        p[m][2] = g_v[(n*3 + 2)*Hh + c] * gg[m];
    }
    #pragma unroll
    for (int m = 0; m < 4; ++m)
        #pragma unroll
        for (int d = 0; d < 3; ++d) {
            float v = p[m][d];
            #pragma unroll
            for (int off = 16; off; off >>= 1) v += __shfl_xor_sync(0xffffffffu, v, off);
            p[m][d] = v;
        }
    const int lane = tid & 31, warp = tid >> 5;
    if (lane == 0) {
        #pragma unroll
        for (int m = 0; m < 4; ++m)
            #pragma unroll
            for (int d = 0; d < 3; ++d) red[warp][m*3 + d] = p[m][d];
    }
    __syncthreads();
    if (tid < 48) {
        const int qtg = tid / 12, rem = tid % 12;
        float s = red[qtg*4 + 0][rem] + red[qtg*4 + 1][rem]
                + red[qtg*4 + 2][rem] + red[qtg*4 + 3][rem];
        out[(n0 + qtg*4 + rem/3)*3 + (rem % 3)] = s * fsp[0];
    }
}

// ---------------- launch ---------------------------------------------------
extern "C" void kernel_launch(void* const* d_in, const int* in_sizes, int n_in,
                              void* d_out, int out_size) {
    const float* positions = (const float*)d_in[0];
    const int*   nodef     = (const int*)  d_in[1];
    const float* gf        = (const float*)d_in[2];
    const float* emb       = (const float*)d_in[3];
    const float* Wt        = (const float*)d_in[4];
    const float* Wr1       = (const float*)d_in[5];
    const float* Wr2       = (const float*)d_in[6];
    const float* Wupd      = (const float*)d_in[7];
    const float* Wmix      = (const float*)d_in[8];
    const float* Wg1       = (const float*)d_in[9];
    const float* Wg2       = (const float*)d_in[10];
    const float* fs        = (const float*)d_in[11];
    float*       out       = (float*)d_out;

    const int msg_smem = MSG_WORDS * 4;
    const int upd_smem = (Hh*Hh*2 + Hh*UP0 + Hh*3*UP0) * 4;
    const int rdo_smem = (Hh*Hh*2 + Hh*RP*2) * 4;
    cudaFuncSetAttribute(msg_kernel,     cudaFuncAttributeMaxDynamicSharedMemorySize, msg_smem);
    cudaFuncSetAttribute(upd_kernel,     cudaFuncAttributeMaxDynamicSharedMemorySize, upd_smem);
    cudaFuncSetAttribute(readout_kernel, cudaFuncAttributeMaxDynamicSharedMemorySize, rdo_smem);

    probe_kernel<<<1, 1>>>(nodef);
    init_kernel<<<Bb*Nn/16, 512>>>(nodef, gf, emb, Wt);
    wr2h_kernel<<<Ll, 256>>>(Wr2);

    for (int l = 0; l < Ll; ++l) {
        dim3 grid(8, Bb);
        msg_kernel<<<grid, 512, msg_smem>>>(positions, Wr1 + l*NBb*Hh, l);
        upd_kernel<<<Bb*Nn/16, 512, upd_smem>>>(Wupd + l*Hh*Hh, Wmix + l*Hh*Hh);
    }
    readout_kernel<<<Bb*Nn/16, 512, rdo_smem>>>(Wg1, Wg2, fs, out);
}

// round 8
// speedup vs baseline: 3.8623x; 1.0281x over previous
#include <cuda_runtime.h>
#include <cuda_fp16.h>
#include <math.h>
#include <stdint.h>

// Problem constants
#define Bb   64
#define Nn   64
#define Hh   128
#define NBb  8
#define Tt   32
#define Ll   2

// ---------------- device scratch (no allocations allowed) ----------------
__device__ float    g_h   [Bb*Nn*Hh];      // node scalar features
__device__ float    g_v   [Bb*Nn*3*Hh];    // vector features SoA [n][d][c]
__device__ float    g_a0  [Bb*Nn*Hh];      // scalar aggregates
__device__ float    g_a1  [Bb*Nn*3*Hh];    // vector aggregates SoA [n][d][c]
__device__ uint32_t g_Wr2H[Ll*8192];       // Wr2^T fp16, B-fragment layout [kb8][c128][8w]
__device__ int      g_z64;                 // species dtype flag

// ---------------- helpers -------------------------------------------------
__device__ __forceinline__ uint32_t f2tf32(float x) {
    uint32_t r;
    asm("cvt.rn.tf32.f32 %0, %1;" : "=r"(r) : "f"(x));
    return r;
}
__device__ __forceinline__ void mma_tf32(float* c,
                                         uint32_t a0, uint32_t a1, uint32_t a2, uint32_t a3,
                                         uint32_t b0, uint32_t b1) {
    asm volatile(
        "mma.sync.aligned.m16n8k8.row.col.f32.tf32.tf32.f32 "
        "{%0,%1,%2,%3},{%4,%5,%6,%7},{%8,%9},{%0,%1,%2,%3};"
        : "+f"(c[0]), "+f"(c[1]), "+f"(c[2]), "+f"(c[3])
        : "r"(a0), "r"(a1), "r"(a2), "r"(a3), "r"(b0), "r"(b1));
}
__device__ __forceinline__ void mma_f16(float* c,
                                        uint32_t a0, uint32_t a1, uint32_t a2, uint32_t a3,
                                        uint32_t b0, uint32_t b1) {
    asm volatile(
        "mma.sync.aligned.m16n8k16.row.col.f32.f16.f16.f32 "
        "{%0,%1,%2,%3},{%4,%5,%6,%7},{%8,%9},{%0,%1,%2,%3};"
        : "+f"(c[0]), "+f"(c[1]), "+f"(c[2]), "+f"(c[3])
        : "r"(a0), "r"(a1), "r"(a2), "r"(a3), "r"(b0), "r"(b1));
}
__device__ __forceinline__ float silu_f(float x) {
    return x / (1.0f + __expf(-x));
}
__device__ __forceinline__ uint32_t pack_h2(float lo, float hi) {
    __half2 h = __floats2half2_rn(lo, hi);
    return *(uint32_t*)&h;
}

// ---------------- K0: probe node_features dtype -------------------------
__global__ void probe_kernel(const int* __restrict__ z) {
    int nz = 0;
    for (int t = 0; t < 64; ++t) nz |= z[2*t + 1];
    g_z64 = (nz == 0) ? 1 : 0;
}

// ---------------- K1: h = emb[z] + t @ Wt ; v = 0  (16 nodes/CTA) --------
__global__ __launch_bounds__(512, 1)
void init_kernel(const int* __restrict__ z,
                 const float* __restrict__ gf,
                 const float* __restrict__ emb,
                 const float* __restrict__ Wt) {
    const int n0 = blockIdx.x * 16;
    const int b  = n0 >> 6;
    const int c  = threadIdx.x & 127;
    const int qt = threadIdx.x >> 7;
    float tw = 0.f;
    const float* g = gf + b*Tt;
    #pragma unroll
    for (int t = 0; t < Tt; ++t) tw += g[t] * Wt[t*Hh + c];
    #pragma unroll
    for (int m = 0; m < 4; ++m) {
        const int n  = n0 + qt*4 + m;
        const int zi = g_z64 ? z[2*n] : z[n];
        g_h[n*Hh + c] = emb[zi*Hh + c] + tw;
        g_v[(n*3 + 0)*Hh + c] = 0.f;
        g_v[(n*3 + 1)*Hh + c] = 0.f;
        g_v[(n*3 + 2)*Hh + c] = 0.f;
    }
}

// ---------------- K1b: Wr2H = fp16(Wr2^T) in fragment layout --------------
__global__ void wr2h_kernel(const float* __restrict__ Wr2) {
    const int l = blockIdx.x;
    for (int idx = threadIdx.x; idx < 8192; idx += 256) {
        int c  = idx >> 6, kp = idx & 63;
        int k  = kp * 2;
        int kb = k >> 4;
        int kw = k & 15;
        int q  = (kw >> 1) & 3;
        int hi = kw >> 3;
        float v0 = Wr2[l*Hh*Hh + k*Hh + c];
        float v1 = Wr2[l*Hh*Hh + (k+1)*Hh + c];
        g_Wr2H[l*8192 + (kb*128 + c)*8 + q*2 + hi] = pack_h2(v0, v1);
    }
}

// ---------------- smem word offsets for msg kernel ------------------------
#define OFF_W2T  0          // 8192 words: fp16 B frags [kb8][c128][8w]
#define OFF_S    8192       // 2 x 4096:   fp16 A frags [buf2][kb8][mt4][r16][8w]
#define OFF_RBF  16384      // 2048:       [jl4][i64][8 perm-k] tf32
#define OFF_U4F  18432      // 1024:       [jl4][i64] float4
#define OFF_POS  19456      // 192
#define OFF_W1U  19648      // 1024:       Wr1 tf32 [8][128]
#define MSG_WORDS 20672     // 82688 bytes

// ---------------- K2: message pass (fp16 tensor GEMM, 2 CTAs/SM) ----------
// CTA = (4 receivers jg, batch b), 256 threads = 8 warps.
__global__ __launch_bounds__(256, 2)
void msg_kernel(const float* __restrict__ pos,
                const float* __restrict__ Wr1,
                int layer) {
    extern __shared__ float smf[];
    uint32_t* W2Tf  = (uint32_t*)smf + OFF_W2T;
    uint32_t* Sall  = (uint32_t*)smf + OFF_S;
    uint32_t* rbf   = (uint32_t*)smf + OFF_RBF;
    float*    u4f   = smf + OFF_U4F;
    float*    pos_s = smf + OFF_POS;
    uint32_t* w1u   = (uint32_t*)smf + OFF_W1U;

    const int b    = blockIdx.y;
    const int jg   = blockIdx.x;            // 0..15
    const int tid  = threadIdx.x;
    const int lane = tid & 31;
    const int widh = tid >> 5;              // 0..7

    // ---- stage W2T fp16 fragments (direct copy), pos, Wr1(tf32) ----
    for (int idx = tid; idx < 8192; idx += 256) W2Tf[idx] = g_Wr2H[layer*8192 + idx];
    for (int idx = tid; idx < Nn*3;   idx += 256) pos_s[idx] = pos[b*Nn*3 + idx];
    for (int idx = tid; idx < NBb*Hh; idx += 256) w1u[idx]   = f2tf32(Wr1[idx]);

    // ---- register-cache h (fixed across receivers): 8 rows x 2 float2 ----
    float2 hreg[4][2][2];
    {
        const float* hb = g_h + (size_t)b*Nn*Hh;
        #pragma unroll
        for (int mt = 0; mt < 4; ++mt)
            #pragma unroll
            for (int rg = 0; rg < 2; ++rg) {
                int i = mt*16 + (lane>>2) + rg*8;
                #pragma unroll
                for (int nt = 0; nt < 2; ++nt) {
                    int c = widh*16 + nt*8 + (lane&3)*2;
                    hreg[mt][rg][nt] = *(const float2*)(hb + i*Hh + c);
                }
            }
    }
    __syncthreads();

    const float PI5 = 0.62831853071795864769f;   // pi/5
    const float s63 = 1.0f / 63.0f;

    // ---- geometry + bessel for all 4 receivers (256 = 4j x 64i) ----
    {
        const int jl = tid >> 6;             // 0..3
        const int i  = tid & 63;
        const int j  = jg*4 + jl;
        float dx = pos_s[j*3+0] - pos_s[i*3+0];
        float dy = pos_s[j*3+1] - pos_s[i*3+1];
        float dz = pos_s[j*3+2] - pos_s[i*3+2];
        float r2 = dx*dx + dy*dy + dz*dz + 1e-12f;
        float r  = sqrtf(r2);
        float inv = 1.0f / r;
        ((float4*)u4f)[jl*Nn + i] = make_float4(dx*inv, dy*inv, dz*inv, 0.f);
        float fc = 0.0f;
        if (r < 5.0f && i != j) fc = 0.5f * (cosf(PI5 * r) + 1.0f);
        float sc  = inv * fc;
        float arg = PI5 * r;
        float rv[8];
        #pragma unroll
        for (int q = 0; q < NBb; ++q) rv[q] = sinf((float)(q+1) * arg) * sc;
        // perm order for tf32 k8 A-frag: [k0,k4,k1,k5 | k2,k6,k3,k7]
        uint4 lo = make_uint4(f2tf32(rv[0]), f2tf32(rv[4]), f2tf32(rv[1]), f2tf32(rv[5]));
        uint4 hi = make_uint4(f2tf32(rv[2]), f2tf32(rv[6]), f2tf32(rv[3]), f2tf32(rv[7]));
        ((uint4*)rbf)[(jl*Nn + i)*2 + 0] = lo;
        ((uint4*)rbf)[(jl*Nn + i)*2 + 1] = hi;
    }
    __syncthreads();

    // ---- hoist Wr1 B-frags (per warp: cols widh*16 .. +16) ----
    uint32_t wb00, wb01, wb10, wb11;
    {
        int colA = widh*16 + (lane>>2);
        int colB = colA + 8;
        int kq   = lane & 3;
        wb00 = w1u[kq*Hh + colA];  wb01 = w1u[(kq+4)*Hh + colA];
        wb10 = w1u[kq*Hh + colB];  wb11 = w1u[(kq+4)*Hh + colB];
    }

    const int r4 = lane >> 2;                // 0..7
    const int q4 = lane & 3;                 // 0..3

    // ---- S-MMA for receiver jl2 into fp16 buffer Sb ----
    auto s_mma = [&](int jl2, uint32_t* Sb) {
        float sacc[8][4];
        #pragma unroll
        for (int q = 0; q < 8; ++q) { sacc[q][0]=0.f; sacc[q][1]=0.f; sacc[q][2]=0.f; sacc[q][3]=0.f; }
        const uint32_t* rbj = rbf + jl2*Nn*8;
        #pragma unroll
        for (int mt = 0; mt < 4; ++mt) {
            int r0 = mt*16 + r4;
            uint2 A0 = *(const uint2*)(rbj + r0*8     + q4*2);
            uint2 A1 = *(const uint2*)(rbj + (r0+8)*8 + q4*2);
            mma_tf32(sacc[mt*2+0], A0.x, A1.x, A0.y, A1.y, wb00, wb01);
            mma_tf32(sacc[mt*2+1], A0.x, A1.x, A0.y, A1.y, wb10, wb11);
        }
        // silu + fp16 pack + store in A-fragment layout (kb = widh)
        #pragma unroll
        for (int mt = 0; mt < 4; ++mt) {
            const int base = widh*512 + mt*128 + r4*8;
            #pragma unroll
            for (int nt = 0; nt < 2; ++nt) {
                const float* a = sacc[mt*2+nt];
                Sb[base + q4*2 + nt]      = pack_h2(silu_f(a[0]), silu_f(a[1]));
                Sb[base + 64 + q4*2 + nt] = pack_h2(silu_f(a[2]), silu_f(a[3]));
            }
        }
    };

    // prologue: fill buffer 0
    s_mma(0, Sall);
    __syncthreads();

    for (int jj = 0; jj < 4; ++jj) {
        const int j = jg*4 + jj;
        const uint32_t* Sb = Sall + (jj & 1)*4096;

        // ---- main warp GEMM (fp16 m16n8k16, 8 kb-blocks) ----
        float acc[8][4];
        #pragma unroll
        for (int q = 0; q < 8; ++q) { acc[q][0]=0.f; acc[q][1]=0.f; acc[q][2]=0.f; acc[q][3]=0.f; }

        const uint32_t* Ap = Sb + r4*8 + q4*2;
        const uint32_t* Bp = W2Tf + (widh*16 + r4)*8 + q4*2;

        #pragma unroll
        for (int kb = 0; kb < 8; ++kb) {
            uint2 Bv0 = *(const uint2*)(Bp + kb*1024);
            uint2 Bv1 = *(const uint2*)(Bp + kb*1024 + 64);
            #pragma unroll
            for (int mt = 0; mt < 4; ++mt) {
                uint2 A0 = *(const uint2*)(Ap + kb*512 + mt*128);
                uint2 A1 = *(const uint2*)(Ap + kb*512 + mt*128 + 64);
                mma_f16(acc[mt*2+0], A0.x, A1.x, A0.y, A1.y, Bv0.x, Bv0.y);
                mma_f16(acc[mt*2+1], A0.x, A1.x, A0.y, A1.y, Bv1.x, Bv1.y);
            }
        }

        // ---- fused epilogue: multiply by h, u; reduce over rows ----
        float pa[2][2][4];
        #pragma unroll
        for (int nt = 0; nt < 2; ++nt)
            #pragma unroll
            for (int cp = 0; cp < 2; ++cp) {
                pa[nt][cp][0]=0.f; pa[nt][cp][1]=0.f; pa[nt][cp][2]=0.f; pa[nt][cp][3]=0.f;
            }
        const float4* uj = (const float4*)u4f + jj*Nn;
        #pragma unroll
        for (int mt = 0; mt < 4; ++mt) {
            #pragma unroll
            for (int rg = 0; rg < 2; ++rg) {
                int i = mt*16 + r4 + rg*8;
                float4 uv = uj[i];
                #pragma unroll
                for (int nt = 0; nt < 2; ++nt) {
                    float hv0 = (nt ? hreg[mt][rg][1].x : hreg[mt][rg][0].x);
                    float hv1 = (nt ? hreg[mt][rg][1].y : hreg[mt][rg][0].y);
                    #pragma unroll
                    for (int cp = 0; cp < 2; ++cp) {
                        float m = acc[mt*2+nt][rg*2+cp] * (cp ? hv1 : hv0);
                        pa[nt][cp][0] += m;
                        pa[nt][cp][1] = fmaf(m, uv.x, pa[nt][cp][1]);
                        pa[nt][cp][2] = fmaf(m, uv.y, pa[nt][cp][2]);
                        pa[nt][cp][3] = fmaf(m, uv.z, pa[nt][cp][3]);
                    }
                }
            }
        }
        #pragma unroll
        for (int nt = 0; nt < 2; ++nt)
            #pragma unroll
            for (int cp = 0; cp < 2; ++cp)
                #pragma unroll
                for (int q = 0; q < 4; ++q) {
                    float v = pa[nt][cp][q];
                    v += __shfl_xor_sync(0xffffffffu, v, 4);
                    v += __shfl_xor_sync(0xffffffffu, v, 8);
                    v += __shfl_xor_sync(0xffffffffu, v, 16);
                    pa[nt][cp][q] = v;
                }
        if (lane < 4) {
            const int nidx = b*Nn + j;
            #pragma unroll
            for (int nt = 0; nt < 2; ++nt)
                #pragma unroll
                for (int cp = 0; cp < 2; ++cp) {
                    int c = widh*16 + nt*8 + lane*2 + cp;
                    g_a0[nidx*Hh + c]         = pa[nt][cp][0] * s63;
                    g_a1[(nidx*3+0)*Hh + c]   = pa[nt][cp][1] * s63;
                    g_a1[(nidx*3+1)*Hh + c]   = pa[nt][cp][2] * s63;
                    g_a1[(nidx*3+2)*Hh + c]   = pa[nt][cp][3] * s63;
                }
        }

        // ---- prepare next receiver's S into the other buffer ----
        if (jj < 3) s_mma(jj + 1, Sall + ((jj + 1) & 1)*4096);
        __syncthreads();
    }
}

// ---------------- K3: h += a0 @ Wupd ; v += einsum(a1, Wmix) -------------
// 256 threads, 8 nodes/CTA, (Wupd,Wmix) packed into one half2 -> 2 CTAs/SM.
#define UP0 12      // aT pitch (8 nodes + pad)
__global__ __launch_bounds__(256, 2)
void upd_kernel(const float* __restrict__ Wupd,
                const float* __restrict__ Wmix) {
    extern __shared__ float usm[];
    uint32_t* Wuv = (uint32_t*)usm;          // 16384 words: half2(wu, wm) [g][c]
    float* a0T  = usm + 16384;               // 128*12
    float* a1T  = a0T + Hh*UP0;              // 384*12

    const int n0  = blockIdx.x * 8;
    const int tid = threadIdx.x;
    for (int idx = tid; idx < Hh*Hh; idx += 256) Wuv[idx] = pack_h2(Wupd[idx], Wmix[idx]);
    for (int idx = tid; idx < 8*Hh; idx += 256) {
        int n = idx >> 7, g = idx & 127;
        a0T[g*UP0 + n] = g_a0[n0*Hh + idx];
    }
    for (int idx = tid; idx < 8*3*Hh; idx += 256) {
        int n = idx / 384, r = idx - n*384;
        int d = r >> 7, g = r & 127;
        a1T[(g*3 + d)*UP0 + n] = g_a1[(size_t)n0*3*Hh + idx];
    }
    __syncthreads();

    const int c  = tid & 127;
    const int qt = tid >> 7;                 // 0/1 -> nodes qt*4..qt*4+3
    float ah[4], avx[4], avy[4], avz[4];
    #pragma unroll
    for (int m = 0; m < 4; ++m) { ah[m]=0.f; avx[m]=0.f; avy[m]=0.f; avz[m]=0.f; }

    #pragma unroll 2
    for (int g = 0; g < Hh; ++g) {
        float2 w = __half22float2(*(const __half2*)&Wuv[g*Hh + c]);
        const float wu = w.x, wm = w.y;
        float4 a0v = *(const float4*)(a0T + g*UP0 + qt*4);
        float4 a1x = *(const float4*)(a1T + (g*3 + 0)*UP0 + qt*4);
        float4 a1y = *(const float4*)(a1T + (g*3 + 1)*UP0 + qt*4);
        float4 a1z = *(const float4*)(a1T + (g*3 + 2)*UP0 + qt*4);
        const float* a0p = (const float*)&a0v;
        const float* axp = (const float*)&a1x;
        const float* ayp = (const float*)&a1y;
        const float* azp = (const float*)&a1z;
        #pragma unroll
        for (int m = 0; m < 4; ++m) {
            ah[m]  = fmaf(a0p[m], wu, ah[m]);
            avx[m] = fmaf(axp[m], wm, avx[m]);
            avy[m] = fmaf(ayp[m], wm, avy[m]);
            avz[m] = fmaf(azp[m], wm, avz[m]);
        }
    }
    #pragma unroll
    for (int m = 0; m < 4; ++m) {
        int n = n0 + qt*4 + m;
        g_h[n*Hh + c] += ah[m];
        g_v[(n*3 + 0)*Hh + c] += avx[m];
        g_v[(n*3 + 1)*Hh + c] += avy[m];
        g_v[(n*3 + 2)*Hh + c] += avz[m];
    }
}

// ---------------- K4: gated readout (16 nodes/CTA, staged weights) --------
#define RP 20
__global__ __launch_bounds__(512, 1)
void readout_kernel(const float* __restrict__ Wg1,
                    const float* __restrict__ Wg2,
                    const float* __restrict__ fsp,
                    float* __restrict__ out) {
    extern __shared__ float rsm[];
    float* W1_s = rsm;                       // 16384
    float* W2_s = W1_s + Hh*Hh;              // 16384
    float* hT   = W2_s + Hh*Hh;              // 128*RP
    float* tT   = hT + Hh*RP;                // 128*RP
    __shared__ float red[16][12];

    const int n0  = blockIdx.x * 16;
    const int tid = threadIdx.x;
    for (int idx = tid; idx < Hh*Hh; idx += 512) { W1_s[idx] = Wg1[idx]; W2_s[idx] = Wg2[idx]; }
    for (int idx = tid; idx < 16*Hh; idx += 512) {
        int n = idx >> 7, g = idx & 127;
        hT[g*RP + n] = g_h[n0*Hh + idx];
    }
    __syncthreads();

    const int c  = tid & 127;
    const int qt = tid >> 7;

    // t = h @ Wg1
    float t[4] = {0.f, 0.f, 0.f, 0.f};
    #pragma unroll 2
    for (int g = 0; g < Hh; ++g) {
        float w = W1_s[g*Hh + c];
        float4 hv = *(const float4*)(hT + g*RP + qt*4);
        t[0] = fmaf(hv.x, w, t[0]);
        t[1] = fmaf(hv.y, w, t[1]);
        t[2] = fmaf(hv.z, w, t[2]);
        t[3] = fmaf(hv.w, w, t[3]);
    }
    #pragma unroll
    for (int m = 0; m < 4; ++m) tT[c*RP + qt*4 + m] = silu_f(t[m]);
    __syncthreads();

    // g = silu(t) @ Wg2
    float gg[4] = {0.f, 0.f, 0.f, 0.f};
    #pragma unroll 2
    for (int k = 0; k < Hh; ++k) {
        float w = W2_s[k*Hh + c];
        float4 tv = *(const float4*)(tT + k*RP + qt*4);
        gg[0] = fmaf(tv.x, w, gg[0]);
        gg[1] = fmaf(tv.y, w, gg[1]);
        gg[2] = fmaf(tv.z, w, gg[2]);
        gg[3] = fmaf(tv.w, w, gg[3]);
    }

    // gate contraction: out[n][d] = sum_c v[n][d][c] * gg[n][c]
    float p[4][3];
    #pragma unroll
    for (int m = 0; m < 4; ++m) {
        int n = n0 + qt*4 + m;
        p[m][0] = g_v[(n*3 + 0)*Hh + c] * gg[m];
        p[m][1] = g_v[(n*3 + 1)*Hh + c] * gg[m];
        p[m][2] = g_v[(n*3 + 2)*Hh + c] * gg[m];
    }
    #pragma unroll
    for (int m = 0; m < 4; ++m)
        #pragma unroll
        for (int d = 0; d < 3; ++d) {
            float v = p[m][d];
            #pragma unroll
            for (int off = 16; off; off >>= 1) v += __shfl_xor_sync(0xffffffffu, v, off);
            p[m][d] = v;
        }
    const int lane = tid & 31, warp = tid >> 5;
    if (lane == 0) {
        #pragma unroll
        for (int m = 0; m < 4; ++m)
            #pragma unroll
            for (int d = 0; d < 3; ++d) red[warp][m*3 + d] = p[m][d];
    }
    __syncthreads();
    if (tid < 48) {
        const int qtg = tid / 12, rem = tid % 12;
        float s = red[qtg*4 + 0][rem] + red[qtg*4 + 1][rem]
                + red[qtg*4 + 2][rem] + red[qtg*4 + 3][rem];
        out[(n0 + qtg*4 + rem/3)*3 + (rem % 3)] = s * fsp[0];
    }
}

// ---------------- launch ---------------------------------------------------
extern "C" void kernel_launch(void* const* d_in, const int* in_sizes, int n_in,
                              void* d_out, int out_size) {
    const float* positions = (const float*)d_in[0];
    const int*   nodef     = (const int*)  d_in[1];
    const float* gf        = (const float*)d_in[2];
    const float* emb       = (const float*)d_in[3];
    const float* Wt        = (const float*)d_in[4];
    const float* Wr1       = (const float*)d_in[5];
    const float* Wr2       = (const float*)d_in[6];
    const float* Wupd      = (const float*)d_in[7];
    const float* Wmix      = (const float*)d_in[8];
    const float* Wg1       = (const float*)d_in[9];
    const float* Wg2       = (const float*)d_in[10];
    const float* fs        = (const float*)d_in[11];
    float*       out       = (float*)d_out;

    const int msg_smem = MSG_WORDS * 4;
    const int upd_smem = (16384 + Hh*UP0 + Hh*3*UP0) * 4;
    const int rdo_smem = (Hh*Hh*2 + Hh*RP*2) * 4;
    cudaFuncSetAttribute(msg_kernel,     cudaFuncAttributeMaxDynamicSharedMemorySize, msg_smem);
    cudaFuncSetAttribute(upd_kernel,     cudaFuncAttributeMaxDynamicSharedMemorySize, upd_smem);
    cudaFuncSetAttribute(readout_kernel, cudaFuncAttributeMaxDynamicSharedMemorySize, rdo_smem);

    probe_kernel<<<1, 1>>>(nodef);
    init_kernel<<<Bb*Nn/16, 512>>>(nodef, gf, emb, Wt);
    wr2h_kernel<<<Ll, 256>>>(Wr2);

    for (int l = 0; l < Ll; ++l) {
        dim3 grid(16, Bb);
        msg_kernel<<<grid, 256, msg_smem>>>(positions, Wr1 + l*NBb*Hh, l);
        upd_kernel<<<Bb*Nn/8, 256, upd_smem>>>(Wupd + l*Hh*Hh, Wmix + l*Hh*Hh);
    }
    readout_kernel<<<Bb*Nn/16, 512, rdo_smem>>>(Wg1, Wg2, fs, out);
}

// round 9
// speedup vs baseline: 4.7958x; 1.2417x over previous
#include <cuda_runtime.h>
#include <cuda_fp16.h>
#include <math.h>
#include <stdint.h>

// Problem constants
#define Bb   64
#define Nn   64
#define Hh   128
#define NBb  8
#define Tt   32
#define Ll   2

// ---------------- device scratch (no allocations allowed) ----------------
__device__ float    g_h   [Bb*Nn*Hh];      // node scalar features
__device__ float    g_v   [Bb*Nn*3*Hh];    // vector features SoA [n][d][c]
__device__ float    g_a0  [Bb*Nn*Hh];      // scalar aggregates
__device__ float    g_a1  [Bb*Nn*3*Hh];    // vector aggregates SoA [n][d][c]
__device__ uint32_t g_Wr2H[Ll*8192];       // Wr2^T fp16, B-fragment layout [kb8][c128][8w]
__device__ int      g_z64;                 // species dtype flag

// ---------------- helpers -------------------------------------------------
__device__ __forceinline__ uint32_t f2tf32(float x) {
    uint32_t r;
    asm("cvt.rn.tf32.f32 %0, %1;" : "=r"(r) : "f"(x));
    return r;
}
__device__ __forceinline__ void mma_tf32(float* c,
                                         uint32_t a0, uint32_t a1, uint32_t a2, uint32_t a3,
                                         uint32_t b0, uint32_t b1) {
    asm volatile(
        "mma.sync.aligned.m16n8k8.row.col.f32.tf32.tf32.f32 "
        "{%0,%1,%2,%3},{%4,%5,%6,%7},{%8,%9},{%0,%1,%2,%3};"
        : "+f"(c[0]), "+f"(c[1]), "+f"(c[2]), "+f"(c[3])
        : "r"(a0), "r"(a1), "r"(a2), "r"(a3), "r"(b0), "r"(b1));
}
__device__ __forceinline__ void mma_f16(float* c,
                                        uint32_t a0, uint32_t a1, uint32_t a2, uint32_t a3,
                                        uint32_t b0, uint32_t b1) {
    asm volatile(
        "mma.sync.aligned.m16n8k16.row.col.f32.f16.f16.f32 "
        "{%0,%1,%2,%3},{%4,%5,%6,%7},{%8,%9},{%0,%1,%2,%3};"
        : "+f"(c[0]), "+f"(c[1]), "+f"(c[2]), "+f"(c[3])
        : "r"(a0), "r"(a1), "r"(a2), "r"(a3), "r"(b0), "r"(b1));
}
__device__ __forceinline__ float silu_f(float x) {
    return __fdividef(x, 1.0f + __expf(-x));
}
__device__ __forceinline__ uint32_t pack_h2(float lo, float hi) {
    __half2 h = __floats2half2_rn(lo, hi);
    return *(uint32_t*)&h;
}

// ---------------- K0: probe node_features dtype -------------------------
__global__ void probe_kernel(const int* __restrict__ z) {
    int nz = 0;
    for (int t = 0; t < 64; ++t) nz |= z[2*t + 1];
    g_z64 = (nz == 0) ? 1 : 0;
}

// ---------------- K1: h = emb[z] + t @ Wt ; v = 0  (16 nodes/CTA) --------
__global__ __launch_bounds__(512, 1)
void init_kernel(const int* __restrict__ z,
                 const float* __restrict__ gf,
                 const float* __restrict__ emb,
                 const float* __restrict__ Wt) {
    const int n0 = blockIdx.x * 16;
    const int b  = n0 >> 6;
    const int c  = threadIdx.x & 127;
    const int qt = threadIdx.x >> 7;
    float tw = 0.f;
    const float* g = gf + b*Tt;
    #pragma unroll
    for (int t = 0; t < Tt; ++t) tw += g[t] * Wt[t*Hh + c];
    #pragma unroll
    for (int m = 0; m < 4; ++m) {
        const int n  = n0 + qt*4 + m;
        const int zi = g_z64 ? z[2*n] : z[n];
        g_h[n*Hh + c] = emb[zi*Hh + c] + tw;
        g_v[(n*3 + 0)*Hh + c] = 0.f;
        g_v[(n*3 + 1)*Hh + c] = 0.f;
        g_v[(n*3 + 2)*Hh + c] = 0.f;
    }
}

// ---------------- K1b: Wr2H = fp16(Wr2^T) in fragment layout --------------
__global__ void wr2h_kernel(const float* __restrict__ Wr2) {
    const int l = blockIdx.x;
    for (int idx = threadIdx.x; idx < 8192; idx += 256) {
        int c  = idx >> 6, kp = idx & 63;
        int k  = kp * 2;
        int kb = k >> 4;
        int kw = k & 15;
        int q  = (kw >> 1) & 3;
        int hi = kw >> 3;
        float v0 = Wr2[l*Hh*Hh + k*Hh + c];
        float v1 = Wr2[l*Hh*Hh + (k+1)*Hh + c];
        g_Wr2H[l*8192 + (kb*128 + c)*8 + q*2 + hi] = pack_h2(v0, v1);
    }
}

// ---------------- smem word offsets for msg kernel ------------------------
#define OFF_W2T  0          // 8192 words: fp16 B frags [kb8][c128][8w]
#define OFF_S    8192       // 4096:  fp16 A frags single buffer [kb8][mt4][r16][8w]
#define OFF_RBF  12288      // 2048:  [jl4][i64][8 perm-k] tf32
#define OFF_U4F  14336      // 1024:  [jl4][i64] float4
#define OFF_POS  15360      // 192
#define OFF_W1U  15552      // 1024:  Wr1 tf32 [8][128]
#define MSG_WORDS 16576     // 66304 bytes -> 3 CTAs/SM

// ---------------- K2: message pass (fp16 tensor GEMM, 3 CTAs/SM) ----------
// CTA = (4 receivers jg, batch b), 256 threads = 8 warps.
__global__ __launch_bounds__(256, 3)
void msg_kernel(const float* __restrict__ pos,
                const float* __restrict__ Wr1,
                int layer) {
    extern __shared__ float smf[];
    uint32_t* W2Tf  = (uint32_t*)smf + OFF_W2T;
    uint32_t* Sall  = (uint32_t*)smf + OFF_S;
    uint32_t* rbf   = (uint32_t*)smf + OFF_RBF;
    float*    u4f   = smf + OFF_U4F;
    float*    pos_s = smf + OFF_POS;
    uint32_t* w1u   = (uint32_t*)smf + OFF_W1U;

    const int b    = blockIdx.y;
    const int jg   = blockIdx.x;            // 0..15
    const int tid  = threadIdx.x;
    const int lane = tid & 31;
    const int widh = tid >> 5;              // 0..7

    // ---- stage W2T fp16 fragments (direct copy), pos, Wr1(tf32) ----
    for (int idx = tid; idx < 8192; idx += 256) W2Tf[idx] = g_Wr2H[layer*8192 + idx];
    for (int idx = tid; idx < Nn*3;   idx += 256) pos_s[idx] = pos[b*Nn*3 + idx];
    for (int idx = tid; idx < NBb*Hh; idx += 256) w1u[idx]   = f2tf32(Wr1[idx]);

    // ---- register-cache h (fixed across receivers): 8 rows x 2 float2 ----
    float2 hreg[4][2][2];
    {
        const float* hb = g_h + (size_t)b*Nn*Hh;
        #pragma unroll
        for (int mt = 0; mt < 4; ++mt)
            #pragma unroll
            for (int rg = 0; rg < 2; ++rg) {
                int i = mt*16 + (lane>>2) + rg*8;
                #pragma unroll
                for (int nt = 0; nt < 2; ++nt) {
                    int c = widh*16 + nt*8 + (lane&3)*2;
                    hreg[mt][rg][nt] = *(const float2*)(hb + i*Hh + c);
                }
            }
    }
    __syncthreads();

    const float PI5 = 0.62831853071795864769f;   // pi/5
    const float s63 = 1.0f / 63.0f;

    // ---- geometry + bessel for all 4 receivers (256 = 4j x 64i) ----
    {
        const int jl = tid >> 6;             // 0..3
        const int i  = tid & 63;
        const int j  = jg*4 + jl;
        float dx = pos_s[j*3+0] - pos_s[i*3+0];
        float dy = pos_s[j*3+1] - pos_s[i*3+1];
        float dz = pos_s[j*3+2] - pos_s[i*3+2];
        float r2 = dx*dx + dy*dy + dz*dz + 1e-12f;
        float r  = sqrtf(r2);
        float inv = 1.0f / r;
        ((float4*)u4f)[jl*Nn + i] = make_float4(dx*inv, dy*inv, dz*inv, 0.f);
        float fc = 0.0f;
        if (r < 5.0f && i != j) fc = 0.5f * (cosf(PI5 * r) + 1.0f);
        float sc  = inv * fc;
        float arg = PI5 * r;
        float rv[8];
        #pragma unroll
        for (int q = 0; q < NBb; ++q) rv[q] = sinf((float)(q+1) * arg) * sc;
        // perm order for tf32 k8 A-frag: [k0,k4,k1,k5 | k2,k6,k3,k7]
        uint4 lo = make_uint4(f2tf32(rv[0]), f2tf32(rv[4]), f2tf32(rv[1]), f2tf32(rv[5]));
        uint4 hi = make_uint4(f2tf32(rv[2]), f2tf32(rv[6]), f2tf32(rv[3]), f2tf32(rv[7]));
        ((uint4*)rbf)[(jl*Nn + i)*2 + 0] = lo;
        ((uint4*)rbf)[(jl*Nn + i)*2 + 1] = hi;
    }
    __syncthreads();

    // ---- hoist Wr1 B-frags (per warp: cols widh*16 .. +16) ----
    uint32_t wb00, wb01, wb10, wb11;
    {
        int colA = widh*16 + (lane>>2);
        int colB = colA + 8;
        int kq   = lane & 3;
        wb00 = w1u[kq*Hh + colA];  wb01 = w1u[(kq+4)*Hh + colA];
        wb10 = w1u[kq*Hh + colB];  wb11 = w1u[(kq+4)*Hh + colB];
    }

    const int r4 = lane >> 2;                // 0..7
    const int q4 = lane & 3;                 // 0..3

    for (int jj = 0; jj < 4; ++jj) {
        const int j = jg*4 + jj;

        // ---- S = silu(rb @ Wr1) via tf32 MMA, per-mt (low reg pressure) ----
        {
            const uint32_t* rbj = rbf + jj*Nn*8;
            #pragma unroll
            for (int mt = 0; mt < 4; ++mt) {
                float s0[4] = {0.f, 0.f, 0.f, 0.f};
                float s1[4] = {0.f, 0.f, 0.f, 0.f};
                int r0 = mt*16 + r4;
                uint2 A0 = *(const uint2*)(rbj + r0*8     + q4*2);
                uint2 A1 = *(const uint2*)(rbj + (r0+8)*8 + q4*2);
                mma_tf32(s0, A0.x, A1.x, A0.y, A1.y, wb00, wb01);
                mma_tf32(s1, A0.x, A1.x, A0.y, A1.y, wb10, wb11);
                const int base = widh*512 + mt*128 + r4*8;
                Sall[base + q4*2 + 0]      = pack_h2(silu_f(s0[0]), silu_f(s0[1]));
                Sall[base + q4*2 + 1]      = pack_h2(silu_f(s1[0]), silu_f(s1[1]));
                Sall[base + 64 + q4*2 + 0] = pack_h2(silu_f(s0[2]), silu_f(s0[3]));
                Sall[base + 64 + q4*2 + 1] = pack_h2(silu_f(s1[2]), silu_f(s1[3]));
            }
        }
        __syncthreads();

        // ---- fused GEMM + epilogue, per-mt tiles (acc live = 8 regs) ----
        float pa[2][2][4];
        #pragma unroll
        for (int nt = 0; nt < 2; ++nt)
            #pragma unroll
            for (int cp = 0; cp < 2; ++cp) {
                pa[nt][cp][0]=0.f; pa[nt][cp][1]=0.f; pa[nt][cp][2]=0.f; pa[nt][cp][3]=0.f;
            }
        const float4* uj = (const float4*)u4f + jj*Nn;
        const uint32_t* Ap = Sall + r4*8 + q4*2;
        const uint32_t* Bp = W2Tf + (widh*16 + r4)*8 + q4*2;

        #pragma unroll
        for (int mt = 0; mt < 4; ++mt) {
            float acc0[4] = {0.f, 0.f, 0.f, 0.f};
            float acc1[4] = {0.f, 0.f, 0.f, 0.f};
            #pragma unroll
            for (int kb = 0; kb < 8; ++kb) {
                uint2 Bv0 = *(const uint2*)(Bp + kb*1024);
                uint2 Bv1 = *(const uint2*)(Bp + kb*1024 + 64);
                uint2 A0  = *(const uint2*)(Ap + kb*512 + mt*128);
                uint2 A1  = *(const uint2*)(Ap + kb*512 + mt*128 + 64);
                mma_f16(acc0, A0.x, A1.x, A0.y, A1.y, Bv0.x, Bv0.y);
                mma_f16(acc1, A0.x, A1.x, A0.y, A1.y, Bv1.x, Bv1.y);
            }
            #pragma unroll
            for (int rg = 0; rg < 2; ++rg) {
                int i = mt*16 + r4 + rg*8;
                float4 uv = uj[i];
                float2 h0 = hreg[mt][rg][0];
                float2 h1 = hreg[mt][rg][1];
                #pragma unroll
                for (int cp = 0; cp < 2; ++cp) {
                    float m0 = acc0[rg*2+cp] * (cp ? h0.y : h0.x);
                    pa[0][cp][0] += m0;
                    pa[0][cp][1] = fmaf(m0, uv.x, pa[0][cp][1]);
                    pa[0][cp][2] = fmaf(m0, uv.y, pa[0][cp][2]);
                    pa[0][cp][3] = fmaf(m0, uv.z, pa[0][cp][3]);
                    float m1 = acc1[rg*2+cp] * (cp ? h1.y : h1.x);
                    pa[1][cp][0] += m1;
                    pa[1][cp][1] = fmaf(m1, uv.x, pa[1][cp][1]);
                    pa[1][cp][2] = fmaf(m1, uv.y, pa[1][cp][2]);
                    pa[1][cp][3] = fmaf(m1, uv.z, pa[1][cp][3]);
                }
            }
        }

        #pragma unroll
        for (int nt = 0; nt < 2; ++nt)
            #pragma unroll
            for (int cp = 0; cp < 2; ++cp)
                #pragma unroll
                for (int q = 0; q < 4; ++q) {
                    float v = pa[nt][cp][q];
                    v += __shfl_xor_sync(0xffffffffu, v, 4);
                    v += __shfl_xor_sync(0xffffffffu, v, 8);
                    v += __shfl_xor_sync(0xffffffffu, v, 16);
                    pa[nt][cp][q] = v;
                }
        if (lane < 4) {
            const int nidx = b*Nn + j;
            #pragma unroll
            for (int nt = 0; nt < 2; ++nt)
                #pragma unroll
                for (int cp = 0; cp < 2; ++cp) {
                    int c = widh*16 + nt*8 + lane*2 + cp;
                    g_a0[nidx*Hh + c]         = pa[nt][cp][0] * s63;
                    g_a1[(nidx*3+0)*Hh + c]   = pa[nt][cp][1] * s63;
                    g_a1[(nidx*3+1)*Hh + c]   = pa[nt][cp][2] * s63;
                    g_a1[(nidx*3+2)*Hh + c]   = pa[nt][cp][3] * s63;
                }
        }
        __syncthreads();   // guard S overwrite next iteration
    }
}

// ---------------- K3: h += a0 @ Wupd ; v += einsum(a1, Wmix) -------------
// 256 threads, 8 nodes/CTA, (Wupd,Wmix) packed into one half2.
#define UP0 12      // aT pitch (8 nodes + pad)
__global__ __launch_bounds__(256, 2)
void upd_kernel(const float* __restrict__ Wupd,
                const float* __restrict__ Wmix) {
    extern __shared__ float usm[];
    uint32_t* Wuv = (uint32_t*)usm;          // 16384 words: half2(wu, wm) [g][c]
    float* a0T  = usm + 16384;               // 128*12
    float* a1T  = a0T + Hh*UP0;              // 384*12

    const int n0  = blockIdx.x * 8;
    const int tid = threadIdx.x;
    for (int idx = tid; idx < Hh*Hh; idx += 256) Wuv[idx] = pack_h2(Wupd[idx], Wmix[idx]);
    for (int idx = tid; idx < 8*Hh; idx += 256) {
        int n = idx >> 7, g = idx & 127;
        a0T[g*UP0 + n] = g_a0[n0*Hh + idx];
    }
    for (int idx = tid; idx < 8*3*Hh; idx += 256) {
        int n = idx / 384, r = idx - n*384;
        int d = r >> 7, g = r & 127;
        a1T[(g*3 + d)*UP0 + n] = g_a1[(size_t)n0*3*Hh + idx];
    }
    __syncthreads();

    const int c  = tid & 127;
    const int qt = tid >> 7;                 // 0/1 -> nodes qt*4..qt*4+3
    float ah[4], avx[4], avy[4], avz[4];
    #pragma unroll
    for (int m = 0; m < 4; ++m) { ah[m]=0.f; avx[m]=0.f; avy[m]=0.f; avz[m]=0.f; }

    #pragma unroll 2
    for (int g = 0; g < Hh; ++g) {
        float2 w = __half22float2(*(const __half2*)&Wuv[g*Hh + c]);
        const float wu = w.x, wm = w.y;
        float4 a0v = *(const float4*)(a0T + g*UP0 + qt*4);
        float4 a1x = *(const float4*)(a1T + (g*3 + 0)*UP0 + qt*4);
        float4 a1y = *(const float4*)(a1T + (g*3 + 1)*UP0 + qt*4);
        float4 a1z = *(const float4*)(a1T + (g*3 + 2)*UP0 + qt*4);
        const float* a0p = (const float*)&a0v;
        const float* axp = (const float*)&a1x;
        const float* ayp = (const float*)&a1y;
        const float* azp = (const float*)&a1z;
        #pragma unroll
        for (int m = 0; m < 4; ++m) {
            ah[m]  = fmaf(a0p[m], wu, ah[m]);
            avx[m] = fmaf(axp[m], wm, avx[m]);
            avy[m] = fmaf(ayp[m], wm, avy[m]);
            avz[m] = fmaf(azp[m], wm, avz[m]);
        }
    }
    #pragma unroll
    for (int m = 0; m < 4; ++m) {
        int n = n0 + qt*4 + m;
        g_h[n*Hh + c] += ah[m];
        g_v[(n*3 + 0)*Hh + c] += avx[m];
        g_v[(n*3 + 1)*Hh + c] += avy[m];
        g_v[(n*3 + 2)*Hh + c] += avz[m];
    }
}

// ---------------- K4: gated readout (16 nodes/CTA, staged weights) --------
#define RP 20
__global__ __launch_bounds__(512, 1)
void readout_kernel(const float* __restrict__ Wg1,
                    const float* __restrict__ Wg2,
                    const float* __restrict__ fsp,
                    float* __restrict__ out) {
    extern __shared__ float rsm[];
    float* W1_s = rsm;                       // 16384
    float* W2_s = W1_s + Hh*Hh;              // 16384
    float* hT   = W2_s + Hh*Hh;              // 128*RP
    float* tT   = hT + Hh*RP;                // 128*RP
    __shared__ float red[16][12];

    const int n0  = blockIdx.x * 16;
    const int tid = threadIdx.x;
    for (int idx = tid; idx < Hh*Hh; idx += 512) { W1_s[idx] = Wg1[idx]; W2_s[idx] = Wg2[idx]; }
    for (int idx = tid; idx < 16*Hh; idx += 512) {
        int n = idx >> 7, g = idx & 127;
        hT[g*RP + n] = g_h[n0*Hh + idx];
    }
    __syncthreads();

    const int c  = tid & 127;
    const int qt = tid >> 7;

    // t = h @ Wg1
    float t[4] = {0.f, 0.f, 0.f, 0.f};
    #pragma unroll 2
    for (int g = 0; g < Hh; ++g) {
        float w = W1_s[g*Hh + c];
        float4 hv = *(const float4*)(hT + g*RP + qt*4);
        t[0] = fmaf(hv.x, w, t[0]);
        t[1] = fmaf(hv.y, w, t[1]);
        t[2] = fmaf(hv.z, w, t[2]);
        t[3] = fmaf(hv.w, w, t[3]);
    }
    #pragma unroll
    for (int m = 0; m < 4; ++m) tT[c*RP + qt*4 + m] = silu_f(t[m]);
    __syncthreads();

    // g = silu(t) @ Wg2
    float gg[4] = {0.f, 0.f, 0.f, 0.f};
    #pragma unroll 2
    for (int k = 0; k < Hh; ++k) {
        float w = W2_s[k*Hh + c];
        float4 tv = *(const float4*)(tT + k*RP + qt*4);
        gg[0] = fmaf(tv.x, w, gg[0]);
        gg[1] = fmaf(tv.y, w, gg[1]);
        gg[2] = fmaf(tv.z, w, gg[2]);
        gg[3] = fmaf(tv.w, w, gg[3]);
    }

    // gate contraction: out[n][d] = sum_c v[n][d][c] * gg[n][c]
    float p[4][3];
    #pragma unroll
    for (int m = 0; m < 4; ++m) {
        int n = n0 + qt*4 + m;
        p[m][0] = g_v[(n*3 + 0)*Hh + c] * gg[m];
        p[m][1] = g_v[(n*3 + 1)*Hh + c] * gg[m];
        p[m][2] = g_v[(n*3 + 2)*Hh + c] * gg[m];
    }
    #pragma unroll
    for (int m = 0; m < 4; ++m)
        #pragma unroll
        for (int d = 0; d < 3; ++d) {
            float v = p[m][d];
            #pragma unroll
            for (int off = 16; off; off >>= 1) v += __shfl_xor_sync(0xffffffffu, v, off);
            p[m][d] = v;
        }
    const int lane = tid & 31, warp = tid >> 5;
    if (lane == 0) {
        #pragma unroll
        for (int m = 0; m < 4; ++m)
            #pragma unroll
            for (int d = 0; d < 3; ++d) red[warp][m*3 + d] = p[m][d];
    }
    __syncthreads();
    if (tid < 48) {
        const int qtg = tid / 12, rem = tid % 12;
        float s = red[qtg*4 + 0][rem] + red[qtg*4 + 1][rem]
                + red[qtg*4 + 2][rem] + red[qtg*4 + 3][rem];
        out[(n0 + qtg*4 + rem/3)*3 + (rem % 3)] = s * fsp[0];
    }
}

// ---------------- launch ---------------------------------------------------
extern "C" void kernel_launch(void* const* d_in, const int* in_sizes, int n_in,
                              void* d_out, int out_size) {
    const float* positions = (const float*)d_in[0];
    const int*   nodef     = (const int*)  d_in[1];
    const float* gf        = (const float*)d_in[2];
    const float* emb       = (const float*)d_in[3];
    const float* Wt        = (const float*)d_in[4];
    const float* Wr1       = (const float*)d_in[5];
    const float* Wr2       = (const float*)d_in[6];
    const float* Wupd      = (const float*)d_in[7];
    const float* Wmix      = (const float*)d_in[8];
    const float* Wg1       = (const float*)d_in[9];
    const float* Wg2       = (const float*)d_in[10];
    const float* fs        = (const float*)d_in[11];
    float*       out       = (float*)d_out;

    const int msg_smem = MSG_WORDS * 4;
    const int upd_smem = (16384 + Hh*UP0 + Hh*3*UP0) * 4;
    const int rdo_smem = (Hh*Hh*2 + Hh*RP*2) * 4;
    cudaFuncSetAttribute(msg_kernel,     cudaFuncAttributeMaxDynamicSharedMemorySize, msg_smem);
    cudaFuncSetAttribute(upd_kernel,     cudaFuncAttributeMaxDynamicSharedMemorySize, upd_smem);
    cudaFuncSetAttribute(readout_kernel, cudaFuncAttributeMaxDynamicSharedMemorySize, rdo_smem);

    probe_kernel<<<1, 1>>>(nodef);
    init_kernel<<<Bb*Nn/16, 512>>>(nodef, gf, emb, Wt);
    wr2h_kernel<<<Ll, 256>>>(Wr2);

    for (int l = 0; l < Ll; ++l) {
        dim3 grid(16, Bb);
        msg_kernel<<<grid, 256, msg_smem>>>(positions, Wr1 + l*NBb*Hh, l);
        upd_kernel<<<Bb*Nn/8, 256, upd_smem>>>(Wupd + l*Hh*Hh, Wmix + l*Hh*Hh);
    }
    readout_kernel<<<Bb*Nn/16, 512, rdo_smem>>>(Wg1, Wg2, fs, out);
}

// round 10
// speedup vs baseline: 6.0672x; 1.2651x over previous
#include <cuda_runtime.h>
#include <cuda_fp16.h>
#include <math.h>
#include <stdint.h>

// Problem constants
#define Bb   64
#define Nn   64
#define Hh   128
#define NBb  8
#define Tt   32
#define Ll   2

// ---------------- device scratch (no allocations allowed) ----------------
__device__ float    g_h   [Bb*Nn*Hh];      // node scalar features
__device__ float    g_v   [Bb*Nn*3*Hh];    // vector features SoA [n][d][c]
__device__ float    g_a0  [Bb*Nn*Hh];      // scalar aggregates
__device__ float    g_a1  [Bb*Nn*3*Hh];    // vector aggregates SoA [n][d][c]
__device__ uint32_t g_Wr2H[Ll*8192];       // Wr2^T fp16 B-frags [kb8][c128][8w]
__device__ uint32_t g_WuH [Ll*8192];       // Wupd^T fp16 B-frags
__device__ uint32_t g_WmH [Ll*8192];       // Wmix^T fp16 B-frags
__device__ int      g_z64;                 // species dtype flag

// ---------------- helpers -------------------------------------------------
__device__ __forceinline__ uint32_t f2tf32(float x) {
    uint32_t r;
    asm("cvt.rn.tf32.f32 %0, %1;" : "=r"(r) : "f"(x));
    return r;
}
__device__ __forceinline__ void mma_tf32(float* c,
                                         uint32_t a0, uint32_t a1, uint32_t a2, uint32_t a3,
                                         uint32_t b0, uint32_t b1) {
    asm volatile(
        "mma.sync.aligned.m16n8k8.row.col.f32.tf32.tf32.f32 "
        "{%0,%1,%2,%3},{%4,%5,%6,%7},{%8,%9},{%0,%1,%2,%3};"
        : "+f"(c[0]), "+f"(c[1]), "+f"(c[2]), "+f"(c[3])
        : "r"(a0), "r"(a1), "r"(a2), "r"(a3), "r"(b0), "r"(b1));
}
__device__ __forceinline__ void mma_f16(float* c,
                                        uint32_t a0, uint32_t a1, uint32_t a2, uint32_t a3,
                                        uint32_t b0, uint32_t b1) {
    asm volatile(
        "mma.sync.aligned.m16n8k16.row.col.f32.f16.f16.f32 "
        "{%0,%1,%2,%3},{%4,%5,%6,%7},{%8,%9},{%0,%1,%2,%3};"
        : "+f"(c[0]), "+f"(c[1]), "+f"(c[2]), "+f"(c[3])
        : "r"(a0), "r"(a1), "r"(a2), "r"(a3), "r"(b0), "r"(b1));
}
__device__ __forceinline__ float silu_f(float x) {
    return __fdividef(x, 1.0f + __expf(-x));
}
__device__ __forceinline__ uint32_t pack_h2(float lo, float hi) {
    __half2 h = __floats2half2_rn(lo, hi);
    return *(uint32_t*)&h;
}

// ---------------- K0: probe node_features dtype -------------------------
__global__ void probe_kernel(const int* __restrict__ z) {
    int nz = 0;
    for (int t = 0; t < 64; ++t) nz |= z[2*t + 1];
    g_z64 = (nz == 0) ? 1 : 0;
}

// ---------------- K1: h = emb[z] + t @ Wt ; v = 0  (16 nodes/CTA) --------
__global__ __launch_bounds__(512, 1)
void init_kernel(const int* __restrict__ z,
                 const float* __restrict__ gf,
                 const float* __restrict__ emb,
                 const float* __restrict__ Wt) {
    const int n0 = blockIdx.x * 16;
    const int b  = n0 >> 6;
    const int c  = threadIdx.x & 127;
    const int qt = threadIdx.x >> 7;
    float tw = 0.f;
    const float* g = gf + b*Tt;
    #pragma unroll
    for (int t = 0; t < Tt; ++t) tw += g[t] * Wt[t*Hh + c];
    #pragma unroll
    for (int m = 0; m < 4; ++m) {
        const int n  = n0 + qt*4 + m;
        const int zi = g_z64 ? z[2*n] : z[n];
        g_h[n*Hh + c] = emb[zi*Hh + c] + tw;
        g_v[(n*3 + 0)*Hh + c] = 0.f;
        g_v[(n*3 + 1)*Hh + c] = 0.f;
        g_v[(n*3 + 2)*Hh + c] = 0.f;
    }
}

// ---------------- K1b: weight -> fp16 B-fragment layout -------------------
// word (kb*128 + c)*8 + q*2 + hi  holds fp16 pair (W[k][c], W[k+1][c]),
// k = kb*16 + 2q + 8hi
__global__ void wfrag_kernel(const float* __restrict__ Wr2,
                             const float* __restrict__ Wupd,
                             const float* __restrict__ Wmix) {
    const int l = blockIdx.x;   // layer
    const int a = blockIdx.y;   // which array
    const float* src = (a == 0) ? Wr2 : (a == 1) ? Wupd : Wmix;
    uint32_t*    dst = (a == 0) ? g_Wr2H : (a == 1) ? g_WuH : g_WmH;
    src += l*Hh*Hh;
    dst += l*8192;
    for (int idx = threadIdx.x; idx < 8192; idx += 256) {
        int c  = idx >> 6, kp = idx & 63;
        int k  = kp * 2;
        int kb = k >> 4;
        int kw = k & 15;
        int q  = (kw >> 1) & 3;
        int hi = kw >> 3;
        dst[(kb*128 + c)*8 + q*2 + hi] = pack_h2(src[k*Hh + c], src[(k+1)*Hh + c]);
    }
}

// ---------------- smem word offsets for msg kernel ------------------------
#define OFF_W2T  0          // 8192 words: fp16 B frags [kb8][c128][8w]
#define OFF_S    8192       // 4096:  fp16 A frags single buffer [kb8][mt4][r16][8w]
#define OFF_RBF  12288      // 2048:  [jl4][i64][8 perm-k] tf32
#define OFF_U4F  14336      // 1024:  [jl4][i64] float4
#define OFF_POS  15360      // 192
#define OFF_W1U  15552      // 1024:  Wr1 tf32 [8][128]
#define MSG_WORDS 16576     // 66304 bytes -> 3 CTAs/SM

// ---------------- K2: message pass (fp16 tensor GEMM, 3 CTAs/SM) ----------
// CTA = (4 receivers jg, batch b), 256 threads = 8 warps.
__global__ __launch_bounds__(256, 3)
void msg_kernel(const float* __restrict__ pos,
                const float* __restrict__ Wr1,
                int layer) {
    extern __shared__ float smf[];
    uint32_t* W2Tf  = (uint32_t*)smf + OFF_W2T;
    uint32_t* Sall  = (uint32_t*)smf + OFF_S;
    uint32_t* rbf   = (uint32_t*)smf + OFF_RBF;
    float*    u4f   = smf + OFF_U4F;
    float*    pos_s = smf + OFF_POS;
    uint32_t* w1u   = (uint32_t*)smf + OFF_W1U;

    const int b    = blockIdx.y;
    const int jg   = blockIdx.x;            // 0..15
    const int tid  = threadIdx.x;
    const int lane = tid & 31;
    const int widh = tid >> 5;              // 0..7

    // ---- stage W2T fp16 fragments (direct copy), pos, Wr1(tf32) ----
    for (int idx = tid; idx < 8192; idx += 256) W2Tf[idx] = g_Wr2H[layer*8192 + idx];
    for (int idx = tid; idx < Nn*3;   idx += 256) pos_s[idx] = pos[b*Nn*3 + idx];
    for (int idx = tid; idx < NBb*Hh; idx += 256) w1u[idx]   = f2tf32(Wr1[idx]);

    // ---- register-cache h (fixed across receivers): 8 rows x 2 float2 ----
    float2 hreg[4][2][2];
    {
        const float* hb = g_h + (size_t)b*Nn*Hh;
        #pragma unroll
        for (int mt = 0; mt < 4; ++mt)
            #pragma unroll
            for (int rg = 0; rg < 2; ++rg) {
                int i = mt*16 + (lane>>2) + rg*8;
                #pragma unroll
                for (int nt = 0; nt < 2; ++nt) {
                    int c = widh*16 + nt*8 + (lane&3)*2;
                    hreg[mt][rg][nt] = *(const float2*)(hb + i*Hh + c);
                }
            }
    }
    __syncthreads();

    const float PI5 = 0.62831853071795864769f;   // pi/5
    const float s63 = 1.0f / 63.0f;

    // ---- geometry + bessel for all 4 receivers (256 = 4j x 64i) ----
    {
        const int jl = tid >> 6;             // 0..3
        const int i  = tid & 63;
        const int j  = jg*4 + jl;
        float dx = pos_s[j*3+0] - pos_s[i*3+0];
        float dy = pos_s[j*3+1] - pos_s[i*3+1];
        float dz = pos_s[j*3+2] - pos_s[i*3+2];
        float r2 = dx*dx + dy*dy + dz*dz + 1e-12f;
        float r  = sqrtf(r2);
        float inv = 1.0f / r;
        ((float4*)u4f)[jl*Nn + i] = make_float4(dx*inv, dy*inv, dz*inv, 0.f);
        float fc = 0.0f;
        if (r < 5.0f && i != j) fc = 0.5f * (cosf(PI5 * r) + 1.0f);
        float sc  = inv * fc;
        float arg = PI5 * r;
        float rv[8];
        #pragma unroll
        for (int q = 0; q < NBb; ++q) rv[q] = sinf((float)(q+1) * arg) * sc;
        // perm order for tf32 k8 A-frag: [k0,k4,k1,k5 | k2,k6,k3,k7]
        uint4 lo = make_uint4(f2tf32(rv[0]), f2tf32(rv[4]), f2tf32(rv[1]), f2tf32(rv[5]));
        uint4 hi = make_uint4(f2tf32(rv[2]), f2tf32(rv[6]), f2tf32(rv[3]), f2tf32(rv[7]));
        ((uint4*)rbf)[(jl*Nn + i)*2 + 0] = lo;
        ((uint4*)rbf)[(jl*Nn + i)*2 + 1] = hi;
    }
    __syncthreads();

    // ---- hoist Wr1 B-frags (per warp: cols widh*16 .. +16) ----
    uint32_t wb00, wb01, wb10, wb11;
    {
        int colA = widh*16 + (lane>>2);
        int colB = colA + 8;
        int kq   = lane & 3;
        wb00 = w1u[kq*Hh + colA];  wb01 = w1u[(kq+4)*Hh + colA];
        wb10 = w1u[kq*Hh + colB];  wb11 = w1u[(kq+4)*Hh + colB];
    }

    const int r4 = lane >> 2;                // 0..7
    const int q4 = lane & 3;                 // 0..3

    for (int jj = 0; jj < 4; ++jj) {
        const int j = jg*4 + jj;

        // ---- S = silu(rb @ Wr1) via tf32 MMA, per-mt (low reg pressure) ----
        {
            const uint32_t* rbj = rbf + jj*Nn*8;
            #pragma unroll
            for (int mt = 0; mt < 4; ++mt) {
                float s0[4] = {0.f, 0.f, 0.f, 0.f};
                float s1[4] = {0.f, 0.f, 0.f, 0.f};
                int r0 = mt*16 + r4;
                uint2 A0 = *(const uint2*)(rbj + r0*8     + q4*2);
                uint2 A1 = *(const uint2*)(rbj + (r0+8)*8 + q4*2);
                mma_tf32(s0, A0.x, A1.x, A0.y, A1.y, wb00, wb01);
                mma_tf32(s1, A0.x, A1.x, A0.y, A1.y, wb10, wb11);
                const int base = widh*512 + mt*128 + r4*8;
                Sall[base + q4*2 + 0]      = pack_h2(silu_f(s0[0]), silu_f(s0[1]));
                Sall[base + q4*2 + 1]      = pack_h2(silu_f(s1[0]), silu_f(s1[1]));
                Sall[base + 64 + q4*2 + 0] = pack_h2(silu_f(s0[2]), silu_f(s0[3]));
                Sall[base + 64 + q4*2 + 1] = pack_h2(silu_f(s1[2]), silu_f(s1[3]));
            }
        }
        __syncthreads();

        // ---- fused GEMM + epilogue, per-mt tiles (acc live = 8 regs) ----
        float pa[2][2][4];
        #pragma unroll
        for (int nt = 0; nt < 2; ++nt)
            #pragma unroll
            for (int cp = 0; cp < 2; ++cp) {
                pa[nt][cp][0]=0.f; pa[nt][cp][1]=0.f; pa[nt][cp][2]=0.f; pa[nt][cp][3]=0.f;
            }
        const float4* uj = (const float4*)u4f + jj*Nn;
        const uint32_t* Ap = Sall + r4*8 + q4*2;
        const uint32_t* Bp = W2Tf + (widh*16 + r4)*8 + q4*2;

        #pragma unroll
        for (int mt = 0; mt < 4; ++mt) {
            float acc0[4] = {0.f, 0.f, 0.f, 0.f};
            float acc1[4] = {0.f, 0.f, 0.f, 0.f};
            #pragma unroll
            for (int kb = 0; kb < 8; ++kb) {
                uint2 Bv0 = *(const uint2*)(Bp + kb*1024);
                uint2 Bv1 = *(const uint2*)(Bp + kb*1024 + 64);
                uint2 A0  = *(const uint2*)(Ap + kb*512 + mt*128);
                uint2 A1  = *(const uint2*)(Ap + kb*512 + mt*128 + 64);
                mma_f16(acc0, A0.x, A1.x, A0.y, A1.y, Bv0.x, Bv0.y);
                mma_f16(acc1, A0.x, A1.x, A0.y, A1.y, Bv1.x, Bv1.y);
            }
            #pragma unroll
            for (int rg = 0; rg < 2; ++rg) {
                int i = mt*16 + r4 + rg*8;
                float4 uv = uj[i];
                float2 h0 = hreg[mt][rg][0];
                float2 h1 = hreg[mt][rg][1];
                #pragma unroll
                for (int cp = 0; cp < 2; ++cp) {
                    float m0 = acc0[rg*2+cp] * (cp ? h0.y : h0.x);
                    pa[0][cp][0] += m0;
                    pa[0][cp][1] = fmaf(m0, uv.x, pa[0][cp][1]);
                    pa[0][cp][2] = fmaf(m0, uv.y, pa[0][cp][2]);
                    pa[0][cp][3] = fmaf(m0, uv.z, pa[0][cp][3]);
                    float m1 = acc1[rg*2+cp] * (cp ? h1.y : h1.x);
                    pa[1][cp][0] += m1;
                    pa[1][cp][1] = fmaf(m1, uv.x, pa[1][cp][1]);
                    pa[1][cp][2] = fmaf(m1, uv.y, pa[1][cp][2]);
                    pa[1][cp][3] = fmaf(m1, uv.z, pa[1][cp][3]);
                }
            }
        }

        #pragma unroll
        for (int nt = 0; nt < 2; ++nt)
            #pragma unroll
            for (int cp = 0; cp < 2; ++cp)
                #pragma unroll
                for (int q = 0; q < 4; ++q) {
                    float v = pa[nt][cp][q];
                    v += __shfl_xor_sync(0xffffffffu, v, 4);
                    v += __shfl_xor_sync(0xffffffffu, v, 8);
                    v += __shfl_xor_sync(0xffffffffu, v, 16);
                    pa[nt][cp][q] = v;
                }
        if (lane < 4) {
            const int nidx = b*Nn + j;
            #pragma unroll
            for (int nt = 0; nt < 2; ++nt)
                #pragma unroll
                for (int cp = 0; cp < 2; ++cp) {
                    int c = widh*16 + nt*8 + lane*2 + cp;
                    g_a0[nidx*Hh + c]         = pa[nt][cp][0] * s63;
                    g_a1[(nidx*3+0)*Hh + c]   = pa[nt][cp][1] * s63;
                    g_a1[(nidx*3+1)*Hh + c]   = pa[nt][cp][2] * s63;
                    g_a1[(nidx*3+2)*Hh + c]   = pa[nt][cp][3] * s63;
                }
        }
        __syncthreads();   // guard S overwrite next iteration
    }
}

// ---------------- K3: tensorized update ----------------------------------
// h += a0 @ Wupd ; v += a1_d @ Wmix  as 4 GEMMs [16x128]@[128x128]
// 256 threads, 16 nodes/CTA; A = a0/a1 fp16 frags; B = prestaged weight frags.
#define UPD_A    0        // 4096 words: A frags [kb8][mt4][r16][8w]
#define UPD_WU   4096     // 8192 words
#define UPD_WM   12288    // 8192 words
#define UPD_WORDS 20480   // 81920 bytes

__global__ __launch_bounds__(256, 1)
void upd_kernel(int layer) {
    extern __shared__ uint32_t usm[];
    uint32_t* A_s  = usm + UPD_A;
    uint32_t* Wu_s = usm + UPD_WU;
    uint32_t* Wm_s = usm + UPD_WM;

    const int n0  = blockIdx.x * 16;
    const int tid = threadIdx.x;

    for (int idx = tid; idx < 8192; idx += 256) {
        Wu_s[idx] = g_WuH[layer*8192 + idx];
        Wm_s[idx] = g_WmH[layer*8192 + idx];
    }
    // stage A frags: mt0 = a0, mt1..3 = a1 components
    for (int idx = tid; idx < 4096; idx += 256) {
        int w  = idx & 7;
        int r  = (idx >> 3) & 15;
        int mt = (idx >> 7) & 3;
        int kb = idx >> 9;
        int k  = kb*16 + ((w >> 1) & 3)*2 + (w & 1)*8;
        const float* src = (mt == 0)
            ? (g_a0 + (size_t)(n0 + r)*Hh + k)
            : (g_a1 + ((size_t)(n0 + r)*3 + (mt - 1))*Hh + k);
        float2 v = *(const float2*)src;
        A_s[idx] = pack_h2(v.x, v.y);
    }
    __syncthreads();

    const int lane = tid & 31;
    const int widh = tid >> 5;
    const int r4 = lane >> 2, q4 = lane & 3;
    const uint32_t* Ap = A_s + r4*8 + q4*2;

    #pragma unroll
    for (int mt = 0; mt < 4; ++mt) {
        const uint32_t* Bp = ((mt == 0) ? Wu_s : Wm_s) + (widh*16 + r4)*8 + q4*2;
        float acc0[4] = {0.f, 0.f, 0.f, 0.f};
        float acc1[4] = {0.f, 0.f, 0.f, 0.f};
        #pragma unroll
        for (int kb = 0; kb < 8; ++kb) {
            uint2 Bv0 = *(const uint2*)(Bp + kb*1024);
            uint2 Bv1 = *(const uint2*)(Bp + kb*1024 + 64);
            uint2 A0  = *(const uint2*)(Ap + kb*512 + mt*128);
            uint2 A1  = *(const uint2*)(Ap + kb*512 + mt*128 + 64);
            mma_f16(acc0, A0.x, A1.x, A0.y, A1.y, Bv0.x, Bv0.y);
            mma_f16(acc1, A0.x, A1.x, A0.y, A1.y, Bv1.x, Bv1.y);
        }
        #pragma unroll
        for (int rg = 0; rg < 2; ++rg) {
            int n = n0 + r4 + rg*8;
            #pragma unroll
            for (int nt = 0; nt < 2; ++nt) {
                int c = widh*16 + nt*8 + q4*2;
                float* dst = (mt == 0) ? (g_h + (size_t)n*Hh + c)
                                       : (g_v + ((size_t)n*3 + (mt - 1))*Hh + c);
                const float* a = nt ? acc1 : acc0;
                float2 old = *(float2*)dst;
                old.x += a[rg*2 + 0];
                old.y += a[rg*2 + 1];
                *(float2*)dst = old;
            }
        }
    }
}

// ---------------- K4: gated readout (16 nodes/CTA, staged weights) --------
#define RP 20
__global__ __launch_bounds__(512, 1)
void readout_kernel(const float* __restrict__ Wg1,
                    const float* __restrict__ Wg2,
                    const float* __restrict__ fsp,
                    float* __restrict__ out) {
    extern __shared__ float rsm[];
    float* W1_s = rsm;                       // 16384
    float* W2_s = W1_s + Hh*Hh;              // 16384
    float* hT   = W2_s + Hh*Hh;              // 128*RP
    float* tT   = hT + Hh*RP;                // 128*RP
    __shared__ float red[16][12];

    const int n0  = blockIdx.x * 16;
    const int tid = threadIdx.x;
    for (int idx = tid; idx < Hh*Hh; idx += 512) { W1_s[idx] = Wg1[idx]; W2_s[idx] = Wg2[idx]; }
    for (int idx = tid; idx < 16*Hh; idx += 512) {
        int n = idx >> 7, g = idx & 127;
        hT[g*RP + n] = g_h[n0*Hh + idx];
    }
    __syncthreads();

    const int c  = tid & 127;
    const int qt = tid >> 7;

    // t = h @ Wg1
    float t[4] = {0.f, 0.f, 0.f, 0.f};
    #pragma unroll 2
    for (int g = 0; g < Hh; ++g) {
        float w = W1_s[g*Hh + c];
        float4 hv = *(const float4*)(hT + g*RP + qt*4);
        t[0] = fmaf(hv.x, w, t[0]);
        t[1] = fmaf(hv.y, w, t[1]);
        t[2] = fmaf(hv.z, w, t[2]);
        t[3] = fmaf(hv.w, w, t[3]);
    }
    #pragma unroll
    for (int m = 0; m < 4; ++m) tT[c*RP + qt*4 + m] = silu_f(t[m]);
    __syncthreads();

    // g = silu(t) @ Wg2
    float gg[4] = {0.f, 0.f, 0.f, 0.f};
    #pragma unroll 2
    for (int k = 0; k < Hh; ++k) {
        float w = W2_s[k*Hh + c];
        float4 tv = *(const float4*)(tT + k*RP + qt*4);
        gg[0] = fmaf(tv.x, w, gg[0]);
        gg[1] = fmaf(tv.y, w, gg[1]);
        gg[2] = fmaf(tv.z, w, gg[2]);
        gg[3] = fmaf(tv.w, w, gg[3]);
    }

    // gate contraction: out[n][d] = sum_c v[n][d][c] * gg[n][c]
    float p[4][3];
    #pragma unroll
    for (int m = 0; m < 4; ++m) {
        int n = n0 + qt*4 + m;
        p[m][0] = g_v[(n*3 + 0)*Hh + c] * gg[m];
        p[m][1] = g_v[(n*3 + 1)*Hh + c] * gg[m];
        p[m][2] = g_v[(n*3 + 2)*Hh + c] * gg[m];
    }
    #pragma unroll
    for (int m = 0; m < 4; ++m)
        #pragma unroll
        for (int d = 0; d < 3; ++d) {
            float v = p[m][d];
            #pragma unroll
            for (int off = 16; off; off >>= 1) v += __shfl_xor_sync(0xffffffffu, v, off);
            p[m][d] = v;
        }
    const int lane = tid & 31, warp = tid >> 5;
    if (lane == 0) {
        #pragma unroll
        for (int m = 0; m < 4; ++m)
            #pragma unroll
            for (int d = 0; d < 3; ++d) red[warp][m*3 + d] = p[m][d];
    }
    __syncthreads();
    if (tid < 48) {
        const int qtg = tid / 12, rem = tid % 12;
        float s = red[qtg*4 + 0][rem] + red[qtg*4 + 1][rem]
                + red[qtg*4 + 2][rem] + red[qtg*4 + 3][rem];
        out[(n0 + qtg*4 + rem/3)*3 + (rem % 3)] = s * fsp[0];
    }
}

// ---------------- launch ---------------------------------------------------
extern "C" void kernel_launch(void* const* d_in, const int* in_sizes, int n_in,
                              void* d_out, int out_size) {
    const float* positions = (const float*)d_in[0];
    const int*   nodef     = (const int*)  d_in[1];
    const float* gf        = (const float*)d_in[2];
    const float* emb       = (const float*)d_in[3];
    const float* Wt        = (const float*)d_in[4];
    const float* Wr1       = (const float*)d_in[5];
    const float* Wr2       = (const float*)d_in[6];
    const float* Wupd      = (const float*)d_in[7];
    const float* Wmix      = (const float*)d_in[8];
    const float* Wg1       = (const float*)d_in[9];
    const float* Wg2       = (const float*)d_in[10];
    const float* fs        = (const float*)d_in[11];
    float*       out       = (float*)d_out;

    const int msg_smem = MSG_WORDS * 4;
    const int upd_smem = UPD_WORDS * 4;
    const int rdo_smem = (Hh*Hh*2 + Hh*RP*2) * 4;
    cudaFuncSetAttribute(msg_kernel,     cudaFuncAttributeMaxDynamicSharedMemorySize, msg_smem);
    cudaFuncSetAttribute(upd_kernel,     cudaFuncAttributeMaxDynamicSharedMemorySize, upd_smem);
    cudaFuncSetAttribute(readout_kernel, cudaFuncAttributeMaxDynamicSharedMemorySize, rdo_smem);

    probe_kernel<<<1, 1>>>(nodef);
    init_kernel<<<Bb*Nn/16, 512>>>(nodef, gf, emb, Wt);
    {
        dim3 wgrid(Ll, 3);
        wfrag_kernel<<<wgrid, 256>>>(Wr2, Wupd, Wmix);
    }

    for (int l = 0; l < Ll; ++l) {
        dim3 grid(16, Bb);
        msg_kernel<<<grid, 256, msg_smem>>>(positions, Wr1 + l*NBb*Hh, l);
        upd_kernel<<<Bb*Nn/16, 256, upd_smem>>>(l);
    }
    readout_kernel<<<Bb*Nn/16, 512, rdo_smem>>>(Wg1, Wg2, fs, out);
}

// round 11
// speedup vs baseline: 6.1874x; 1.0198x over previous
#include <cuda_runtime.h>
#include <cuda_fp16.h>
#include <math.h>
#include <stdint.h>

// Problem constants
#define Bb   64
#define Nn   64
#define Hh   128
#define NBb  8
#define Tt   32
#define Ll   2

// ---------------- device scratch (no allocations allowed) ----------------
__device__ float    g_h   [Bb*Nn*Hh];      // node scalar features
__device__ float    g_v   [Bb*Nn*3*Hh];    // vector features SoA [n][d][c]
__device__ float    g_a0  [Bb*Nn*Hh];      // scalar aggregates
__device__ float    g_a1  [Bb*Nn*3*Hh];    // vector aggregates SoA [n][d][c]
__device__ uint32_t g_Wr2H[Ll*8192];       // Wr2^T fp16 B-frags [kb8][c128][8w]
__device__ uint32_t g_WuH [Ll*8192];       // Wupd^T fp16 B-frags
__device__ uint32_t g_WmH [Ll*8192];       // Wmix^T fp16 B-frags
__device__ int      g_z64;                 // species dtype flag

// ---------------- helpers -------------------------------------------------
__device__ __forceinline__ void mma_f16(float* c,
                                        uint32_t a0, uint32_t a1, uint32_t a2, uint32_t a3,
                                        uint32_t b0, uint32_t b1) {
    asm volatile(
        "mma.sync.aligned.m16n8k16.row.col.f32.f16.f16.f32 "
        "{%0,%1,%2,%3},{%4,%5,%6,%7},{%8,%9},{%0,%1,%2,%3};"
        : "+f"(c[0]), "+f"(c[1]), "+f"(c[2]), "+f"(c[3])
        : "r"(a0), "r"(a1), "r"(a2), "r"(a3), "r"(b0), "r"(b1));
}
__device__ __forceinline__ float silu_f(float x) {
    return __fdividef(x, 1.0f + __expf(-x));
}
__device__ __forceinline__ uint32_t pack_h2(float lo, float hi) {
    __half2 h = __floats2half2_rn(lo, hi);
    return *(uint32_t*)&h;
}

// ---------------- K0: probe node_features dtype -------------------------
__global__ void probe_kernel(const int* __restrict__ z) {
    int nz = 0;
    for (int t = 0; t < 64; ++t) nz |= z[2*t + 1];
    g_z64 = (nz == 0) ? 1 : 0;
}

// ---------------- K1: h = emb[z] + t @ Wt ; v = 0  (16 nodes/CTA) --------
__global__ __launch_bounds__(512, 1)
void init_kernel(const int* __restrict__ z,
                 const float* __restrict__ gf,
                 const float* __restrict__ emb,
                 const float* __restrict__ Wt) {
    const int n0 = blockIdx.x * 16;
    const int b  = n0 >> 6;
    const int c  = threadIdx.x & 127;
    const int qt = threadIdx.x >> 7;
    float tw = 0.f;
    const float* g = gf + b*Tt;
    #pragma unroll
    for (int t = 0; t < Tt; ++t) tw += g[t] * Wt[t*Hh + c];
    #pragma unroll
    for (int m = 0; m < 4; ++m) {
        const int n  = n0 + qt*4 + m;
        const int zi = g_z64 ? z[2*n] : z[n];
        g_h[n*Hh + c] = emb[zi*Hh + c] + tw;
        g_v[(n*3 + 0)*Hh + c] = 0.f;
        g_v[(n*3 + 1)*Hh + c] = 0.f;
        g_v[(n*3 + 2)*Hh + c] = 0.f;
    }
}

// ---------------- K1b: weight -> fp16 B-fragment layout -------------------
// word (kb*128 + c)*8 + q*2 + hi  holds fp16 pair (W[k][c], W[k+1][c]),
// k = kb*16 + 2q + 8hi
__global__ void wfrag_kernel(const float* __restrict__ Wr2,
                             const float* __restrict__ Wupd,
                             const float* __restrict__ Wmix) {
    const int l = blockIdx.x;   // layer
    const int a = blockIdx.y;   // which array
    const float* src = (a == 0) ? Wr2 : (a == 1) ? Wupd : Wmix;
    uint32_t*    dst = (a == 0) ? g_Wr2H : (a == 1) ? g_WuH : g_WmH;
    src += l*Hh*Hh;
    dst += l*8192;
    for (int idx = threadIdx.x; idx < 8192; idx += 256) {
        int c  = idx >> 6, kp = idx & 63;
        int k  = kp * 2;
        int kb = k >> 4;
        int kw = k & 15;
        int q  = (kw >> 1) & 3;
        int hi = kw >> 3;
        dst[(kb*128 + c)*8 + q*2 + hi] = pack_h2(src[k*Hh + c], src[(k+1)*Hh + c]);
    }
}

// ---------------- smem word offsets for msg kernel ------------------------
#define OFF_W2T  0          // 8192 words: fp16 B frags [kb8][c128][8w]
#define OFF_S    8192       // 8192:  fp16 A frags 2 receivers [kb8][mtS8][r16][8w]
#define OFF_RBF  16384      // 1024:  fp16 rb [jl4][i64][4w]
#define OFF_U4F  17408      // 1024:  [jl4][i64] float4
#define MSG_WORDS 18432     // 73728 bytes -> 3 CTAs/SM

// ---------------- K2: message pass (fp16 tensor GEMM, 3 CTAs/SM) ----------
// CTA = (4 receivers jg, batch b), 256 threads = 8 warps, 2 receivers/round.
__global__ __launch_bounds__(256, 3)
void msg_kernel(const float* __restrict__ pos,
                const float* __restrict__ Wr1,
                int layer) {
    extern __shared__ float smf[];
    uint32_t* W2Tf = (uint32_t*)smf + OFF_W2T;
    uint32_t* Sf   = (uint32_t*)smf + OFF_S;
    uint32_t* rbf  = (uint32_t*)smf + OFF_RBF;
    float*    u4f  = smf + OFF_U4F;

    const int b    = blockIdx.y;
    const int jg   = blockIdx.x;            // 0..15
    const int tid  = threadIdx.x;
    const int lane = tid & 31;
    const int widh = tid >> 5;              // 0..7
    const int r4   = lane >> 2;             // 0..7
    const int q4   = lane & 3;              // 0..3

    // ---- stage W2T fp16 fragments (direct copy) ----
    for (int idx = tid; idx < 8192; idx += 256) W2Tf[idx] = g_Wr2H[layer*8192 + idx];

    // ---- register-cache h (fixed across receivers): 8 rows x 2 float2 ----
    float2 hreg[4][2][2];
    {
        const float* hb = g_h + (size_t)b*Nn*Hh;
        #pragma unroll
        for (int mt = 0; mt < 4; ++mt)
            #pragma unroll
            for (int rg = 0; rg < 2; ++rg) {
                int i = mt*16 + r4 + rg*8;
                #pragma unroll
                for (int nt = 0; nt < 2; ++nt) {
                    int c = widh*16 + nt*8 + q4*2;
                    hreg[mt][rg][nt] = *(const float2*)(hb + i*Hh + c);
                }
            }
    }

    // ---- Wr1 fp16 B-frags in registers (b0 only; k8-15 are zero) ----
    uint32_t wbA, wbB;
    {
        int cA = widh*16 + r4;
        int cB = cA + 8;
        wbA = pack_h2(Wr1[(q4*2)*Hh + cA], Wr1[(q4*2+1)*Hh + cA]);
        wbB = pack_h2(Wr1[(q4*2)*Hh + cB], Wr1[(q4*2+1)*Hh + cB]);
    }

    const float PI5 = 0.62831853071795864769f;   // pi/5
    const float s63 = 1.0f / 63.0f;

    // ---- geometry + bessel for all 4 receivers (256 = 4j x 64i) ----
    {
        const int jl = tid >> 6;             // 0..3
        const int i  = tid & 63;
        const int j  = jg*4 + jl;
        const float* pb = pos + b*Nn*3;
        float dx = pb[j*3+0] - pb[i*3+0];
        float dy = pb[j*3+1] - pb[i*3+1];
        float dz = pb[j*3+2] - pb[i*3+2];
        float r2 = dx*dx + dy*dy + dz*dz + 1e-12f;
        float r  = sqrtf(r2);
        float inv = 1.0f / r;
        ((float4*)u4f)[jl*Nn + i] = make_float4(dx*inv, dy*inv, dz*inv, 0.f);
        float fc = 0.0f;
        if (r < 5.0f && i != j) fc = 0.5f * (cosf(PI5 * r) + 1.0f);
        float sc  = inv * fc;
        float arg = PI5 * r;
        float rv[8];
        #pragma unroll
        for (int q = 0; q < NBb; ++q) rv[q] = sinf((float)(q+1) * arg) * sc;
        uint4 rw;
        rw.x = pack_h2(rv[0], rv[1]);
        rw.y = pack_h2(rv[2], rv[3]);
        rw.z = pack_h2(rv[4], rv[5]);
        rw.w = pack_h2(rv[6], rv[7]);
        ((uint4*)rbf)[jl*Nn + i] = rw;
    }
    __syncthreads();

    for (int rr = 0; rr < 2; ++rr) {
        // ---- S = silu(rb @ Wr1) for receivers rr*2, rr*2+1 (fp16 MMA, K=8) ----
        #pragma unroll
        for (int jh = 0; jh < 2; ++jh) {
            const uint32_t* rbj = rbf + (rr*2 + jh)*Nn*4;
            #pragma unroll
            for (int mt = 0; mt < 4; ++mt) {
                int r0 = mt*16 + r4;
                uint32_t A0 = rbj[r0*4 + q4];
                uint32_t A1 = rbj[(r0+8)*4 + q4];
                float s0[4] = {0.f, 0.f, 0.f, 0.f};
                float s1[4] = {0.f, 0.f, 0.f, 0.f};
                mma_f16(s0, A0, A1, 0u, 0u, wbA, 0u);
                mma_f16(s1, A0, A1, 0u, 0u, wbB, 0u);
                const int mtS = jh*4 + mt;
                uint32_t* Sb = Sf + (widh*8 + mtS)*128 + r4*8 + q4*2;
                *(uint2*)(Sb)      = make_uint2(pack_h2(silu_f(s0[0]), silu_f(s0[1])),
                                                pack_h2(silu_f(s1[0]), silu_f(s1[1])));
                *(uint2*)(Sb + 64) = make_uint2(pack_h2(silu_f(s0[2]), silu_f(s0[3])),
                                                pack_h2(silu_f(s1[2]), silu_f(s1[3])));
            }
        }
        __syncthreads();

        // ---- fused GEMM + epilogue over 8 m-tiles (2 receivers) ----
        float pa[2][2][4];
        #pragma unroll
        for (int nt = 0; nt < 2; ++nt)
            #pragma unroll
            for (int cp = 0; cp < 2; ++cp) {
                pa[nt][cp][0]=0.f; pa[nt][cp][1]=0.f; pa[nt][cp][2]=0.f; pa[nt][cp][3]=0.f;
            }
        const uint32_t* Bp = W2Tf + (widh*16 + r4)*8 + q4*2;

        #pragma unroll
        for (int mtS = 0; mtS < 8; ++mtS) {
            const int mt = mtS & 3;
            const int jh = mtS >> 2;
            const uint32_t* Am = Sf + mtS*128 + r4*8 + q4*2;

            float acc0[4] = {0.f, 0.f, 0.f, 0.f};
            float acc1[4] = {0.f, 0.f, 0.f, 0.f};
            #pragma unroll
            for (int kb = 0; kb < 8; ++kb) {
                uint2 Bv0 = *(const uint2*)(Bp + kb*1024);
                uint2 Bv1 = *(const uint2*)(Bp + kb*1024 + 64);
                uint2 A0  = *(const uint2*)(Am + kb*1024);
                uint2 A1  = *(const uint2*)(Am + kb*1024 + 64);
                mma_f16(acc0, A0.x, A1.x, A0.y, A1.y, Bv0.x, Bv0.y);
                mma_f16(acc1, A0.x, A1.x, A0.y, A1.y, Bv1.x, Bv1.y);
            }

            const float4* uj = (const float4*)u4f + (rr*2 + jh)*Nn;
            #pragma unroll
            for (int rg = 0; rg < 2; ++rg) {
                int i = mt*16 + r4 + rg*8;
                float4 uv = uj[i];
                float2 h0 = hreg[mt][rg][0];
                float2 h1 = hreg[mt][rg][1];
                #pragma unroll
                for (int cp = 0; cp < 2; ++cp) {
                    float m0 = acc0[rg*2+cp] * (cp ? h0.y : h0.x);
                    pa[0][cp][0] += m0;
                    pa[0][cp][1] = fmaf(m0, uv.x, pa[0][cp][1]);
                    pa[0][cp][2] = fmaf(m0, uv.y, pa[0][cp][2]);
                    pa[0][cp][3] = fmaf(m0, uv.z, pa[0][cp][3]);
                    float m1 = acc1[rg*2+cp] * (cp ? h1.y : h1.x);
                    pa[1][cp][0] += m1;
                    pa[1][cp][1] = fmaf(m1, uv.x, pa[1][cp][1]);
                    pa[1][cp][2] = fmaf(m1, uv.y, pa[1][cp][2]);
                    pa[1][cp][3] = fmaf(m1, uv.z, pa[1][cp][3]);
                }
            }

            if (mt == 3) {
                // finalize receiver j = jg*4 + rr*2 + jh
                #pragma unroll
                for (int nt = 0; nt < 2; ++nt)
                    #pragma unroll
                    for (int cp = 0; cp < 2; ++cp)
                        #pragma unroll
                        for (int q = 0; q < 4; ++q) {
                            float v = pa[nt][cp][q];
                            v += __shfl_xor_sync(0xffffffffu, v, 4);
                            v += __shfl_xor_sync(0xffffffffu, v, 8);
                            v += __shfl_xor_sync(0xffffffffu, v, 16);
                            pa[nt][cp][q] = v;
                        }
                if (lane < 4) {
                    const int nidx = b*Nn + jg*4 + rr*2 + jh;
                    #pragma unroll
                    for (int nt = 0; nt < 2; ++nt)
                        #pragma unroll
                        for (int cp = 0; cp < 2; ++cp) {
                            int c = widh*16 + nt*8 + lane*2 + cp;
                            g_a0[nidx*Hh + c]         = pa[nt][cp][0] * s63;
                            g_a1[(nidx*3+0)*Hh + c]   = pa[nt][cp][1] * s63;
                            g_a1[(nidx*3+1)*Hh + c]   = pa[nt][cp][2] * s63;
                            g_a1[(nidx*3+2)*Hh + c]   = pa[nt][cp][3] * s63;
                        }
                }
                #pragma unroll
                for (int nt = 0; nt < 2; ++nt)
                    #pragma unroll
                    for (int cp = 0; cp < 2; ++cp) {
                        pa[nt][cp][0]=0.f; pa[nt][cp][1]=0.f; pa[nt][cp][2]=0.f; pa[nt][cp][3]=0.f;
                    }
            }
        }
        __syncthreads();   // guard S overwrite next round
    }
}

// ---------------- K3: tensorized update ----------------------------------
// h += a0 @ Wupd ; v += a1_d @ Wmix  as 4 GEMMs [16x128]@[128x128]
#define UPD_A    0        // 4096 words: A frags [kb8][mt4][r16][8w]
#define UPD_WU   4096     // 8192 words
#define UPD_WM   12288    // 8192 words
#define UPD_WORDS 20480   // 81920 bytes

__global__ __launch_bounds__(256, 1)
void upd_kernel(int layer) {
    extern __shared__ uint32_t usm[];
    uint32_t* A_s  = usm + UPD_A;
    uint32_t* Wu_s = usm + UPD_WU;
    uint32_t* Wm_s = usm + UPD_WM;

    const int n0  = blockIdx.x * 16;
    const int tid = threadIdx.x;

    for (int idx = tid; idx < 8192; idx += 256) {
        Wu_s[idx] = g_WuH[layer*8192 + idx];
        Wm_s[idx] = g_WmH[layer*8192 + idx];
    }
    for (int idx = tid; idx < 4096; idx += 256) {
        int w  = idx & 7;
        int r  = (idx >> 3) & 15;
        int mt = (idx >> 7) & 3;
        int kb = idx >> 9;
        int k  = kb*16 + ((w >> 1) & 3)*2 + (w & 1)*8;
        const float* src = (mt == 0)
            ? (g_a0 + (size_t)(n0 + r)*Hh + k)
            : (g_a1 + ((size_t)(n0 + r)*3 + (mt - 1))*Hh + k);
        float2 v = *(const float2*)src;
        A_s[idx] = pack_h2(v.x, v.y);
    }
    __syncthreads();

    const int lane = tid & 31;
    const int widh = tid >> 5;
    const int r4 = lane >> 2, q4 = lane & 3;
    const uint32_t* Ap = A_s + r4*8 + q4*2;

    #pragma unroll
    for (int mt = 0; mt < 4; ++mt) {
        const uint32_t* Bp = ((mt == 0) ? Wu_s : Wm_s) + (widh*16 + r4)*8 + q4*2;
        float acc0[4] = {0.f, 0.f, 0.f, 0.f};
        float acc1[4] = {0.f, 0.f, 0.f, 0.f};
        #pragma unroll
        for (int kb = 0; kb < 8; ++kb) {
            uint2 Bv0 = *(const uint2*)(Bp + kb*1024);
            uint2 Bv1 = *(const uint2*)(Bp + kb*1024 + 64);
            uint2 A0  = *(const uint2*)(Ap + kb*512 + mt*128);
            uint2 A1  = *(const uint2*)(Ap + kb*512 + mt*128 + 64);
            mma_f16(acc0, A0.x, A1.x, A0.y, A1.y, Bv0.x, Bv0.y);
            mma_f16(acc1, A0.x, A1.x, A0.y, A1.y, Bv1.x, Bv1.y);
        }
        #pragma unroll
        for (int rg = 0; rg < 2; ++rg) {
            int n = n0 + r4 + rg*8;
            #pragma unroll
            for (int nt = 0; nt < 2; ++nt) {
                int c = widh*16 + nt*8 + q4*2;
                float* dst = (mt == 0) ? (g_h + (size_t)n*Hh + c)
                                       : (g_v + ((size_t)n*3 + (mt - 1))*Hh + c);
                const float* a = nt ? acc1 : acc0;
                float2 old = *(float2*)dst;
                old.x += a[rg*2 + 0];
                old.y += a[rg*2 + 1];
                *(float2*)dst = old;
            }
        }
    }
}

// ---------------- K4: gated readout (16 nodes/CTA, staged weights) --------
#define RP 20
__global__ __launch_bounds__(512, 1)
void readout_kernel(const float* __restrict__ Wg1,
                    const float* __restrict__ Wg2,
                    const float* __restrict__ fsp,
                    float* __restrict__ out) {
    extern __shared__ float rsm[];
    float* W1_s = rsm;                       // 16384
    float* W2_s = W1_s + Hh*Hh;              // 16384
    float* hT   = W2_s + Hh*Hh;              // 128*RP
    float* tT   = hT + Hh*RP;                // 128*RP
    __shared__ float red[16][12];

    const int n0  = blockIdx.x * 16;
    const int tid = threadIdx.x;
    for (int idx = tid; idx < Hh*Hh; idx += 512) { W1_s[idx] = Wg1[idx]; W2_s[idx] = Wg2[idx]; }
    for (int idx = tid; idx < 16*Hh; idx += 512) {
        int n = idx >> 7, g = idx & 127;
        hT[g*RP + n] = g_h[n0*Hh + idx];
    }
    __syncthreads();

    const int c  = tid & 127;
    const int qt = tid >> 7;

    float t[4] = {0.f, 0.f, 0.f, 0.f};
    #pragma unroll 2
    for (int g = 0; g < Hh; ++g) {
        float w = W1_s[g*Hh + c];
        float4 hv = *(const float4*)(hT + g*RP + qt*4);
        t[0] = fmaf(hv.x, w, t[0]);
        t[1] = fmaf(hv.y, w, t[1]);
        t[2] = fmaf(hv.z, w, t[2]);
        t[3] = fmaf(hv.w, w, t[3]);
    }
    #pragma unroll
    for (int m = 0; m < 4; ++m) tT[c*RP + qt*4 + m] = silu_f(t[m]);
    __syncthreads();

    float gg[4] = {0.f, 0.f, 0.f, 0.f};
    #pragma unroll 2
    for (int k = 0; k < Hh; ++k) {
        float w = W2_s[k*Hh + c];
        float4 tv = *(const float4*)(tT + k*RP + qt*4);
        gg[0] = fmaf(tv.x, w, gg[0]);
        gg[1] = fmaf(tv.y, w, gg[1]);
        gg[2] = fmaf(tv.z, w, gg[2]);
        gg[3] = fmaf(tv.w, w, gg[3]);
    }

    float p[4][3];
    #pragma unroll
    for (int m = 0; m < 4; ++m) {
        int n = n0 + qt*4 + m;
        p[m][0] = g_v[(n*3 + 0)*Hh + c] * gg[m];
        p[m][1] = g_v[(n*3 + 1)*Hh + c] * gg[m];
        p[m][2] = g_v[(n*3 + 2)*Hh + c] * gg[m];
    }
    #pragma unroll
    for (int m = 0; m < 4; ++m)
        #pragma unroll
        for (int d = 0; d < 3; ++d) {
            float v = p[m][d];
            #pragma unroll
            for (int off = 16; off; off >>= 1) v += __shfl_xor_sync(0xffffffffu, v, off);
            p[m][d] = v;
        }
    const int lane = tid & 31, warp = tid >> 5;
    if (lane == 0) {
        #pragma unroll
        for (int m = 0; m < 4; ++m)
            #pragma unroll
            for (int d = 0; d < 3; ++d) red[warp][m*3 + d] = p[m][d];
    }
    __syncthreads();
    if (tid < 48) {
        const int qtg = tid / 12, rem = tid % 12;
        float s = red[qtg*4 + 0][rem] + red[qtg*4 + 1][rem]
                + red[qtg*4 + 2][rem] + red[qtg*4 + 3][rem];
        out[(n0 + qtg*4 + rem/3)*3 + (rem % 3)] = s * fsp[0];
    }
}

// ---------------- launch ---------------------------------------------------
extern "C" void kernel_launch(void* const* d_in, const int* in_sizes, int n_in,
                              void* d_out, int out_size) {
    const float* positions = (const float*)d_in[0];
    const int*   nodef     = (const int*)  d_in[1];
    const float* gf        = (const float*)d_in[2];
    const float* emb       = (const float*)d_in[3];
    const float* Wt        = (const float*)d_in[4];
    const float* Wr1       = (const float*)d_in[5];
    const float* Wr2       = (const float*)d_in[6];
    const float* Wupd      = (const float*)d_in[7];
    const float* Wmix      = (const float*)d_in[8];
    const float* Wg1       = (const float*)d_in[9];
    const float* Wg2       = (const float*)d_in[10];
    const float* fs        = (const float*)d_in[11];
    float*       out       = (float*)d_out;

    const int msg_smem = MSG_WORDS * 4;
    const int upd_smem = UPD_WORDS * 4;
    const int rdo_smem = (Hh*Hh*2 + Hh*RP*2) * 4;
    cudaFuncSetAttribute(msg_kernel,     cudaFuncAttributeMaxDynamicSharedMemorySize, msg_smem);
    cudaFuncSetAttribute(upd_kernel,     cudaFuncAttributeMaxDynamicSharedMemorySize, upd_smem);
    cudaFuncSetAttribute(readout_kernel, cudaFuncAttributeMaxDynamicSharedMemorySize, rdo_smem);

    probe_kernel<<<1, 1>>>(nodef);
    init_kernel<<<Bb*Nn/16, 512>>>(nodef, gf, emb, Wt);
    {
        dim3 wgrid(Ll, 3);
        wfrag_kernel<<<wgrid, 256>>>(Wr2, Wupd, Wmix);
    }

    for (int l = 0; l < Ll; ++l) {
        dim3 grid(16, Bb);
        msg_kernel<<<grid, 256, msg_smem>>>(positions, Wr1 + l*NBb*Hh, l);
        upd_kernel<<<Bb*Nn/16, 256, upd_smem>>>(l);
    }
    readout_kernel<<<Bb*Nn/16, 512, rdo_smem>>>(Wg1, Wg2, fs, out);
}

// round 12
// speedup vs baseline: 6.6871x; 1.0808x over previous
#include <cuda_runtime.h>
#include <cuda_fp16.h>
#include <math.h>
#include <stdint.h>

// Problem constants
#define Bb   64
#define Nn   64
#define Hh   128
#define NBb  8
#define Tt   32
#define Ll   2

// ---------------- device scratch (no allocations allowed) ----------------
__device__ float    g_h   [Bb*Nn*Hh];      // node scalar features
__device__ float    g_v   [Bb*Nn*3*Hh];    // vector features SoA [n][d][c]
__device__ float    g_a0  [Bb*Nn*Hh];      // scalar aggregates
__device__ float    g_a1  [Bb*Nn*3*Hh];    // vector aggregates SoA [n][d][c]
__device__ uint32_t g_Wr2H[Ll*8192];       // Wr2^T fp16 B-frags [kb8][c128][8w]
__device__ uint32_t g_WuH [Ll*8192];       // Wupd^T fp16 B-frags
__device__ uint32_t g_WmH [Ll*8192];       // Wmix^T fp16 B-frags
__device__ int      g_z64;                 // species dtype flag

// ---------------- helpers -------------------------------------------------
__device__ __forceinline__ void mma_f16(float* c,
                                        uint32_t a0, uint32_t a1, uint32_t a2, uint32_t a3,
                                        uint32_t b0, uint32_t b1) {
    asm volatile(
        "mma.sync.aligned.m16n8k16.row.col.f32.f16.f16.f32 "
        "{%0,%1,%2,%3},{%4,%5,%6,%7},{%8,%9},{%0,%1,%2,%3};"
        : "+f"(c[0]), "+f"(c[1]), "+f"(c[2]), "+f"(c[3])
        : "r"(a0), "r"(a1), "r"(a2), "r"(a3), "r"(b0), "r"(b1));
}
__device__ __forceinline__ float silu_f(float x) {
    return __fdividef(x, 1.0f + __expf(-x));
}
__device__ __forceinline__ uint32_t pack_h2(float lo, float hi) {
    __half2 h = __floats2half2_rn(lo, hi);
    return *(uint32_t*)&h;
}

// ---------------- K0: probe node_features dtype -------------------------
__global__ void probe_kernel(const int* __restrict__ z) {
    int nz = 0;
    for (int t = 0; t < 64; ++t) nz |= z[2*t + 1];
    g_z64 = (nz == 0) ? 1 : 0;
}

// ---------------- K1: h = emb[z] + t @ Wt ; v = 0  (16 nodes/CTA) --------
__global__ __launch_bounds__(512, 1)
void init_kernel(const int* __restrict__ z,
                 const float* __restrict__ gf,
                 const float* __restrict__ emb,
                 const float* __restrict__ Wt) {
    const int n0 = blockIdx.x * 16;
    const int b  = n0 >> 6;
    const int c  = threadIdx.x & 127;
    const int qt = threadIdx.x >> 7;
    float tw = 0.f;
    const float* g = gf + b*Tt;
    #pragma unroll
    for (int t = 0; t < Tt; ++t) tw += g[t] * Wt[t*Hh + c];
    #pragma unroll
    for (int m = 0; m < 4; ++m) {
        const int n  = n0 + qt*4 + m;
        const int zi = g_z64 ? z[2*n] : z[n];
        g_h[n*Hh + c] = emb[zi*Hh + c] + tw;
        g_v[(n*3 + 0)*Hh + c] = 0.f;
        g_v[(n*3 + 1)*Hh + c] = 0.f;
        g_v[(n*3 + 2)*Hh + c] = 0.f;
    }
}

// ---------------- K1b: weight -> fp16 B-fragment layout -------------------
__global__ void wfrag_kernel(const float* __restrict__ Wr2,
                             const float* __restrict__ Wupd,
                             const float* __restrict__ Wmix) {
    const int l = blockIdx.x;   // layer
    const int a = blockIdx.y;   // which array
    const float* src = (a == 0) ? Wr2 : (a == 1) ? Wupd : Wmix;
    uint32_t*    dst = (a == 0) ? g_Wr2H : (a == 1) ? g_WuH : g_WmH;
    src += l*Hh*Hh;
    dst += l*8192;
    for (int idx = threadIdx.x; idx < 8192; idx += 256) {
        int c  = idx >> 6, kp = idx & 63;
        int k  = kp * 2;
        int kb = k >> 4;
        int kw = k & 15;
        int q  = (kw >> 1) & 3;
        int hi = kw >> 3;
        dst[(kb*128 + c)*8 + q*2 + hi] = pack_h2(src[k*Hh + c], src[(k+1)*Hh + c]);
    }
}

// ---------------- smem word offsets for msg kernel ------------------------
#define OFF_W2T  0          // 8192 words: fp16 B frags [kb8][c128][8w]
#define OFF_S    8192       // 8192:  fp16 A frags 2 receivers [kb8][mtS8][r16][8w]
#define OFF_RBF  16384      // 1024:  fp16 rb [jl4][i64][4w]
#define OFF_U4F  17408      // 1024:  [jl4][i64] float4
#define MSG_WORDS 18432     // 73728 bytes -> 3 CTAs/SM

// ---------------- K2: message pass (fp16 tensor GEMM, 3 CTAs/SM) ----------
// CTA = (4 receivers jg, batch b), 256 threads = 8 warps, 2 receivers/round.
// GEMM is kb-outer: B fragments loaded ONCE per kb (was 8x redundant).
__global__ __launch_bounds__(256, 3)
void msg_kernel(const float* __restrict__ pos,
                const float* __restrict__ Wr1,
                int layer) {
    extern __shared__ float smf[];
    uint32_t* W2Tf = (uint32_t*)smf + OFF_W2T;
    uint32_t* Sf   = (uint32_t*)smf + OFF_S;
    uint32_t* rbf  = (uint32_t*)smf + OFF_RBF;
    float*    u4f  = smf + OFF_U4F;

    const int b    = blockIdx.y;
    const int jg   = blockIdx.x;            // 0..15
    const int tid  = threadIdx.x;
    const int lane = tid & 31;
    const int widh = tid >> 5;              // 0..7
    const int r4   = lane >> 2;             // 0..7
    const int q4   = lane & 3;              // 0..3

    // ---- stage W2T fp16 fragments (direct copy) ----
    for (int idx = tid; idx < 8192; idx += 256) W2Tf[idx] = g_Wr2H[layer*8192 + idx];

    // ---- register-cache h (fixed across receivers): 8 rows x 2 float2 ----
    float2 hreg[4][2][2];
    {
        const float* hb = g_h + (size_t)b*Nn*Hh;
        #pragma unroll
        for (int mt = 0; mt < 4; ++mt)
            #pragma unroll
            for (int rg = 0; rg < 2; ++rg) {
                int i = mt*16 + r4 + rg*8;
                #pragma unroll
                for (int nt = 0; nt < 2; ++nt) {
                    int c = widh*16 + nt*8 + q4*2;
                    hreg[mt][rg][nt] = *(const float2*)(hb + i*Hh + c);
                }
            }
    }

    // ---- Wr1 fp16 B-frags in registers (b0 only; k8-15 are zero) ----
    uint32_t wbA, wbB;
    {
        int cA = widh*16 + r4;
        int cB = cA + 8;
        wbA = pack_h2(Wr1[(q4*2)*Hh + cA], Wr1[(q4*2+1)*Hh + cA]);
        wbB = pack_h2(Wr1[(q4*2)*Hh + cB], Wr1[(q4*2+1)*Hh + cB]);
    }

    const float PI5 = 0.62831853071795864769f;   // pi/5
    const float s63 = 1.0f / 63.0f;

    // ---- geometry + bessel for all 4 receivers (256 = 4j x 64i) ----
    {
        const int jl = tid >> 6;             // 0..3
        const int i  = tid & 63;
        const int j  = jg*4 + jl;
        const float* pb = pos + b*Nn*3;
        float dx = pb[j*3+0] - pb[i*3+0];
        float dy = pb[j*3+1] - pb[i*3+1];
        float dz = pb[j*3+2] - pb[i*3+2];
        float r2 = dx*dx + dy*dy + dz*dz + 1e-12f;
        float r  = sqrtf(r2);
        float inv = 1.0f / r;
        ((float4*)u4f)[jl*Nn + i] = make_float4(dx*inv, dy*inv, dz*inv, 0.f);
        float fc = 0.0f;
        if (r < 5.0f && i != j) fc = 0.5f * (cosf(PI5 * r) + 1.0f);
        float sc  = inv * fc;
        float arg = PI5 * r;
        float rv[8];
        #pragma unroll
        for (int q = 0; q < NBb; ++q) rv[q] = sinf((float)(q+1) * arg) * sc;
        uint4 rw;
        rw.x = pack_h2(rv[0], rv[1]);
        rw.y = pack_h2(rv[2], rv[3]);
        rw.z = pack_h2(rv[4], rv[5]);
        rw.w = pack_h2(rv[6], rv[7]);
        ((uint4*)rbf)[jl*Nn + i] = rw;
    }
    __syncthreads();

    for (int rr = 0; rr < 2; ++rr) {
        // ---- S = silu(rb @ Wr1) for receivers rr*2, rr*2+1 (fp16 MMA, K=8) ----
        #pragma unroll
        for (int jh = 0; jh < 2; ++jh) {
            const uint32_t* rbj = rbf + (rr*2 + jh)*Nn*4;
            #pragma unroll
            for (int mt = 0; mt < 4; ++mt) {
                int r0 = mt*16 + r4;
                uint32_t A0 = rbj[r0*4 + q4];
                uint32_t A1 = rbj[(r0+8)*4 + q4];
                float s0[4] = {0.f, 0.f, 0.f, 0.f};
                float s1[4] = {0.f, 0.f, 0.f, 0.f};
                mma_f16(s0, A0, A1, 0u, 0u, wbA, 0u);
                mma_f16(s1, A0, A1, 0u, 0u, wbB, 0u);
                const int mtS = jh*4 + mt;
                uint32_t* Sb = Sf + (widh*8 + mtS)*128 + r4*8 + q4*2;
                *(uint2*)(Sb)      = make_uint2(pack_h2(silu_f(s0[0]), silu_f(s0[1])),
                                                pack_h2(silu_f(s1[0]), silu_f(s1[1])));
                *(uint2*)(Sb + 64) = make_uint2(pack_h2(silu_f(s0[2]), silu_f(s0[3])),
                                                pack_h2(silu_f(s1[2]), silu_f(s1[3])));
            }
        }
        __syncthreads();

        // ---- per receiver: kb-outer GEMM (B loaded once/kb) + epilogue ----
        #pragma unroll
        for (int jh = 0; jh < 2; ++jh) {
            float acc[4][2][4];
            #pragma unroll
            for (int mt = 0; mt < 4; ++mt)
                #pragma unroll
                for (int nt = 0; nt < 2; ++nt) {
                    acc[mt][nt][0]=0.f; acc[mt][nt][1]=0.f; acc[mt][nt][2]=0.f; acc[mt][nt][3]=0.f;
                }
            const uint32_t* Bp = W2Tf + (widh*16 + r4)*8 + q4*2;
            const uint32_t* Am0 = Sf + jh*4*128 + r4*8 + q4*2;

            #pragma unroll
            for (int kb = 0; kb < 8; ++kb) {
                uint2 Bv0 = *(const uint2*)(Bp + kb*1024);
                uint2 Bv1 = *(const uint2*)(Bp + kb*1024 + 64);
                #pragma unroll
                for (int mt = 0; mt < 4; ++mt) {
                    const uint32_t* Am = Am0 + kb*1024 + mt*128;
                    uint2 A0 = *(const uint2*)(Am);
                    uint2 A1 = *(const uint2*)(Am + 64);
                    mma_f16(acc[mt][0], A0.x, A1.x, A0.y, A1.y, Bv0.x, Bv0.y);
                    mma_f16(acc[mt][1], A0.x, A1.x, A0.y, A1.y, Bv1.x, Bv1.y);
                }
            }

            // ---- epilogue: multiply by h, u; reduce over rows ----
            float pa[2][2][4];
            #pragma unroll
            for (int nt = 0; nt < 2; ++nt)
                #pragma unroll
                for (int cp = 0; cp < 2; ++cp) {
                    pa[nt][cp][0]=0.f; pa[nt][cp][1]=0.f; pa[nt][cp][2]=0.f; pa[nt][cp][3]=0.f;
                }
            const float4* uj = (const float4*)u4f + (rr*2 + jh)*Nn;
            #pragma unroll
            for (int mt = 0; mt < 4; ++mt) {
                #pragma unroll
                for (int rg = 0; rg < 2; ++rg) {
                    int i = mt*16 + r4 + rg*8;
                    float4 uv = uj[i];
                    float2 h0 = hreg[mt][rg][0];
                    float2 h1 = hreg[mt][rg][1];
                    #pragma unroll
                    for (int cp = 0; cp < 2; ++cp) {
                        float m0 = acc[mt][0][rg*2+cp] * (cp ? h0.y : h0.x);
                        pa[0][cp][0] += m0;
                        pa[0][cp][1] = fmaf(m0, uv.x, pa[0][cp][1]);
                        pa[0][cp][2] = fmaf(m0, uv.y, pa[0][cp][2]);
                        pa[0][cp][3] = fmaf(m0, uv.z, pa[0][cp][3]);
                        float m1 = acc[mt][1][rg*2+cp] * (cp ? h1.y : h1.x);
                        pa[1][cp][0] += m1;
                        pa[1][cp][1] = fmaf(m1, uv.x, pa[1][cp][1]);
                        pa[1][cp][2] = fmaf(m1, uv.y, pa[1][cp][2]);
                        pa[1][cp][3] = fmaf(m1, uv.z, pa[1][cp][3]);
                    }
                }
            }
            #pragma unroll
            for (int nt = 0; nt < 2; ++nt)
                #pragma unroll
                for (int cp = 0; cp < 2; ++cp)
                    #pragma unroll
                    for (int q = 0; q < 4; ++q) {
                        float v = pa[nt][cp][q];
                        v += __shfl_xor_sync(0xffffffffu, v, 4);
                        v += __shfl_xor_sync(0xffffffffu, v, 8);
                        v += __shfl_xor_sync(0xffffffffu, v, 16);
                        pa[nt][cp][q] = v;
                    }
            if (lane < 4) {
                const int nidx = b*Nn + jg*4 + rr*2 + jh;
                #pragma unroll
                for (int nt = 0; nt < 2; ++nt)
                    #pragma unroll
                    for (int cp = 0; cp < 2; ++cp) {
                        int c = widh*16 + nt*8 + lane*2 + cp;
                        g_a0[nidx*Hh + c]         = pa[nt][cp][0] * s63;
                        g_a1[(nidx*3+0)*Hh + c]   = pa[nt][cp][1] * s63;
                        g_a1[(nidx*3+1)*Hh + c]   = pa[nt][cp][2] * s63;
                        g_a1[(nidx*3+2)*Hh + c]   = pa[nt][cp][3] * s63;
                    }
            }
        }
        __syncthreads();   // guard S overwrite next round
    }
}

// ---------------- K3: tensorized update ----------------------------------
#define UPD_A    0        // 4096 words: A frags [kb8][mt4][r16][8w]
#define UPD_WU   4096     // 8192 words
#define UPD_WM   12288    // 8192 words
#define UPD_WORDS 20480   // 81920 bytes

__global__ __launch_bounds__(256, 1)
void upd_kernel(int layer) {
    extern __shared__ uint32_t usm[];
    uint32_t* A_s  = usm + UPD_A;
    uint32_t* Wu_s = usm + UPD_WU;
    uint32_t* Wm_s = usm + UPD_WM;

    const int n0  = blockIdx.x * 16;
    const int tid = threadIdx.x;

    for (int idx = tid; idx < 8192; idx += 256) {
        Wu_s[idx] = g_WuH[layer*8192 + idx];
        Wm_s[idx] = g_WmH[layer*8192 + idx];
    }
    for (int idx = tid; idx < 4096; idx += 256) {
        int w  = idx & 7;
        int r  = (idx >> 3) & 15;
        int mt = (idx >> 7) & 3;
        int kb = idx >> 9;
        int k  = kb*16 + ((w >> 1) & 3)*2 + (w & 1)*8;
        const float* src = (mt == 0)
            ? (g_a0 + (size_t)(n0 + r)*Hh + k)
            : (g_a1 + ((size_t)(n0 + r)*3 + (mt - 1))*Hh + k);
        float2 v = *(const float2*)src;
        A_s[idx] = pack_h2(v.x, v.y);
    }
    __syncthreads();

    const int lane = tid & 31;
    const int widh = tid >> 5;
    const int r4 = lane >> 2, q4 = lane & 3;
    const uint32_t* Ap = A_s + r4*8 + q4*2;

    #pragma unroll
    for (int mt = 0; mt < 4; ++mt) {
        const uint32_t* Bp = ((mt == 0) ? Wu_s : Wm_s) + (widh*16 + r4)*8 + q4*2;
        float acc0[4] = {0.f, 0.f, 0.f, 0.f};
        float acc1[4] = {0.f, 0.f, 0.f, 0.f};
        #pragma unroll
        for (int kb = 0; kb < 8; ++kb) {
            uint2 Bv0 = *(const uint2*)(Bp + kb*1024);
            uint2 Bv1 = *(const uint2*)(Bp + kb*1024 + 64);
            uint2 A0  = *(const uint2*)(Ap + kb*512 + mt*128);
            uint2 A1  = *(const uint2*)(Ap + kb*512 + mt*128 + 64);
            mma_f16(acc0, A0.x, A1.x, A0.y, A1.y, Bv0.x, Bv0.y);
            mma_f16(acc1, A0.x, A1.x, A0.y, A1.y, Bv1.x, Bv1.y);
        }
        #pragma unroll
        for (int rg = 0; rg < 2; ++rg) {
            int n = n0 + r4 + rg*8;
            #pragma unroll
            for (int nt = 0; nt < 2; ++nt) {
                int c = widh*16 + nt*8 + q4*2;
                float* dst = (mt == 0) ? (g_h + (size_t)n*Hh + c)
                                       : (g_v + ((size_t)n*3 + (mt - 1))*Hh + c);
                const float* a = nt ? acc1 : acc0;
                float2 old = *(float2*)dst;
                old.x += a[rg*2 + 0];
                old.y += a[rg*2 + 1];
                *(float2*)dst = old;
            }
        }
    }
}

// ---------------- K4: gated readout (16 nodes/CTA, staged weights) --------
#define RP 20
__global__ __launch_bounds__(512, 1)
void readout_kernel(const float* __restrict__ Wg1,
                    const float* __restrict__ Wg2,
                    const float* __restrict__ fsp,
                    float* __restrict__ out) {
    extern __shared__ float rsm[];
    float* W1_s = rsm;                       // 16384
    float* W2_s = W1_s + Hh*Hh;              // 16384
    float* hT   = W2_s + Hh*Hh;              // 128*RP
    float* tT   = hT + Hh*RP;                // 128*RP
    __shared__ float red[16][12];

    const int n0  = blockIdx.x * 16;
    const int tid = threadIdx.x;
    for (int idx = tid; idx < Hh*Hh; idx += 512) { W1_s[idx] = Wg1[idx]; W2_s[idx] = Wg2[idx]; }
    for (int idx = tid; idx < 16*Hh; idx += 512) {
        int n = idx >> 7, g = idx & 127;
        hT[g*RP + n] = g_h[n0*Hh + idx];
    }
    __syncthreads();

    const int c  = tid & 127;
    const int qt = tid >> 7;

    float t[4] = {0.f, 0.f, 0.f, 0.f};
    #pragma unroll 2
    for (int g = 0; g < Hh; ++g) {
        float w = W1_s[g*Hh + c];
        float4 hv = *(const float4*)(hT + g*RP + qt*4);
        t[0] = fmaf(hv.x, w, t[0]);
        t[1] = fmaf(hv.y, w, t[1]);
        t[2] = fmaf(hv.z, w, t[2]);
        t[3] = fmaf(hv.w, w, t[3]);
    }
    #pragma unroll
    for (int m = 0; m < 4; ++m) tT[c*RP + qt*4 + m] = silu_f(t[m]);
    __syncthreads();

    float gg[4] = {0.f, 0.f, 0.f, 0.f};
    #pragma unroll 2
    for (int k = 0; k < Hh; ++k) {
        float w = W2_s[k*Hh + c];
        float4 tv = *(const float4*)(tT + k*RP + qt*4);
        gg[0] = fmaf(tv.x, w, gg[0]);
        gg[1] = fmaf(tv.y, w, gg[1]);
        gg[2] = fmaf(tv.z, w, gg[2]);
        gg[3] = fmaf(tv.w, w, gg[3]);
    }

    float p[4][3];
    #pragma unroll
    for (int m = 0; m < 4; ++m) {
        int n = n0 + qt*4 + m;
        p[m][0] = g_v[(n*3 + 0)*Hh + c] * gg[m];
        p[m][1] = g_v[(n*3 + 1)*Hh + c] * gg[m];
        p[m][2] = g_v[(n*3 + 2)*Hh + c] * gg[m];
    }
    #pragma unroll
    for (int m = 0; m < 4; ++m)
        #pragma unroll
        for (int d = 0; d < 3; ++d) {
            float v = p[m][d];
            #pragma unroll
            for (int off = 16; off; off >>= 1) v += __shfl_xor_sync(0xffffffffu, v, off);
            p[m][d] = v;
        }
    const int lane = tid & 31, warp = tid >> 5;
    if (lane == 0) {
        #pragma unroll
        for (int m = 0; m < 4; ++m)
            #pragma unroll
            for (int d = 0; d < 3; ++d) red[warp][m*3 + d] = p[m][d];
    }
    __syncthreads();
    if (tid < 48) {
        const int qtg = tid / 12, rem = tid % 12;
        float s = red[qtg*4 + 0][rem] + red[qtg*4 + 1][rem]
                + red[qtg*4 + 2][rem] + red[qtg*4 + 3][rem];
        out[(n0 + qtg*4 + rem/3)*3 + (rem % 3)] = s * fsp[0];
    }
}

// ---------------- launch ---------------------------------------------------
extern "C" void kernel_launch(void* const* d_in, const int* in_sizes, int n_in,
                              void* d_out, int out_size) {
    const float* positions = (const float*)d_in[0];
    const int*   nodef     = (const int*)  d_in[1];
    const float* gf        = (const float*)d_in[2];
    const float* emb       = (const float*)d_in[3];
    const float* Wt        = (const float*)d_in[4];
    const float* Wr1       = (const float*)d_in[5];
    const float* Wr2       = (const float*)d_in[6];
    const float* Wupd      = (const float*)d_in[7];
    const float* Wmix      = (const float*)d_in[8];
    const float* Wg1       = (const float*)d_in[9];
    const float* Wg2       = (const float*)d_in[10];
    const float* fs        = (const float*)d_in[11];
    float*       out       = (float*)d_out;

    const int msg_smem = MSG_WORDS * 4;
    const int upd_smem = UPD_WORDS * 4;
    const int rdo_smem = (Hh*Hh*2 + Hh*RP*2) * 4;
    cudaFuncSetAttribute(msg_kernel,     cudaFuncAttributeMaxDynamicSharedMemorySize, msg_smem);
    cudaFuncSetAttribute(upd_kernel,     cudaFuncAttributeMaxDynamicSharedMemorySize, upd_smem);
    cudaFuncSetAttribute(readout_kernel, cudaFuncAttributeMaxDynamicSharedMemorySize, rdo_smem);

    probe_kernel<<<1, 1>>>(nodef);
    init_kernel<<<Bb*Nn/16, 512>>>(nodef, gf, emb, Wt);
    {
        dim3 wgrid(Ll, 3);
        wfrag_kernel<<<wgrid, 256>>>(Wr2, Wupd, Wmix);
    }

    for (int l = 0; l < Ll; ++l) {
        dim3 grid(16, Bb);
        msg_kernel<<<grid, 256, msg_smem>>>(positions, Wr1 + l*NBb*Hh, l);
        upd_kernel<<<Bb*Nn/16, 256, upd_smem>>>(l);
    }
    readout_kernel<<<Bb*Nn/16, 512, rdo_smem>>>(Wg1, Wg2, fs, out);
}

// round 13
// speedup vs baseline: 7.1736x; 1.0728x over previous
#include <cuda_runtime.h>
#include <cuda_fp16.h>
#include <math.h>
#include <stdint.h>

// Problem constants
#define Bb   64
#define Nn   64
#define Hh   128
#define NBb  8
#define Tt   32
#define Ll   2

// ---------------- device scratch (no allocations allowed) ----------------
__device__ float    g_h   [Bb*Nn*Hh];      // node scalar features
__device__ float    g_v   [Bb*Nn*3*Hh];    // vector features SoA [n][d][c]
__device__ uint32_t g_aF  [Bb*16*1024];    // aggregates, fp16 A-frag layout per (b,jg)
__device__ uint32_t g_Wr2H[Ll*8192];       // Wr2^T fp16 B-frags [kb8][c128][8w]
__device__ uint32_t g_WuH [Ll*8192];       // Wupd^T fp16 B-frags
__device__ uint32_t g_WmH [Ll*8192];       // Wmix^T fp16 B-frags

// ---------------- helpers -------------------------------------------------
__device__ __forceinline__ void mma_f16(float* c,
                                        uint32_t a0, uint32_t a1, uint32_t a2, uint32_t a3,
                                        uint32_t b0, uint32_t b1) {
    asm volatile(
        "mma.sync.aligned.m16n8k16.row.col.f32.f16.f16.f32 "
        "{%0,%1,%2,%3},{%4,%5,%6,%7},{%8,%9},{%0,%1,%2,%3};"
        : "+f"(c[0]), "+f"(c[1]), "+f"(c[2]), "+f"(c[3])
        : "r"(a0), "r"(a1), "r"(a2), "r"(a3), "r"(b0), "r"(b1));
}
__device__ __forceinline__ float tanh_approx(float x) {
    float r;
    asm("tanh.approx.f32 %0, %1;" : "=f"(r) : "f"(x));
    return r;
}
// silu(x) = 0.5x + 0.5x * tanh(0.5x)
__device__ __forceinline__ float silu_f(float x) {
    float s = 0.5f * x;
    return fmaf(s, tanh_approx(s), s);
}
__device__ __forceinline__ uint32_t pack_h2(float lo, float hi) {
    __half2 h = __floats2half2_rn(lo, hi);
    return *(uint32_t*)&h;
}

// ---------------- K1: fused setup (z-probe + init + weight frags) ---------
// blocks 0..511: init 8 nodes each; blocks 512..517: weight frag conversion
__global__ __launch_bounds__(256, 2)
void setup_kernel(const int* __restrict__ z,
                  const float* __restrict__ gf,
                  const float* __restrict__ emb,
                  const float* __restrict__ Wt,
                  const float* __restrict__ Wr2,
                  const float* __restrict__ Wupd,
                  const float* __restrict__ Wmix) {
    const int blk = blockIdx.x;
    const int tid = threadIdx.x;
    if (blk < 512) {
        // ---- init: h = emb[z] + t @ Wt ; v = 0 ----
        // per-block int64-vs-int32 probe (values 0..4 -> odd words zero if i64)
        int t32 = tid & 31;
        int v = z[2*t32 + 1] | z[2*(t32 + 32) + 1];
        int nz = __reduce_or_sync(0xffffffffu, v);
        const int z64 = (nz == 0);
        const int n0 = blk * 8;
        const int b  = n0 >> 6;
        const int c  = tid & 127;
        const int qt = tid >> 7;
        float tw = 0.f;
        const float* g = gf + b*Tt;
        #pragma unroll
        for (int t = 0; t < Tt; ++t) tw += g[t] * Wt[t*Hh + c];
        #pragma unroll
        for (int m = 0; m < 4; ++m) {
            const int n  = n0 + qt*4 + m;
            const int zi = z64 ? z[2*n] : z[n];
            g_h[n*Hh + c] = emb[zi*Hh + c] + tw;
            g_v[(n*3 + 0)*Hh + c] = 0.f;
            g_v[(n*3 + 1)*Hh + c] = 0.f;
            g_v[(n*3 + 2)*Hh + c] = 0.f;
        }
    } else {
        // ---- weight -> fp16 B-fragment layout ----
        const int b2 = blk - 512;
        const int a  = b2 / Ll;
        const int l  = b2 % Ll;
        const float* src = (a == 0) ? Wr2 : (a == 1) ? Wupd : Wmix;
        uint32_t*    dst = (a == 0) ? g_Wr2H : (a == 1) ? g_WuH : g_WmH;
        src += l*Hh*Hh;
        dst += l*8192;
        for (int idx = tid; idx < 8192; idx += 256) {
            int c  = idx >> 6, kp = idx & 63;
            int k  = kp * 2;
            int kb = k >> 4;
            int kw = k & 15;
            int q  = (kw >> 1) & 3;
            int hi = kw >> 3;
            dst[(kb*128 + c)*8 + q*2 + hi] = pack_h2(src[k*Hh + c], src[(k+1)*Hh + c]);
        }
    }
}

// ---------------- smem word offsets for msg kernel ------------------------
#define OFF_W2T  0          // 8192 words: fp16 B frags [kb8][c128][8w]
#define OFF_S    8192       // 8192:  fp16 A frags 2 receivers [kb8][mtS8][r16][8w]
#define OFF_RBF  16384      // 1024:  fp16 rb [jl4][i64][4w]
#define OFF_U4F  17408      // 1024:  [jl4][i64] float4
#define MSG_WORDS 18432     // 73728 bytes -> 3 CTAs/SM

// ---------------- K2: message pass (fp16 tensor GEMM, 3 CTAs/SM) ----------
// CTA = (4 receivers jg, batch b), 256 threads = 8 warps, 2 receivers/round.
__global__ __launch_bounds__(256, 3)
void msg_kernel(const float* __restrict__ pos,
                const float* __restrict__ Wr1,
                int layer) {
    extern __shared__ float smf[];
    uint32_t* W2Tf = (uint32_t*)smf + OFF_W2T;
    uint32_t* Sf   = (uint32_t*)smf + OFF_S;
    uint32_t* rbf  = (uint32_t*)smf + OFF_RBF;
    float*    u4f  = smf + OFF_U4F;

    const int b    = blockIdx.y;
    const int jg   = blockIdx.x;            // 0..15
    const int tid  = threadIdx.x;
    const int lane = tid & 31;
    const int widh = tid >> 5;              // 0..7
    const int r4   = lane >> 2;             // 0..7
    const int q4   = lane & 3;              // 0..3

    // ---- stage W2T fp16 fragments (direct copy) ----
    for (int idx = tid; idx < 8192; idx += 256) W2Tf[idx] = g_Wr2H[layer*8192 + idx];

    // ---- register-cache h (fixed across receivers): 8 rows x 2 float2 ----
    float2 hreg[4][2][2];
    {
        const float* hb = g_h + (size_t)b*Nn*Hh;
        #pragma unroll
        for (int mt = 0; mt < 4; ++mt)
            #pragma unroll
            for (int rg = 0; rg < 2; ++rg) {
                int i = mt*16 + r4 + rg*8;
                #pragma unroll
                for (int nt = 0; nt < 2; ++nt) {
                    int c = widh*16 + nt*8 + q4*2;
                    hreg[mt][rg][nt] = *(const float2*)(hb + i*Hh + c);
                }
            }
    }

    // ---- Wr1 fp16 B-frags in registers (b0 only; k8-15 are zero) ----
    uint32_t wbA, wbB;
    {
        int cA = widh*16 + r4;
        int cB = cA + 8;
        wbA = pack_h2(Wr1[(q4*2)*Hh + cA], Wr1[(q4*2+1)*Hh + cA]);
        wbB = pack_h2(Wr1[(q4*2)*Hh + cB], Wr1[(q4*2+1)*Hh + cB]);
    }

    const float PI5 = 0.62831853071795864769f;   // pi/5
    const float s63 = 1.0f / 63.0f;

    // ---- geometry + bessel for all 4 receivers (256 = 4j x 64i) ----
    {
        const int jl = tid >> 6;             // 0..3
        const int i  = tid & 63;
        const int j  = jg*4 + jl;
        const float* pb = pos + b*Nn*3;
        float dx = pb[j*3+0] - pb[i*3+0];
        float dy = pb[j*3+1] - pb[i*3+1];
        float dz = pb[j*3+2] - pb[i*3+2];
        float r2 = dx*dx + dy*dy + dz*dz + 1e-12f;
        float r  = sqrtf(r2);
        float inv = 1.0f / r;
        ((float4*)u4f)[jl*Nn + i] = make_float4(dx*inv, dy*inv, dz*inv, 0.f);
        float fc = 0.0f;
        if (r < 5.0f && i != j) fc = 0.5f * (__cosf(PI5 * r) + 1.0f);
        float sc  = inv * fc;
        float arg = PI5 * r;
        float rv[8];
        #pragma unroll
        for (int q = 0; q < NBb; ++q) rv[q] = __sinf((float)(q+1) * arg) * sc;
        uint4 rw;
        rw.x = pack_h2(rv[0], rv[1]);
        rw.y = pack_h2(rv[2], rv[3]);
        rw.z = pack_h2(rv[4], rv[5]);
        rw.w = pack_h2(rv[6], rv[7]);
        ((uint4*)rbf)[jl*Nn + i] = rw;
    }
    __syncthreads();

    for (int rr = 0; rr < 2; ++rr) {
        // ---- S = silu(rb @ Wr1) for receivers rr*2, rr*2+1 (fp16 MMA, K=8) ----
        #pragma unroll
        for (int jh = 0; jh < 2; ++jh) {
            const uint32_t* rbj = rbf + (rr*2 + jh)*Nn*4;
            #pragma unroll
            for (int mt = 0; mt < 4; ++mt) {
                int r0 = mt*16 + r4;
                uint32_t A0 = rbj[r0*4 + q4];
                uint32_t A1 = rbj[(r0+8)*4 + q4];
                float s0[4] = {0.f, 0.f, 0.f, 0.f};
                float s1[4] = {0.f, 0.f, 0.f, 0.f};
                mma_f16(s0, A0, A1, 0u, 0u, wbA, 0u);
                mma_f16(s1, A0, A1, 0u, 0u, wbB, 0u);
                const int mtS = jh*4 + mt;
                uint32_t* Sb = Sf + (widh*8 + mtS)*128 + r4*8 + q4*2;
                *(uint2*)(Sb)      = make_uint2(pack_h2(silu_f(s0[0]), silu_f(s0[1])),
                                                pack_h2(silu_f(s1[0]), silu_f(s1[1])));
                *(uint2*)(Sb + 64) = make_uint2(pack_h2(silu_f(s0[2]), silu_f(s0[3])),
                                                pack_h2(silu_f(s1[2]), silu_f(s1[3])));
            }
        }
        __syncthreads();

        // ---- per receiver: kb-outer GEMM (B loaded once/kb) + epilogue ----
        #pragma unroll
        for (int jh = 0; jh < 2; ++jh) {
            float acc[4][2][4];
            #pragma unroll
            for (int mt = 0; mt < 4; ++mt)
                #pragma unroll
                for (int nt = 0; nt < 2; ++nt) {
                    acc[mt][nt][0]=0.f; acc[mt][nt][1]=0.f; acc[mt][nt][2]=0.f; acc[mt][nt][3]=0.f;
                }
            const uint32_t* Bp = W2Tf + (widh*16 + r4)*8 + q4*2;
            const uint32_t* Am0 = Sf + jh*4*128 + r4*8 + q4*2;

            #pragma unroll
            for (int kb = 0; kb < 8; ++kb) {
                uint2 Bv0 = *(const uint2*)(Bp + kb*1024);
                uint2 Bv1 = *(const uint2*)(Bp + kb*1024 + 64);
                #pragma unroll
                for (int mt = 0; mt < 4; ++mt) {
                    const uint32_t* Am = Am0 + kb*1024 + mt*128;
                    uint2 A0 = *(const uint2*)(Am);
                    uint2 A1 = *(const uint2*)(Am + 64);
                    mma_f16(acc[mt][0], A0.x, A1.x, A0.y, A1.y, Bv0.x, Bv0.y);
                    mma_f16(acc[mt][1], A0.x, A1.x, A0.y, A1.y, Bv1.x, Bv1.y);
                }
            }

            // ---- epilogue: multiply by h, u; reduce over rows ----
            float pa[2][2][4];
            #pragma unroll
            for (int nt = 0; nt < 2; ++nt)
                #pragma unroll
                for (int cp = 0; cp < 2; ++cp) {
                    pa[nt][cp][0]=0.f; pa[nt][cp][1]=0.f; pa[nt][cp][2]=0.f; pa[nt][cp][3]=0.f;
                }
            const float4* uj = (const float4*)u4f + (rr*2 + jh)*Nn;
            #pragma unroll
            for (int mt = 0; mt < 4; ++mt) {
                #pragma unroll
                for (int rg = 0; rg < 2; ++rg) {
                    int i = mt*16 + r4 + rg*8;
                    float4 uv = uj[i];
                    float2 h0 = hreg[mt][rg][0];
                    float2 h1 = hreg[mt][rg][1];
                    #pragma unroll
                    for (int cp = 0; cp < 2; ++cp) {
                        float m0 = acc[mt][0][rg*2+cp] * (cp ? h0.y : h0.x);
                        pa[0][cp][0] += m0;
                        pa[0][cp][1] = fmaf(m0, uv.x, pa[0][cp][1]);
                        pa[0][cp][2] = fmaf(m0, uv.y, pa[0][cp][2]);
                        pa[0][cp][3] = fmaf(m0, uv.z, pa[0][cp][3]);
                        float m1 = acc[mt][1][rg*2+cp] * (cp ? h1.y : h1.x);
                        pa[1][cp][0] += m1;
                        pa[1][cp][1] = fmaf(m1, uv.x, pa[1][cp][1]);
                        pa[1][cp][2] = fmaf(m1, uv.y, pa[1][cp][2]);
                        pa[1][cp][3] = fmaf(m1, uv.z, pa[1][cp][3]);
                    }
                }
            }
            #pragma unroll
            for (int nt = 0; nt < 2; ++nt)
                #pragma unroll
                for (int cp = 0; cp < 2; ++cp)
                    #pragma unroll
                    for (int q = 0; q < 4; ++q) {
                        float v = pa[nt][cp][q];
                        v += __shfl_xor_sync(0xffffffffu, v, 4);
                        v += __shfl_xor_sync(0xffffffffu, v, 8);
                        v += __shfl_xor_sync(0xffffffffu, v, 16);
                        pa[nt][cp][q] = v;
                    }
            // store aggregates directly in fp16 A-frag layout:
            // word = kb(=widh)*128 + (q*4 + node)*8 + lane*2 + nt
            if (lane < 4) {
                uint32_t* aF = g_aF + (b*16 + jg)*1024 + widh*128 + lane*2;
                const int node = rr*2 + jh;
                #pragma unroll
                for (int nt = 0; nt < 2; ++nt)
                    #pragma unroll
                    for (int q = 0; q < 4; ++q)
                        aF[(q*4 + node)*8 + nt] =
                            pack_h2(pa[nt][0][q]*s63, pa[nt][1][q]*s63);
            }
        }
        __syncthreads();   // guard S overwrite next round
    }
}

// ---------------- K3: tensorized update ----------------------------------
// h += a0 @ Wupd ; v += a1_d @ Wmix ; A-frags read directly from g_aF (L2).
#define UPD_WU   0        // 8192 words
#define UPD_WM   8192     // 8192 words
#define UPD_WORDS 16384   // 65536 bytes

__global__ __launch_bounds__(256, 2)
void upd_kernel(int layer) {
    extern __shared__ uint32_t usm[];
    uint32_t* Wu_s = usm + UPD_WU;
    uint32_t* Wm_s = usm + UPD_WM;

    const int n0  = blockIdx.x * 16;
    const int b   = n0 >> 6;
    const int jg0 = (n0 & 63) >> 2;        // first of 4 receiver groups
    const int tid = threadIdx.x;

    for (int idx = tid; idx < 8192; idx += 256) {
        Wu_s[idx] = g_WuH[layer*8192 + idx];
        Wm_s[idx] = g_WmH[layer*8192 + idx];
    }
    __syncthreads();

    const int lane = tid & 31;
    const int widh = tid >> 5;
    const int r4 = lane >> 2, q4 = lane & 3;

    // A rows r = 0..15: group = r>>2 (aF block), row-in-block = mt*4 + (r&3)
    const uint32_t* base = g_aF + (b*16 + jg0)*1024;
    const int g1  = r4 >> 2, nd1 = r4 & 3;

    #pragma unroll
    for (int mt = 0; mt < 4; ++mt) {
        const uint32_t* Bp = ((mt == 0) ? Wu_s : Wm_s) + (widh*16 + r4)*8 + q4*2;
        const uint32_t* Ap = base + g1*1024 + (mt*4 + nd1)*8 + q4*2;
        float acc0[4] = {0.f, 0.f, 0.f, 0.f};
        float acc1[4] = {0.f, 0.f, 0.f, 0.f};
        #pragma unroll
        for (int kb = 0; kb < 8; ++kb) {
            uint2 Bv0 = *(const uint2*)(Bp + kb*1024);
            uint2 Bv1 = *(const uint2*)(Bp + kb*1024 + 64);
            uint2 A0  = *(const uint2*)(Ap + kb*128);
            uint2 A1  = *(const uint2*)(Ap + kb*128 + 2048);   // rows r4+8 = +2 groups
            mma_f16(acc0, A0.x, A1.x, A0.y, A1.y, Bv0.x, Bv0.y);
            mma_f16(acc1, A0.x, A1.x, A0.y, A1.y, Bv1.x, Bv1.y);
        }
        #pragma unroll
        for (int rg = 0; rg < 2; ++rg) {
            int n = n0 + r4 + rg*8;
            #pragma unroll
            for (int nt = 0; nt < 2; ++nt) {
                int c = widh*16 + nt*8 + q4*2;
                float* dst = (mt == 0) ? (g_h + (size_t)n*Hh + c)
                                       : (g_v + ((size_t)n*3 + (mt - 1))*Hh + c);
                const float* a = nt ? acc1 : acc0;
                float2 old = *(float2*)dst;
                old.x += a[rg*2 + 0];
                old.y += a[rg*2 + 1];
                *(float2*)dst = old;
            }
        }
    }
}

// ---------------- K4: gated readout (16 nodes/CTA, staged weights) --------
#define RP 20
__global__ __launch_bounds__(512, 1)
void readout_kernel(const float* __restrict__ Wg1,
                    const float* __restrict__ Wg2,
                    const float* __restrict__ fsp,
                    float* __restrict__ out) {
    extern __shared__ float rsm[];
    float* W1_s = rsm;                       // 16384
    float* W2_s = W1_s + Hh*Hh;              // 16384
    float* hT   = W2_s + Hh*Hh;              // 128*RP
    float* tT   = hT + Hh*RP;                // 128*RP
    __shared__ float red[16][12];

    const int n0  = blockIdx.x * 16;
    const int tid = threadIdx.x;
    for (int idx = tid; idx < Hh*Hh; idx += 512) { W1_s[idx] = Wg1[idx]; W2_s[idx] = Wg2[idx]; }
    for (int idx = tid; idx < 16*Hh; idx += 512) {
        int n = idx >> 7, g = idx & 127;
        hT[g*RP + n] = g_h[n0*Hh + idx];
    }
    __syncthreads();

    const int c  = tid & 127;
    const int qt = tid >> 7;

    float t[4] = {0.f, 0.f, 0.f, 0.f};
    #pragma unroll 2
    for (int g = 0; g < Hh; ++g) {
        float w = W1_s[g*Hh + c];
        float4 hv = *(const float4*)(hT + g*RP + qt*4);
        t[0] = fmaf(hv.x, w, t[0]);
        t[1] = fmaf(hv.y, w, t[1]);
        t[2] = fmaf(hv.z, w, t[2]);
        t[3] = fmaf(hv.w, w, t[3]);
    }
    #pragma unroll
    for (int m = 0; m < 4; ++m) tT[c*RP + qt*4 + m] = silu_f(t[m]);
    __syncthreads();

    float gg[4] = {0.f, 0.f, 0.f, 0.f};
    #pragma unroll 2
    for (int k = 0; k < Hh; ++k) {
        float w = W2_s[k*Hh + c];
        float4 tv = *(const float4*)(tT + k*RP + qt*4);
        gg[0] = fmaf(tv.x, w, gg[0]);
        gg[1] = fmaf(tv.y, w, gg[1]);
        gg[2] = fmaf(tv.z, w, gg[2]);
        gg[3] = fmaf(tv.w, w, gg[3]);
    }

    float p[4][3];
    #pragma unroll
    for (int m = 0; m < 4; ++m) {
        int n = n0 + qt*4 + m;
        p[m][0] = g_v[(n*3 + 0)*Hh + c] * gg[m];
        p[m][1] = g_v[(n*3 + 1)*Hh + c] * gg[m];
        p[m][2] = g_v[(n*3 + 2)*Hh + c] * gg[m];
    }
    #pragma unroll
    for (int m = 0; m < 4; ++m)
        #pragma unroll
        for (int d = 0; d < 3; ++d) {
            float v = p[m][d];
            #pragma unroll
            for (int off = 16; off; off >>= 1) v += __shfl_xor_sync(0xffffffffu, v, off);
            p[m][d] = v;
        }
    const int lane = tid & 31, warp = tid >> 5;
    if (lane == 0) {
        #pragma unroll
        for (int m = 0; m < 4; ++m)
            #pragma unroll
            for (int d = 0; d < 3; ++d) red[warp][m*3 + d] = p[m][d];
    }
    __syncthreads();
    if (tid < 48) {
        const int qtg = tid / 12, rem = tid % 12;
        float s = red[qtg*4 + 0][rem] + red[qtg*4 + 1][rem]
                + red[qtg*4 + 2][rem] + red[qtg*4 + 3][rem];
        out[(n0 + qtg*4 + rem/3)*3 + (rem % 3)] = s * fsp[0];
    }
}

// ---------------- launch ---------------------------------------------------
extern "C" void kernel_launch(void* const* d_in, const int* in_sizes, int n_in,
                              void* d_out, int out_size) {
    const float* positions = (const float*)d_in[0];
    const int*   nodef     = (const int*)  d_in[1];
    const float* gf        = (const float*)d_in[2];
    const float* emb       = (const float*)d_in[3];
    const float* Wt        = (const float*)d_in[4];
    const float* Wr1       = (const float*)d_in[5];
    const float* Wr2       = (const float*)d_in[6];
    const float* Wupd      = (const float*)d_in[7];
    const float* Wmix      = (const float*)d_in[8];
    const float* Wg1       = (const float*)d_in[9];
    const float* Wg2       = (const float*)d_in[10];
    const float* fs        = (const float*)d_in[11];
    float*       out       = (float*)d_out;

    const int msg_smem = MSG_WORDS * 4;
    const int upd_smem = UPD_WORDS * 4;
    const int rdo_smem = (Hh*Hh*2 + Hh*RP*2) * 4;
    cudaFuncSetAttribute(msg_kernel,     cudaFuncAttributeMaxDynamicSharedMemorySize, msg_smem);
    cudaFuncSetAttribute(upd_kernel,     cudaFuncAttributeMaxDynamicSharedMemorySize, upd_smem);
    cudaFuncSetAttribute(readout_kernel, cudaFuncAttributeMaxDynamicSharedMemorySize, rdo_smem);

    setup_kernel<<<512 + 3*Ll, 256>>>(nodef, gf, emb, Wt, Wr2, Wupd, Wmix);

    for (int l = 0; l < Ll; ++l) {
        dim3 grid(16, Bb);
        msg_kernel<<<grid, 256, msg_smem>>>(positions, Wr1 + l*NBb*Hh, l);
        upd_kernel<<<Bb*Nn/16, 256, upd_smem>>>(l);
    }
    readout_kernel<<<Bb*Nn/16, 512, rdo_smem>>>(Wg1, Wg2, fs, out);
}

// round 14
// speedup vs baseline: 7.7270x; 1.0771x over previous
#include <cuda_runtime.h>
#include <cuda_fp16.h>
#include <math.h>
#include <stdint.h>

// Problem constants
#define Bb   64
#define Nn   64
#define Hh   128
#define NBb  8
#define Tt   32
#define Ll   2
#define HSZ  (Bb*Nn*Hh)
#define VSZ  (Bb*Nn*3*Hh)

// ---------------- device scratch (no allocations allowed) ----------------
__device__ float    g_h   [2*HSZ];         // node scalar features (ping-pong)
__device__ float    g_v   [2*VSZ];         // vector features SoA (ping-pong)
__device__ uint32_t g_aF  [Bb*16*1024];    // aggregates, fp16 A-frag layout per (b,jg)
__device__ uint32_t g_Wr2H[Ll*8192];       // Wr2^T fp16 B-frags [kb8][c128][8w]
__device__ uint32_t g_WuH [Ll*8192];       // Wupd^T fp16 B-frags
__device__ uint32_t g_WmH [Ll*8192];       // Wmix^T fp16 B-frags

// ---------------- helpers -------------------------------------------------
__device__ __forceinline__ void mma_f16(float* c,
                                        uint32_t a0, uint32_t a1, uint32_t a2, uint32_t a3,
                                        uint32_t b0, uint32_t b1) {
    asm volatile(
        "mma.sync.aligned.m16n8k16.row.col.f32.f16.f16.f32 "
        "{%0,%1,%2,%3},{%4,%5,%6,%7},{%8,%9},{%0,%1,%2,%3};"
        : "+f"(c[0]), "+f"(c[1]), "+f"(c[2]), "+f"(c[3])
        : "r"(a0), "r"(a1), "r"(a2), "r"(a3), "r"(b0), "r"(b1));
}
__device__ __forceinline__ float tanh_approx(float x) {
    float r;
    asm("tanh.approx.f32 %0, %1;" : "=f"(r) : "f"(x));
    return r;
}
// silu(x) = 0.5x + 0.5x * tanh(0.5x)
__device__ __forceinline__ float silu_f(float x) {
    float s = 0.5f * x;
    return fmaf(s, tanh_approx(s), s);
}
__device__ __forceinline__ uint32_t pack_h2(float lo, float hi) {
    __half2 h = __floats2half2_rn(lo, hi);
    return *(uint32_t*)&h;
}

// ---------------- K1: fused setup (z-probe + init + weight frags) ---------
__global__ __launch_bounds__(256, 2)
void setup_kernel(const int* __restrict__ z,
                  const float* __restrict__ gf,
                  const float* __restrict__ emb,
                  const float* __restrict__ Wt,
                  const float* __restrict__ Wr2,
                  const float* __restrict__ Wupd,
                  const float* __restrict__ Wmix) {
    const int blk = blockIdx.x;
    const int tid = threadIdx.x;
    if (blk < 512) {
        // ---- init into buffer 0: h = emb[z] + t @ Wt ; v = 0 ----
        int t32 = tid & 31;
        int v = z[2*t32 + 1] | z[2*(t32 + 32) + 1];
        int nz = __reduce_or_sync(0xffffffffu, v);
        const int z64 = (nz == 0);
        const int n0 = blk * 8;
        const int b  = n0 >> 6;
        const int c  = tid & 127;
        const int qt = tid >> 7;
        float tw = 0.f;
        const float* g = gf + b*Tt;
        #pragma unroll
        for (int t = 0; t < Tt; ++t) tw += g[t] * Wt[t*Hh + c];
        #pragma unroll
        for (int m = 0; m < 4; ++m) {
            const int n  = n0 + qt*4 + m;
            const int zi = z64 ? z[2*n] : z[n];
            g_h[n*Hh + c] = emb[zi*Hh + c] + tw;
            g_v[(n*3 + 0)*Hh + c] = 0.f;
            g_v[(n*3 + 1)*Hh + c] = 0.f;
            g_v[(n*3 + 2)*Hh + c] = 0.f;
        }
    } else {
        // ---- weight -> fp16 B-fragment layout ----
        const int b2 = blk - 512;
        const int a  = b2 / Ll;
        const int l  = b2 % Ll;
        const float* src = (a == 0) ? Wr2 : (a == 1) ? Wupd : Wmix;
        uint32_t*    dst = (a == 0) ? g_Wr2H : (a == 1) ? g_WuH : g_WmH;
        src += l*Hh*Hh;
        dst += l*8192;
        for (int idx = tid; idx < 8192; idx += 256) {
            int c  = idx >> 6, kp = idx & 63;
            int k  = kp * 2;
            int kb = k >> 4;
            int kw = k & 15;
            int q  = (kw >> 1) & 3;
            int hi = kw >> 3;
            dst[(kb*128 + c)*8 + q*2 + hi] = pack_h2(src[k*Hh + c], src[(k+1)*Hh + c]);
        }
    }
}

// ---------------- smem word offsets for msg kernel ------------------------
#define OFF_W2T  0          // 8192 words: fp16 B frags [kb8][c128][8w]
#define OFF_S    8192       // 8192:  fp16 A frags 2 receivers [kb8][mtS8][r16][8w]
#define OFF_RBF  16384      // 1024:  fp16 rb [jl4][i64][4w]
#define OFF_U4F  17408      // 1024:  [jl4][i64] float4
#define MSG_WORDS 18432     // 73728 bytes -> 3 CTAs/SM

// ---------------- K2: message pass + fused update (3 CTAs/SM) -------------
// CTA = (4 receivers jg, batch b), 256 threads = 8 warps, 2 receivers/round.
// Tail: fused h/v update for the CTA's own 4 nodes (ping-pong buffers).
__global__ __launch_bounds__(256, 3)
void msg_kernel(const float* __restrict__ pos,
                const float* __restrict__ Wr1,
                int layer) {
    extern __shared__ float smf[];
    uint32_t* W2Tf = (uint32_t*)smf + OFF_W2T;
    uint32_t* Sf   = (uint32_t*)smf + OFF_S;
    uint32_t* rbf  = (uint32_t*)smf + OFF_RBF;
    float*    u4f  = smf + OFF_U4F;

    const float* h_in  = g_h + (layer & 1)*HSZ;
    float*       h_out = g_h + ((layer + 1) & 1)*HSZ;
    const float* v_in  = g_v + (layer & 1)*VSZ;
    float*       v_out = g_v + ((layer + 1) & 1)*VSZ;

    const int b    = blockIdx.y;
    const int jg   = blockIdx.x;            // 0..15
    const int tid  = threadIdx.x;
    const int lane = tid & 31;
    const int widh = tid >> 5;              // 0..7
    const int r4   = lane >> 2;             // 0..7
    const int q4   = lane & 3;              // 0..3

    // ---- stage W2T fp16 fragments (direct copy) ----
    for (int idx = tid; idx < 8192; idx += 256) W2Tf[idx] = g_Wr2H[layer*8192 + idx];

    // ---- register-cache h (fixed across receivers): 8 rows x 2 float2 ----
    float2 hreg[4][2][2];
    {
        const float* hb = h_in + (size_t)b*Nn*Hh;
        #pragma unroll
        for (int mt = 0; mt < 4; ++mt)
            #pragma unroll
            for (int rg = 0; rg < 2; ++rg) {
                int i = mt*16 + r4 + rg*8;
                #pragma unroll
                for (int nt = 0; nt < 2; ++nt) {
                    int c = widh*16 + nt*8 + q4*2;
                    hreg[mt][rg][nt] = *(const float2*)(hb + i*Hh + c);
                }
            }
    }

    // ---- Wr1 fp16 B-frags in registers (b0 only; k8-15 are zero) ----
    uint32_t wbA, wbB;
    {
        int cA = widh*16 + r4;
        int cB = cA + 8;
        wbA = pack_h2(Wr1[(q4*2)*Hh + cA], Wr1[(q4*2+1)*Hh + cA]);
        wbB = pack_h2(Wr1[(q4*2)*Hh + cB], Wr1[(q4*2+1)*Hh + cB]);
    }

    const float PI5 = 0.62831853071795864769f;   // pi/5
    const float s63 = 1.0f / 63.0f;

    // ---- geometry + bessel for all 4 receivers (256 = 4j x 64i) ----
    {
        const int jl = tid >> 6;             // 0..3
        const int i  = tid & 63;
        const int j  = jg*4 + jl;
        const float* pb = pos + b*Nn*3;
        float dx = pb[j*3+0] - pb[i*3+0];
        float dy = pb[j*3+1] - pb[i*3+1];
        float dz = pb[j*3+2] - pb[i*3+2];
        float r2 = dx*dx + dy*dy + dz*dz + 1e-12f;
        float r  = sqrtf(r2);
        float inv = 1.0f / r;
        ((float4*)u4f)[jl*Nn + i] = make_float4(dx*inv, dy*inv, dz*inv, 0.f);
        float fc = 0.0f;
        if (r < 5.0f && i != j) fc = 0.5f * (__cosf(PI5 * r) + 1.0f);
        float sc  = inv * fc;
        float arg = PI5 * r;
        float rv[8];
        #pragma unroll
        for (int q = 0; q < NBb; ++q) rv[q] = __sinf((float)(q+1) * arg) * sc;
        uint4 rw;
        rw.x = pack_h2(rv[0], rv[1]);
        rw.y = pack_h2(rv[2], rv[3]);
        rw.z = pack_h2(rv[4], rv[5]);
        rw.w = pack_h2(rv[6], rv[7]);
        ((uint4*)rbf)[jl*Nn + i] = rw;
    }
    __syncthreads();

    for (int rr = 0; rr < 2; ++rr) {
        // ---- S = silu(rb @ Wr1) for receivers rr*2, rr*2+1 (fp16 MMA, K=8) ----
        #pragma unroll
        for (int jh = 0; jh < 2; ++jh) {
            const uint32_t* rbj = rbf + (rr*2 + jh)*Nn*4;
            #pragma unroll
            for (int mt = 0; mt < 4; ++mt) {
                int r0 = mt*16 + r4;
                uint32_t A0 = rbj[r0*4 + q4];
                uint32_t A1 = rbj[(r0+8)*4 + q4];
                float s0[4] = {0.f, 0.f, 0.f, 0.f};
                float s1[4] = {0.f, 0.f, 0.f, 0.f};
                mma_f16(s0, A0, A1, 0u, 0u, wbA, 0u);
                mma_f16(s1, A0, A1, 0u, 0u, wbB, 0u);
                const int mtS = jh*4 + mt;
                uint32_t* Sb = Sf + (widh*8 + mtS)*128 + r4*8 + q4*2;
                *(uint2*)(Sb)      = make_uint2(pack_h2(silu_f(s0[0]), silu_f(s0[1])),
                                                pack_h2(silu_f(s1[0]), silu_f(s1[1])));
                *(uint2*)(Sb + 64) = make_uint2(pack_h2(silu_f(s0[2]), silu_f(s0[3])),
                                                pack_h2(silu_f(s1[2]), silu_f(s1[3])));
            }
        }
        __syncthreads();

        // ---- per receiver: kb-outer GEMM (B loaded once/kb) + epilogue ----
        #pragma unroll
        for (int jh = 0; jh < 2; ++jh) {
            float acc[4][2][4];
            #pragma unroll
            for (int mt = 0; mt < 4; ++mt)
                #pragma unroll
                for (int nt = 0; nt < 2; ++nt) {
                    acc[mt][nt][0]=0.f; acc[mt][nt][1]=0.f; acc[mt][nt][2]=0.f; acc[mt][nt][3]=0.f;
                }
            const uint32_t* Bp = W2Tf + (widh*16 + r4)*8 + q4*2;
            const uint32_t* Am0 = Sf + jh*4*128 + r4*8 + q4*2;

            #pragma unroll
            for (int kb = 0; kb < 8; ++kb) {
                uint2 Bv0 = *(const uint2*)(Bp + kb*1024);
                uint2 Bv1 = *(const uint2*)(Bp + kb*1024 + 64);
                #pragma unroll
                for (int mt = 0; mt < 4; ++mt) {
                    const uint32_t* Am = Am0 + kb*1024 + mt*128;
                    uint2 A0 = *(const uint2*)(Am);
                    uint2 A1 = *(const uint2*)(Am + 64);
                    mma_f16(acc[mt][0], A0.x, A1.x, A0.y, A1.y, Bv0.x, Bv0.y);
                    mma_f16(acc[mt][1], A0.x, A1.x, A0.y, A1.y, Bv1.x, Bv1.y);
                }
            }

            // ---- epilogue: multiply by h, u; reduce over rows ----
            float pa[2][2][4];
            #pragma unroll
            for (int nt = 0; nt < 2; ++nt)
                #pragma unroll
                for (int cp = 0; cp < 2; ++cp) {
                    pa[nt][cp][0]=0.f; pa[nt][cp][1]=0.f; pa[nt][cp][2]=0.f; pa[nt][cp][3]=0.f;
                }
            const float4* uj = (const float4*)u4f + (rr*2 + jh)*Nn;
            #pragma unroll
            for (int mt = 0; mt < 4; ++mt) {
                #pragma unroll
                for (int rg = 0; rg < 2; ++rg) {
                    int i = mt*16 + r4 + rg*8;
                    float4 uv = uj[i];
                    float2 h0 = hreg[mt][rg][0];
                    float2 h1 = hreg[mt][rg][1];
                    #pragma unroll
                    for (int cp = 0; cp < 2; ++cp) {
                        float m0 = acc[mt][0][rg*2+cp] * (cp ? h0.y : h0.x);
                        pa[0][cp][0] += m0;
                        pa[0][cp][1] = fmaf(m0, uv.x, pa[0][cp][1]);
                        pa[0][cp][2] = fmaf(m0, uv.y, pa[0][cp][2]);
                        pa[0][cp][3] = fmaf(m0, uv.z, pa[0][cp][3]);
                        float m1 = acc[mt][1][rg*2+cp] * (cp ? h1.y : h1.x);
                        pa[1][cp][0] += m1;
                        pa[1][cp][1] = fmaf(m1, uv.x, pa[1][cp][1]);
                        pa[1][cp][2] = fmaf(m1, uv.y, pa[1][cp][2]);
                        pa[1][cp][3] = fmaf(m1, uv.z, pa[1][cp][3]);
                    }
                }
            }
            #pragma unroll
            for (int nt = 0; nt < 2; ++nt)
                #pragma unroll
                for (int cp = 0; cp < 2; ++cp)
                    #pragma unroll
                    for (int q = 0; q < 4; ++q) {
                        float v = pa[nt][cp][q];
                        v += __shfl_xor_sync(0xffffffffu, v, 4);
                        v += __shfl_xor_sync(0xffffffffu, v, 8);
                        v += __shfl_xor_sync(0xffffffffu, v, 16);
                        pa[nt][cp][q] = v;
                    }
            // store aggregates in fp16 A-frag layout (global, own slice)
            if (lane < 4) {
                uint32_t* aF = g_aF + (b*16 + jg)*1024 + widh*128 + lane*2;
                const int node = rr*2 + jh;
                #pragma unroll
                for (int nt = 0; nt < 2; ++nt)
                    #pragma unroll
                    for (int q = 0; q < 4; ++q)
                        aF[(q*4 + node)*8 + nt] =
                            pack_h2(pa[nt][0][q]*s63, pa[nt][1][q]*s63);
            }
        }
        __syncthreads();   // guard S overwrite / make aF stores visible
    }

    // ---- fused update for own 4 nodes: h_out = h_in + a0@Wu ; v_out = v_in + a1@Wm
    {
        const uint32_t* aB  = g_aF + (b*16 + jg)*1024 + r4*8 + q4*2;
        const uint32_t* WuB = g_WuH + layer*8192 + (widh*16 + r4)*8 + q4*2;
        const uint32_t* WmB = g_WmH + layer*8192 + (widh*16 + r4)*8 + q4*2;
        float aU0[4] = {0.f,0.f,0.f,0.f}, aU1[4] = {0.f,0.f,0.f,0.f};
        float aM0[4] = {0.f,0.f,0.f,0.f}, aM1[4] = {0.f,0.f,0.f,0.f};
        #pragma unroll
        for (int kb = 0; kb < 8; ++kb) {
            uint2 A0 = *(const uint2*)(aB + kb*128);
            uint2 A1 = *(const uint2*)(aB + kb*128 + 64);
            uint2 Bu0 = *(const uint2*)(WuB + kb*1024);
            uint2 Bu1 = *(const uint2*)(WuB + kb*1024 + 64);
            uint2 Bm0 = *(const uint2*)(WmB + kb*1024);
            uint2 Bm1 = *(const uint2*)(WmB + kb*1024 + 64);
            mma_f16(aU0, A0.x, A1.x, A0.y, A1.y, Bu0.x, Bu0.y);
            mma_f16(aU1, A0.x, A1.x, A0.y, A1.y, Bu1.x, Bu1.y);
            mma_f16(aM0, A0.x, A1.x, A0.y, A1.y, Bm0.x, Bm0.y);
            mma_f16(aM1, A0.x, A1.x, A0.y, A1.y, Bm1.x, Bm1.y);
        }
        const int c0 = widh*16 + q4*2;
        // h: rows 0-3 (rg=0, r4<4) of the Wu GEMM -> node = r4
        if (r4 < 4) {
            const size_t n = (size_t)(b*Nn + jg*4 + r4);
            float2 hv0 = *(const float2*)(h_in + n*Hh + c0);
            float2 hv1 = *(const float2*)(h_in + n*Hh + c0 + 8);
            hv0.x += aU0[0]; hv0.y += aU0[1];
            hv1.x += aU1[0]; hv1.y += aU1[1];
            *(float2*)(h_out + n*Hh + c0)     = hv0;
            *(float2*)(h_out + n*Hh + c0 + 8) = hv1;
        }
        // v: Wm GEMM rows 4-7 (rg=0, r4>=4 -> d=0), rows 8-15 (rg=1 -> d=1/2)
        if (r4 >= 4) {
            const size_t n = (size_t)(b*Nn + jg*4 + (r4 - 4));
            float* vd = v_out + (n*3 + 0)*Hh + c0;
            const float* vs = v_in + (n*3 + 0)*Hh + c0;
            float2 v0 = *(const float2*)(vs);
            float2 v1 = *(const float2*)(vs + 8);
            v0.x += aM0[0]; v0.y += aM0[1];
            v1.x += aM1[0]; v1.y += aM1[1];
            *(float2*)(vd)     = v0;
            *(float2*)(vd + 8) = v1;
        }
        {
            const int d    = (r4 < 4) ? 1 : 2;
            const int node = (r4 < 4) ? r4 : (r4 - 4);
            const size_t n = (size_t)(b*Nn + jg*4 + node);
            float* vd = v_out + (n*3 + d)*Hh + c0;
            const float* vs = v_in + (n*3 + d)*Hh + c0;
            float2 v0 = *(const float2*)(vs);
            float2 v1 = *(const float2*)(vs + 8);
            v0.x += aM0[2]; v0.y += aM0[3];
            v1.x += aM1[2]; v1.y += aM1[3];
            *(float2*)(vd)     = v0;
            *(float2*)(vd + 8) = v1;
        }
    }
}

// ---------------- K4: gated readout (16 nodes/CTA, staged weights) --------
#define RP 20
__global__ __launch_bounds__(512, 1)
void readout_kernel(const float* __restrict__ Wg1,
                    const float* __restrict__ Wg2,
                    const float* __restrict__ fsp,
                    float* __restrict__ out) {
    extern __shared__ float rsm[];
    float* W1_s = rsm;                       // 16384
    float* W2_s = W1_s + Hh*Hh;              // 16384
    float* hT   = W2_s + Hh*Hh;              // 128*RP
    float* tT   = hT + Hh*RP;                // 128*RP
    __shared__ float red[16][12];

    const int n0  = blockIdx.x * 16;
    const int tid = threadIdx.x;
    for (int idx = tid; idx < Hh*Hh; idx += 512) { W1_s[idx] = Wg1[idx]; W2_s[idx] = Wg2[idx]; }
    for (int idx = tid; idx < 16*Hh; idx += 512) {
        int n = idx >> 7, g = idx & 127;
        hT[g*RP + n] = g_h[n0*Hh + idx];     // final h is buffer 0 (Ll even)
    }
    __syncthreads();

    const int c  = tid & 127;
    const int qt = tid >> 7;

    float t[4] = {0.f, 0.f, 0.f, 0.f};
    #pragma unroll 2
    for (int g = 0; g < Hh; ++g) {
        float w = W1_s[g*Hh + c];
        float4 hv = *(const float4*)(hT + g*RP + qt*4);
        t[0] = fmaf(hv.x, w, t[0]);
        t[1] = fmaf(hv.y, w, t[1]);
        t[2] = fmaf(hv.z, w, t[2]);
        t[3] = fmaf(hv.w, w, t[3]);
    }
    #pragma unroll
    for (int m = 0; m < 4; ++m) tT[c*RP + qt*4 + m] = silu_f(t[m]);
    __syncthreads();

    float gg[4] = {0.f, 0.f, 0.f, 0.f};
    #pragma unroll 2
    for (int k = 0; k < Hh; ++k) {
        float w = W2_s[k*Hh + c];
        float4 tv = *(const float4*)(tT + k*RP + qt*4);
        gg[0] = fmaf(tv.x, w, gg[0]);
        gg[1] = fmaf(tv.y, w, gg[1]);
        gg[2] = fmaf(tv.z, w, gg[2]);
        gg[3] = fmaf(tv.w, w, gg[3]);
    }

    float p[4][3];
    #pragma unroll
    for (int m = 0; m < 4; ++m) {
        int n = n0 + qt*4 + m;
        p[m][0] = g_v[(n*3 + 0)*Hh + c] * gg[m];   // final v is buffer 0
        p[m][1] = g_v[(n*3 + 1)*Hh + c] * gg[m];
        p[m][2] = g_v[(n*3 + 2)*Hh + c] * gg[m];
    }
    #pragma unroll
    for (int m = 0; m < 4; ++m)
        #pragma unroll
        for (int d = 0; d < 3; ++d) {
            float v = p[m][d];
            #pragma unroll
            for (int off = 16; off; off >>= 1) v += __shfl_xor_sync(0xffffffffu, v, off);
            p[m][d] = v;
        }
    const int lane = tid & 31, warp = tid >> 5;
    if (lane == 0) {
        #pragma unroll
        for (int m = 0; m < 4; ++m)
            #pragma unroll
            for (int d = 0; d < 3; ++d) red[warp][m*3 + d] = p[m][d];
    }
    __syncthreads();
    if (tid < 48) {
        const int qtg = tid / 12, rem = tid % 12;
        float s = red[qtg*4 + 0][rem] + red[qtg*4 + 1][rem]
                + red[qtg*4 + 2][rem] + red[qtg*4 + 3][rem];
        out[(n0 + qtg*4 + rem/3)*3 + (rem % 3)] = s * fsp[0];
    }
}

// ---------------- launch ---------------------------------------------------
extern "C" void kernel_launch(void* const* d_in, const int* in_sizes, int n_in,
                              void* d_out, int out_size) {
    const float* positions = (const float*)d_in[0];
    const int*   nodef     = (const int*)  d_in[1];
    const float* gf        = (const float*)d_in[2];
    const float* emb       = (const float*)d_in[3];
    const float* Wt        = (const float*)d_in[4];
    const float* Wr1       = (const float*)d_in[5];
    const float* Wr2       = (const float*)d_in[6];
    const float* Wupd      = (const float*)d_in[7];
    const float* Wmix      = (const float*)d_in[8];
    const float* Wg1       = (const float*)d_in[9];
    const float* Wg2       = (const float*)d_in[10];
    const float* fs        = (const float*)d_in[11];
    float*       out       = (float*)d_out;

    const int msg_smem = MSG_WORDS * 4;
    const int rdo_smem = (Hh*Hh*2 + Hh*RP*2) * 4;
    cudaFuncSetAttribute(msg_kernel,     cudaFuncAttributeMaxDynamicSharedMemorySize, msg_smem);
    cudaFuncSetAttribute(readout_kernel, cudaFuncAttributeMaxDynamicSharedMemorySize, rdo_smem);

    setup_kernel<<<512 + 3*Ll, 256>>>(nodef, gf, emb, Wt, Wr2, Wupd, Wmix);

    for (int l = 0; l < Ll; ++l) {
        dim3 grid(16, Bb);
        msg_kernel<<<grid, 256, msg_smem>>>(positions, Wr1 + l*NBb*Hh, l);
    }
    readout_kernel<<<Bb*Nn/16, 512, rdo_smem>>>(Wg1, Wg2, fs, out);
}

// round 15
// speedup vs baseline: 8.6038x; 1.1135x over previous
#include <cuda_runtime.h>
#include <cuda_fp16.h>
#include <math.h>
#include <stdint.h>

// Problem constants
#define Bb   64
#define Nn   64
#define Hh   128
#define NBb  8
#define Tt   32
#define Ll   2
#define HSZ  (Bb*Nn*Hh)
#define VSZ  (Bb*Nn*3*Hh)

// ---------------- device scratch (no allocations allowed) ----------------
__device__ float    g_h   [2*HSZ];         // node scalar features (ping-pong)
__device__ float    g_v   [2*VSZ];         // vector features SoA (ping-pong)
__device__ uint32_t g_aF  [Bb*16*1024];    // aggregates, fp16 A-frag layout per (b,jg)
__device__ uint32_t g_Wr2H[Ll*8192];       // Wr2^T fp16 B-frags [kb8][c128][8w]
__device__ uint32_t g_WuH [Ll*8192];       // Wupd^T fp16 B-frags
__device__ uint32_t g_WmH [Ll*8192];       // Wmix^T fp16 B-frags
__device__ uint32_t g_Wg1H[8192];          // Wg1^T fp16 B-frags
__device__ uint32_t g_Wg2H[8192];          // Wg2^T fp16 B-frags

// ---------------- helpers -------------------------------------------------
__device__ __forceinline__ void mma_f16(float* c,
                                        uint32_t a0, uint32_t a1, uint32_t a2, uint32_t a3,
                                        uint32_t b0, uint32_t b1) {
    asm volatile(
        "mma.sync.aligned.m16n8k16.row.col.f32.f16.f16.f32 "
        "{%0,%1,%2,%3},{%4,%5,%6,%7},{%8,%9},{%0,%1,%2,%3};"
        : "+f"(c[0]), "+f"(c[1]), "+f"(c[2]), "+f"(c[3])
        : "r"(a0), "r"(a1), "r"(a2), "r"(a3), "r"(b0), "r"(b1));
}
__device__ __forceinline__ float tanh_approx(float x) {
    float r;
    asm("tanh.approx.f32 %0, %1;" : "=f"(r) : "f"(x));
    return r;
}
// silu(x) = 0.5x + 0.5x * tanh(0.5x)
__device__ __forceinline__ float silu_f(float x) {
    float s = 0.5f * x;
    return fmaf(s, tanh_approx(s), s);
}
__device__ __forceinline__ uint32_t pack_h2(float lo, float hi) {
    __half2 h = __floats2half2_rn(lo, hi);
    return *(uint32_t*)&h;
}

// ---------------- K1: fused setup (z-probe + init + weight frags) ---------
__global__ __launch_bounds__(256, 2)
void setup_kernel(const int* __restrict__ z,
                  const float* __restrict__ gf,
                  const float* __restrict__ emb,
                  const float* __restrict__ Wt,
                  const float* __restrict__ Wr2,
                  const float* __restrict__ Wupd,
                  const float* __restrict__ Wmix,
                  const float* __restrict__ Wg1,
                  const float* __restrict__ Wg2) {
    const int blk = blockIdx.x;
    const int tid = threadIdx.x;
    if (blk < 512) {
        // ---- init into buffer 0: h = emb[z] + t @ Wt ; v = 0 ----
        int t32 = tid & 31;
        int v = z[2*t32 + 1] | z[2*(t32 + 32) + 1];
        int nz = __reduce_or_sync(0xffffffffu, v);
        const int z64 = (nz == 0);
        const int n0 = blk * 8;
        const int b  = n0 >> 6;
        const int c  = tid & 127;
        const int qt = tid >> 7;
        float tw = 0.f;
        const float* g = gf + b*Tt;
        #pragma unroll
        for (int t = 0; t < Tt; ++t) tw += g[t] * Wt[t*Hh + c];
        #pragma unroll
        for (int m = 0; m < 4; ++m) {
            const int n  = n0 + qt*4 + m;
            const int zi = z64 ? z[2*n] : z[n];
            g_h[n*Hh + c] = emb[zi*Hh + c] + tw;
            g_v[(n*3 + 0)*Hh + c] = 0.f;
            g_v[(n*3 + 1)*Hh + c] = 0.f;
            g_v[(n*3 + 2)*Hh + c] = 0.f;
        }
    } else {
        // ---- weight -> fp16 B-fragment layout ----
        const int b2 = blk - 512;
        const float* src;
        uint32_t*    dst;
        if (b2 < 3*Ll) {
            const int a = b2 / Ll;
            const int l = b2 % Ll;
            src = ((a == 0) ? Wr2 : (a == 1) ? Wupd : Wmix) + l*Hh*Hh;
            dst = ((a == 0) ? g_Wr2H : (a == 1) ? g_WuH : g_WmH) + l*8192;
        } else if (b2 == 3*Ll) {
            src = Wg1; dst = g_Wg1H;
        } else {
            src = Wg2; dst = g_Wg2H;
        }
        for (int idx = tid; idx < 8192; idx += 256) {
            int c  = idx >> 6, kp = idx & 63;
            int k  = kp * 2;
            int kb = k >> 4;
            int kw = k & 15;
            int q  = (kw >> 1) & 3;
            int hi = kw >> 3;
            dst[(kb*128 + c)*8 + q*2 + hi] = pack_h2(src[k*Hh + c], src[(k+1)*Hh + c]);
        }
    }
}

// ---------------- smem word offsets for msg kernel ------------------------
#define OFF_W2T  0          // 8192 words: fp16 B frags [kb8][c128][8w]
#define OFF_S    8192       // 8192:  fp16 A frags 2 receivers [kb8][mtS8][r16][8w]
#define OFF_RBF  16384      // 1024:  fp16 rb [jl4][i64][4w]
#define OFF_U4F  17408      // 1024:  [jl4][i64] float4
#define MSG_WORDS 18432     // 73728 bytes -> 3 CTAs/SM

// ---------------- K2: message pass + fused update (3 CTAs/SM) -------------
__global__ __launch_bounds__(256, 3)
void msg_kernel(const float* __restrict__ pos,
                const float* __restrict__ Wr1,
                int layer) {
    extern __shared__ float smf[];
    uint32_t* W2Tf = (uint32_t*)smf + OFF_W2T;
    uint32_t* Sf   = (uint32_t*)smf + OFF_S;
    uint32_t* rbf  = (uint32_t*)smf + OFF_RBF;
    float*    u4f  = smf + OFF_U4F;

    const float* h_in  = g_h + (layer & 1)*HSZ;
    float*       h_out = g_h + ((layer + 1) & 1)*HSZ;
    const float* v_in  = g_v + (layer & 1)*VSZ;
    float*       v_out = g_v + ((layer + 1) & 1)*VSZ;

    const int b    = blockIdx.y;
    const int jg   = blockIdx.x;            // 0..15
    const int tid  = threadIdx.x;
    const int lane = tid & 31;
    const int widh = tid >> 5;              // 0..7
    const int r4   = lane >> 2;             // 0..7
    const int q4   = lane & 3;              // 0..3

    for (int idx = tid; idx < 8192; idx += 256) W2Tf[idx] = g_Wr2H[layer*8192 + idx];

    float2 hreg[4][2][2];
    {
        const float* hb = h_in + (size_t)b*Nn*Hh;
        #pragma unroll
        for (int mt = 0; mt < 4; ++mt)
            #pragma unroll
            for (int rg = 0; rg < 2; ++rg) {
                int i = mt*16 + r4 + rg*8;
                #pragma unroll
                for (int nt = 0; nt < 2; ++nt) {
                    int c = widh*16 + nt*8 + q4*2;
                    hreg[mt][rg][nt] = *(const float2*)(hb + i*Hh + c);
                }
            }
    }

    uint32_t wbA, wbB;
    {
        int cA = widh*16 + r4;
        int cB = cA + 8;
        wbA = pack_h2(Wr1[(q4*2)*Hh + cA], Wr1[(q4*2+1)*Hh + cA]);
        wbB = pack_h2(Wr1[(q4*2)*Hh + cB], Wr1[(q4*2+1)*Hh + cB]);
    }

    const float PI5 = 0.62831853071795864769f;   // pi/5
    const float s63 = 1.0f / 63.0f;

    {
        const int jl = tid >> 6;             // 0..3
        const int i  = tid & 63;
        const int j  = jg*4 + jl;
        const float* pb = pos + b*Nn*3;
        float dx = pb[j*3+0] - pb[i*3+0];
        float dy = pb[j*3+1] - pb[i*3+1];
        float dz = pb[j*3+2] - pb[i*3+2];
        float r2 = dx*dx + dy*dy + dz*dz + 1e-12f;
        float r  = sqrtf(r2);
        float inv = 1.0f / r;
        ((float4*)u4f)[jl*Nn + i] = make_float4(dx*inv, dy*inv, dz*inv, 0.f);
        float fc = 0.0f;
        if (r < 5.0f && i != j) fc = 0.5f * (__cosf(PI5 * r) + 1.0f);
        float sc  = inv * fc;
        float arg = PI5 * r;
        float rv[8];
        #pragma unroll
        for (int q = 0; q < NBb; ++q) rv[q] = __sinf((float)(q+1) * arg) * sc;
        uint4 rw;
        rw.x = pack_h2(rv[0], rv[1]);
        rw.y = pack_h2(rv[2], rv[3]);
        rw.z = pack_h2(rv[4], rv[5]);
        rw.w = pack_h2(rv[6], rv[7]);
        ((uint4*)rbf)[jl*Nn + i] = rw;
    }
    __syncthreads();

    for (int rr = 0; rr < 2; ++rr) {
        #pragma unroll
        for (int jh = 0; jh < 2; ++jh) {
            const uint32_t* rbj = rbf + (rr*2 + jh)*Nn*4;
            #pragma unroll
            for (int mt = 0; mt < 4; ++mt) {
                int r0 = mt*16 + r4;
                uint32_t A0 = rbj[r0*4 + q4];
                uint32_t A1 = rbj[(r0+8)*4 + q4];
                float s0[4] = {0.f, 0.f, 0.f, 0.f};
                float s1[4] = {0.f, 0.f, 0.f, 0.f};
                mma_f16(s0, A0, A1, 0u, 0u, wbA, 0u);
                mma_f16(s1, A0, A1, 0u, 0u, wbB, 0u);
                const int mtS = jh*4 + mt;
                uint32_t* Sb = Sf + (widh*8 + mtS)*128 + r4*8 + q4*2;
                *(uint2*)(Sb)      = make_uint2(pack_h2(silu_f(s0[0]), silu_f(s0[1])),
                                                pack_h2(silu_f(s1[0]), silu_f(s1[1])));
                *(uint2*)(Sb + 64) = make_uint2(pack_h2(silu_f(s0[2]), silu_f(s0[3])),
                                                pack_h2(silu_f(s1[2]), silu_f(s1[3])));
            }
        }
        __syncthreads();

        #pragma unroll
        for (int jh = 0; jh < 2; ++jh) {
            float acc[4][2][4];
            #pragma unroll
            for (int mt = 0; mt < 4; ++mt)
                #pragma unroll
                for (int nt = 0; nt < 2; ++nt) {
                    acc[mt][nt][0]=0.f; acc[mt][nt][1]=0.f; acc[mt][nt][2]=0.f; acc[mt][nt][3]=0.f;
                }
            const uint32_t* Bp = W2Tf + (widh*16 + r4)*8 + q4*2;
            const uint32_t* Am0 = Sf + jh*4*128 + r4*8 + q4*2;

            #pragma unroll
            for (int kb = 0; kb < 8; ++kb) {
                uint2 Bv0 = *(const uint2*)(Bp + kb*1024);
                uint2 Bv1 = *(const uint2*)(Bp + kb*1024 + 64);
                #pragma unroll
                for (int mt = 0; mt < 4; ++mt) {
                    const uint32_t* Am = Am0 + kb*1024 + mt*128;
                    uint2 A0 = *(const uint2*)(Am);
                    uint2 A1 = *(const uint2*)(Am + 64);
                    mma_f16(acc[mt][0], A0.x, A1.x, A0.y, A1.y, Bv0.x, Bv0.y);
                    mma_f16(acc[mt][1], A0.x, A1.x, A0.y, A1.y, Bv1.x, Bv1.y);
                }
            }

            float pa[2][2][4];
            #pragma unroll
            for (int nt = 0; nt < 2; ++nt)
                #pragma unroll
                for (int cp = 0; cp < 2; ++cp) {
                    pa[nt][cp][0]=0.f; pa[nt][cp][1]=0.f; pa[nt][cp][2]=0.f; pa[nt][cp][3]=0.f;
                }
            const float4* uj = (const float4*)u4f + (rr*2 + jh)*Nn;
            #pragma unroll
            for (int mt = 0; mt < 4; ++mt) {
                #pragma unroll
                for (int rg = 0; rg < 2; ++rg) {
                    int i = mt*16 + r4 + rg*8;
                    float4 uv = uj[i];
                    float2 h0 = hreg[mt][rg][0];
                    float2 h1 = hreg[mt][rg][1];
                    #pragma unroll
                    for (int cp = 0; cp < 2; ++cp) {
                        float m0 = acc[mt][0][rg*2+cp] * (cp ? h0.y : h0.x);
                        pa[0][cp][0] += m0;
                        pa[0][cp][1] = fmaf(m0, uv.x, pa[0][cp][1]);
                        pa[0][cp][2] = fmaf(m0, uv.y, pa[0][cp][2]);
                        pa[0][cp][3] = fmaf(m0, uv.z, pa[0][cp][3]);
                        float m1 = acc[mt][1][rg*2+cp] * (cp ? h1.y : h1.x);
                        pa[1][cp][0] += m1;
                        pa[1][cp][1] = fmaf(m1, uv.x, pa[1][cp][1]);
                        pa[1][cp][2] = fmaf(m1, uv.y, pa[1][cp][2]);
                        pa[1][cp][3] = fmaf(m1, uv.z, pa[1][cp][3]);
                    }
                }
            }
            #pragma unroll
            for (int nt = 0; nt < 2; ++nt)
                #pragma unroll
                for (int cp = 0; cp < 2; ++cp)
                    #pragma unroll
                    for (int q = 0; q < 4; ++q) {
                        float v = pa[nt][cp][q];
                        v += __shfl_xor_sync(0xffffffffu, v, 4);
                        v += __shfl_xor_sync(0xffffffffu, v, 8);
                        v += __shfl_xor_sync(0xffffffffu, v, 16);
                        pa[nt][cp][q] = v;
                    }
            if (lane < 4) {
                uint32_t* aF = g_aF + (b*16 + jg)*1024 + widh*128 + lane*2;
                const int node = rr*2 + jh;
                #pragma unroll
                for (int nt = 0; nt < 2; ++nt)
                    #pragma unroll
                    for (int q = 0; q < 4; ++q)
                        aF[(q*4 + node)*8 + nt] =
                            pack_h2(pa[nt][0][q]*s63, pa[nt][1][q]*s63);
            }
        }
        __syncthreads();
    }

    // ---- fused update for own 4 nodes ----
    {
        const uint32_t* aB  = g_aF + (b*16 + jg)*1024 + r4*8 + q4*2;
        const uint32_t* WuB = g_WuH + layer*8192 + (widh*16 + r4)*8 + q4*2;
        const uint32_t* WmB = g_WmH + layer*8192 + (widh*16 + r4)*8 + q4*2;
        float aU0[4] = {0.f,0.f,0.f,0.f}, aU1[4] = {0.f,0.f,0.f,0.f};
        float aM0[4] = {0.f,0.f,0.f,0.f}, aM1[4] = {0.f,0.f,0.f,0.f};
        #pragma unroll
        for (int kb = 0; kb < 8; ++kb) {
            uint2 A0 = *(const uint2*)(aB + kb*128);
            uint2 A1 = *(const uint2*)(aB + kb*128 + 64);
            uint2 Bu0 = *(const uint2*)(WuB + kb*1024);
            uint2 Bu1 = *(const uint2*)(WuB + kb*1024 + 64);
            uint2 Bm0 = *(const uint2*)(WmB + kb*1024);
            uint2 Bm1 = *(const uint2*)(WmB + kb*1024 + 64);
            mma_f16(aU0, A0.x, A1.x, A0.y, A1.y, Bu0.x, Bu0.y);
            mma_f16(aU1, A0.x, A1.x, A0.y, A1.y, Bu1.x, Bu1.y);
            mma_f16(aM0, A0.x, A1.x, A0.y, A1.y, Bm0.x, Bm0.y);
            mma_f16(aM1, A0.x, A1.x, A0.y, A1.y, Bm1.x, Bm1.y);
        }
        const int c0 = widh*16 + q4*2;
        if (r4 < 4) {
            const size_t n = (size_t)(b*Nn + jg*4 + r4);
            float2 hv0 = *(const float2*)(h_in + n*Hh + c0);
            float2 hv1 = *(const float2*)(h_in + n*Hh + c0 + 8);
            hv0.x += aU0[0]; hv0.y += aU0[1];
            hv1.x += aU1[0]; hv1.y += aU1[1];
            *(float2*)(h_out + n*Hh + c0)     = hv0;
            *(float2*)(h_out + n*Hh + c0 + 8) = hv1;
        }
        if (r4 >= 4) {
            const size_t n = (size_t)(b*Nn + jg*4 + (r4 - 4));
            float* vd = v_out + (n*3 + 0)*Hh + c0;
            const float* vs = v_in + (n*3 + 0)*Hh + c0;
            float2 v0 = *(const float2*)(vs);
            float2 v1 = *(const float2*)(vs + 8);
            v0.x += aM0[0]; v0.y += aM0[1];
            v1.x += aM1[0]; v1.y += aM1[1];
            *(float2*)(vd)     = v0;
            *(float2*)(vd + 8) = v1;
        }
        {
            const int d    = (r4 < 4) ? 1 : 2;
            const int node = (r4 < 4) ? r4 : (r4 - 4);
            const size_t n = (size_t)(b*Nn + jg*4 + node);
            float* vd = v_out + (n*3 + d)*Hh + c0;
            const float* vs = v_in + (n*3 + d)*Hh + c0;
            float2 v0 = *(const float2*)(vs);
            float2 v1 = *(const float2*)(vs + 8);
            v0.x += aM0[2]; v0.y += aM0[3];
            v1.x += aM1[2]; v1.y += aM1[3];
            *(float2*)(vd)     = v0;
            *(float2*)(vd + 8) = v1;
        }
    }
}

// ---------------- K4: tensorized gated readout (16 nodes/CTA) -------------
// t = h@Wg1 (MMA), silu, g = t@Wg2 (MMA), out[n][d] = sum_c v[n][d][c]*g[n][c]
__global__ __launch_bounds__(256, 4)
void readout_kernel(const float* __restrict__ fsp,
                    float* __restrict__ out) {
    __shared__ uint32_t rsm[4096];           // [0:2048) h A-frags, [2048:4096) t A-frags
    __shared__ float red[8][48];

    const int n0  = blockIdx.x * 16;
    const int tid = threadIdx.x;
    const int lane = tid & 31;
    const int widh = tid >> 5;
    const int r4 = lane >> 2, q4 = lane & 3;

    // stage h (final = buffer 0) as fp16 A-frags
    for (int idx = tid; idx < 2048; idx += 256) {
        int w  = idx & 7;
        int r  = (idx >> 3) & 15;
        int kb = idx >> 7;
        int k  = kb*16 + ((w >> 1) & 3)*2 + (w & 1)*8;
        float2 v = *(const float2*)(g_h + (size_t)(n0 + r)*Hh + k);
        rsm[idx] = pack_h2(v.x, v.y);
    }
    __syncthreads();

    // GEMM1: t = h @ Wg1
    float a0[4] = {0.f,0.f,0.f,0.f}, a1[4] = {0.f,0.f,0.f,0.f};
    {
        const uint32_t* Ap = rsm + r4*8 + q4*2;
        const uint32_t* Bp = g_Wg1H + (widh*16 + r4)*8 + q4*2;
        #pragma unroll
        for (int kb = 0; kb < 8; ++kb) {
            uint2 A0 = *(const uint2*)(Ap + kb*128);
            uint2 A1 = *(const uint2*)(Ap + kb*128 + 64);
            uint2 B0 = *(const uint2*)(Bp + kb*1024);
            uint2 B1 = *(const uint2*)(Bp + kb*1024 + 64);
            mma_f16(a0, A0.x, A1.x, A0.y, A1.y, B0.x, B0.y);
            mma_f16(a1, A0.x, A1.x, A0.y, A1.y, B1.x, B1.y);
        }
    }
    // silu + pack into t A-frags
    {
        uint32_t* Tb = rsm + 2048 + widh*128 + r4*8 + q4*2;
        Tb[0]      = pack_h2(silu_f(a0[0]), silu_f(a0[1]));
        Tb[1]      = pack_h2(silu_f(a1[0]), silu_f(a1[1]));
        Tb[64]     = pack_h2(silu_f(a0[2]), silu_f(a0[3]));
        Tb[65]     = pack_h2(silu_f(a1[2]), silu_f(a1[3]));
    }
    __syncthreads();

    // GEMM2: g = t @ Wg2
    float g0[4] = {0.f,0.f,0.f,0.f}, g1[4] = {0.f,0.f,0.f,0.f};
    {
        const uint32_t* Ap = rsm + 2048 + r4*8 + q4*2;
        const uint32_t* Bp = g_Wg2H + (widh*16 + r4)*8 + q4*2;
        #pragma unroll
        for (int kb = 0; kb < 8; ++kb) {
            uint2 A0 = *(const uint2*)(Ap + kb*128);
            uint2 A1 = *(const uint2*)(Ap + kb*128 + 64);
            uint2 B0 = *(const uint2*)(Bp + kb*1024);
            uint2 B1 = *(const uint2*)(Bp + kb*1024 + 64);
            mma_f16(g0, A0.x, A1.x, A0.y, A1.y, B0.x, B0.y);
            mma_f16(g1, A0.x, A1.x, A0.y, A1.y, B1.x, B1.y);
        }
    }

    // contraction with v (final = buffer 0)
    float pr[2][3];
    #pragma unroll
    for (int rg = 0; rg < 2; ++rg) { pr[rg][0]=0.f; pr[rg][1]=0.f; pr[rg][2]=0.f; }
    #pragma unroll
    for (int rg = 0; rg < 2; ++rg) {
        const size_t n = (size_t)(n0 + r4 + rg*8);
        #pragma unroll
        for (int nt = 0; nt < 2; ++nt) {
            const int c = widh*16 + nt*8 + q4*2;
            float gv0 = (nt ? g1 : g0)[rg*2 + 0];
            float gv1 = (nt ? g1 : g0)[rg*2 + 1];
            #pragma unroll
            for (int d = 0; d < 3; ++d) {
                float2 vv = *(const float2*)(g_v + (n*3 + d)*Hh + c);
                pr[rg][d] = fmaf(vv.x, gv0, fmaf(vv.y, gv1, pr[rg][d]));
            }
        }
    }
    // reduce over q4 (quad) then across warps via smem
    #pragma unroll
    for (int rg = 0; rg < 2; ++rg)
        #pragma unroll
        for (int d = 0; d < 3; ++d) {
            float v = pr[rg][d];
            v += __shfl_xor_sync(0xffffffffu, v, 1);
            v += __shfl_xor_sync(0xffffffffu, v, 2);
            pr[rg][d] = v;
        }
    if (q4 == 0) {
        #pragma unroll
        for (int rg = 0; rg < 2; ++rg)
            #pragma unroll
            for (int d = 0; d < 3; ++d)
                red[widh][(r4 + rg*8)*3 + d] = pr[rg][d];
    }
    __syncthreads();
    if (tid < 48) {
        float s = 0.f;
        #pragma unroll
        for (int w = 0; w < 8; ++w) s += red[w][tid];
        out[(n0 + tid/3)*3 + (tid % 3)] = s * fsp[0];
    }
}

// ---------------- launch ---------------------------------------------------
extern "C" void kernel_launch(void* const* d_in, const int* in_sizes, int n_in,
                              void* d_out, int out_size) {
    const float* positions = (const float*)d_in[0];
    const int*   nodef     = (const int*)  d_in[1];
    const float* gf        = (const float*)d_in[2];
    const float* emb       = (const float*)d_in[3];
    const float* Wt        = (const float*)d_in[4];
    const float* Wr1       = (const float*)d_in[5];
    const float* Wr2       = (const float*)d_in[6];
    const float* Wupd      = (const float*)d_in[7];
    const float* Wmix      = (const float*)d_in[8];
    const float* Wg1       = (const float*)d_in[9];
    const float* Wg2       = (const float*)d_in[10];
    const float* fs        = (const float*)d_in[11];
    float*       out       = (float*)d_out;

    const int msg_smem = MSG_WORDS * 4;
    cudaFuncSetAttribute(msg_kernel, cudaFuncAttributeMaxDynamicSharedMemorySize, msg_smem);

    setup_kernel<<<512 + 3*Ll + 2, 256>>>(nodef, gf, emb, Wt, Wr2, Wupd, Wmix, Wg1, Wg2);

    for (int l = 0; l < Ll; ++l) {
        dim3 grid(16, Bb);
        msg_kernel<<<grid, 256, msg_smem>>>(positions, Wr1 + l*NBb*Hh, l);
    }
    readout_kernel<<<Bb*Nn/16, 256>>>(fs, out);
}